// round 1
// baseline (speedup 1.0000x reference)
#include <cuda_runtime.h>
#include <math.h>

#define T_SEQ 2048
#define DIM   4096
#define NH    32
#define NKV   8
#define HD    128
#define KVD   1024      // NKV*HD
#define KDIM  4096

// Scratch (static __device__ — no allocation allowed)
__device__ float g_q[T_SEQ * DIM];
__device__ float g_k[T_SEQ * KVD];
__device__ float g_v[T_SEQ * KVD];
__device__ float g_att[T_SEQ * DIM];

// ---------------------------------------------------------------------------
// SGEMM: C[M,N] = A[M,K] @ W[N,K]^T + bias.  3-region variant: blockIdx.x
// column ranges select (Wq,Cq) / (Wk,Ck) / (Wv,Cv) so QKV is one launch.
// Out-projection launches with grid.x=32 (only region 0 used).
// BM=BN=128, BK=16, 256 threads, 8x8 per-thread micro-tile.
// ---------------------------------------------------------------------------
__global__ __launch_bounds__(256) void sgemm_kernel(
    const float* __restrict__ A,
    const float* __restrict__ Wq, const float* __restrict__ bq, float* __restrict__ Cq,
    const float* __restrict__ Wk, const float* __restrict__ bk, float* __restrict__ Ck,
    const float* __restrict__ Wv, const float* __restrict__ bv, float* __restrict__ Cv)
{
    const int BK = 16;
    __shared__ float As[BK][128];
    __shared__ float Bs[BK][128];

    int bn_g = blockIdx.x * 128;
    const float* W; const float* bias; float* C; int n0; int ldc;
    if (bn_g < 4096)      { W = Wq; bias = bq; C = Cq; n0 = bn_g;        ldc = DIM; }
    else if (bn_g < 5120) { W = Wk; bias = bk; C = Ck; n0 = bn_g - 4096; ldc = KVD; }
    else                  { W = Wv; bias = bv; C = Cv; n0 = bn_g - 5120; ldc = KVD; }

    int bm  = blockIdx.y * 128;
    int tid = threadIdx.x;
    int tx = tid & 15, ty = tid >> 4;
    int lr = tid >> 2;
    int lc = (tid & 3) << 2;

    const float* Aptr = A + (size_t)(bm + lr) * KDIM + lc;
    const float* Wptr = W + (size_t)(n0 + lr) * KDIM + lc;

    float acc[8][8];
    #pragma unroll
    for (int i = 0; i < 8; i++)
        #pragma unroll
        for (int j = 0; j < 8; j++) acc[i][j] = 0.f;

    for (int k0 = 0; k0 < KDIM; k0 += BK) {
        float4 a0 = *(const float4*)(Aptr + k0);
        float4 a1 = *(const float4*)(Aptr + (size_t)64 * KDIM + k0);
        float4 w0 = *(const float4*)(Wptr + k0);
        float4 w1 = *(const float4*)(Wptr + (size_t)64 * KDIM + k0);
        __syncthreads();
        As[lc+0][lr]    = a0.x; As[lc+1][lr]    = a0.y; As[lc+2][lr]    = a0.z; As[lc+3][lr]    = a0.w;
        As[lc+0][lr+64] = a1.x; As[lc+1][lr+64] = a1.y; As[lc+2][lr+64] = a1.z; As[lc+3][lr+64] = a1.w;
        Bs[lc+0][lr]    = w0.x; Bs[lc+1][lr]    = w0.y; Bs[lc+2][lr]    = w0.z; Bs[lc+3][lr]    = w0.w;
        Bs[lc+0][lr+64] = w1.x; Bs[lc+1][lr+64] = w1.y; Bs[lc+2][lr+64] = w1.z; Bs[lc+3][lr+64] = w1.w;
        __syncthreads();
        #pragma unroll
        for (int kk = 0; kk < BK; kk++) {
            float ra[8], rb[8];
            #pragma unroll
            for (int i = 0; i < 8; i++) ra[i] = As[kk][ty*8 + i];
            #pragma unroll
            for (int j = 0; j < 8; j++) rb[j] = Bs[kk][tx*8 + j];
            #pragma unroll
            for (int i = 0; i < 8; i++)
                #pragma unroll
                for (int j = 0; j < 8; j++)
                    acc[i][j] = fmaf(ra[i], rb[j], acc[i][j]);
        }
    }

    float bb[8];
    #pragma unroll
    for (int j = 0; j < 8; j++) bb[j] = bias[n0 + tx*8 + j];
    #pragma unroll
    for (int i = 0; i < 8; i++) {
        int row = bm + ty*8 + i;
        #pragma unroll
        for (int j4 = 0; j4 < 8; j4 += 4) {
            float4 o;
            o.x = acc[i][j4+0] + bb[j4+0];
            o.y = acc[i][j4+1] + bb[j4+1];
            o.z = acc[i][j4+2] + bb[j4+2];
            o.w = acc[i][j4+3] + bb[j4+3];
            *(float4*)&C[(size_t)row * ldc + n0 + tx*8 + j4] = o;
        }
    }
}

// ---------------------------------------------------------------------------
// RoPE on g_q (T,NH,HD) and g_k (T,NKV,HD).  Pairs (2i, 2i+1), i<64.
// ---------------------------------------------------------------------------
__global__ void rope_kernel(const float* __restrict__ fc, const float* __restrict__ fs)
{
    int idx = blockIdx.x * blockDim.x + threadIdx.x;
    const int QP = T_SEQ * NH  * (HD/2);   // 4194304
    const int KP = T_SEQ * NKV * (HD/2);   // 1048576
    if (idx < QP) {
        int t = idx / (NH * 64);
        int r = idx - t * (NH * 64);
        int h = r >> 6, i = r & 63;
        float c = fc[t*64 + i], s = fs[t*64 + i];
        float2* p = (float2*)&g_q[(size_t)t*DIM + h*HD + 2*i];
        float2 v = *p;
        p->x = v.x * c - v.y * s;
        p->y = v.x * s + v.y * c;
    } else if (idx < QP + KP) {
        int j = idx - QP;
        int t = j / (NKV * 64);
        int r = j - t * (NKV * 64);
        int h = r >> 6, i = r & 63;
        float c = fc[t*64 + i], s = fs[t*64 + i];
        float2* p = (float2*)&g_k[(size_t)t*KVD + h*HD + 2*i];
        float2 v = *p;
        p->x = v.x * c - v.y * s;
        p->y = v.x * s + v.y * c;
    }
}

// ---------------------------------------------------------------------------
// Flash attention, fp32, causal, GQA (4 q-heads per kv-head).
// Block: 128 threads, one q-row per thread, acc[128] in registers.
// Tiles: BM=128 q rows, BN=32 kv rows.  Q in SMEM with XOR swizzle
// (conflict-free strided reads); K/V in SMEM read via warp-broadcast.
// ---------------------------------------------------------------------------
#define FA_BM 128
#define FA_BN 32
#define FA_SMEM ((FA_BM + FA_BN + FA_BN) * HD * 4)   // 98304 bytes

__global__ __launch_bounds__(128) void flash_attn_kernel(
    const float* __restrict__ q, const float* __restrict__ k,
    const float* __restrict__ v, float* __restrict__ out)
{
    extern __shared__ float smem[];
    float4* q_s = (float4*)smem;                  // [FA_BM][32] swizzled
    float4* k_s = q_s + FA_BM * 32;               // [FA_BN][32]
    float4* v_s = k_s + FA_BN * 32;               // [FA_BN][32]

    int qtile = gridDim.x - 1 - blockIdx.x;       // heavy (late) tiles first
    int h     = blockIdx.y;
    int kvh   = h >> 2;                           // REP = 4
    int tid   = threadIdx.x;
    int row   = tid;
    int qi    = qtile * FA_BM + row;

    // cooperative coalesced Q-tile load, XOR swizzle on float4 column
    for (int i = tid; i < FA_BM * 32; i += 128) {
        int r = i >> 5, c = i & 31;
        float4 val = *(const float4*)&q[(size_t)(qtile*FA_BM + r)*DIM + h*HD + c*4];
        q_s[r*32 + (c ^ (r & 7))] = val;
    }

    float m = -1e30f, l = 0.f;
    float accv[HD];
    #pragma unroll
    for (int d = 0; d < HD; d++) accv[d] = 0.f;

    const float scale = 0.08838834764831845f;     // 1/sqrt(128)
    int ntiles = (qtile + 1) * (FA_BM / FA_BN);
    int sw = row & 7;

    for (int jt = 0; jt < ntiles; jt++) {
        __syncthreads();
        for (int i = tid; i < FA_BN * 32; i += 128) {
            int r = i >> 5, c = i & 31;
            size_t goff = (size_t)(jt*FA_BN + r) * KVD + kvh*HD + c*4;
            k_s[r*32 + c] = *(const float4*)&k[goff];
            v_s[r*32 + c] = *(const float4*)&v[goff];
        }
        __syncthreads();

        // S = q_row . K^T  (d outer so Q is loaded once per d4)
        float s[FA_BN];
        #pragma unroll
        for (int j = 0; j < FA_BN; j++) s[j] = 0.f;
        #pragma unroll 8
        for (int d = 0; d < 32; d++) {
            float4 qv = q_s[row*32 + (d ^ sw)];
            #pragma unroll
            for (int j = 0; j < FA_BN; j++) {
                float4 kv = k_s[j*32 + d];   // broadcast
                s[j] = fmaf(qv.x, kv.x, s[j]);
                s[j] = fmaf(qv.y, kv.y, s[j]);
                s[j] = fmaf(qv.z, kv.z, s[j]);
                s[j] = fmaf(qv.w, kv.w, s[j]);
            }
        }

        int jbase = jt * FA_BN;
        float mt = m;
        #pragma unroll
        for (int j = 0; j < FA_BN; j++) {
            s[j] = (jbase + j <= qi) ? s[j] * scale : -1e30f;
            mt = fmaxf(mt, s[j]);
        }
        float corr = __expf(m - mt);
        float lsum = 0.f;
        #pragma unroll
        for (int j = 0; j < FA_BN; j++) { s[j] = __expf(s[j] - mt); lsum += s[j]; }
        m = mt;
        l = l * corr + lsum;
        #pragma unroll
        for (int d = 0; d < HD; d++) accv[d] *= corr;

        #pragma unroll
        for (int j = 0; j < FA_BN; j++) {
            float p = s[j];
            #pragma unroll
            for (int d4 = 0; d4 < 32; d4++) {
                float4 vv = v_s[j*32 + d4];  // broadcast
                accv[d4*4+0] = fmaf(p, vv.x, accv[d4*4+0]);
                accv[d4*4+1] = fmaf(p, vv.y, accv[d4*4+1]);
                accv[d4*4+2] = fmaf(p, vv.z, accv[d4*4+2]);
                accv[d4*4+3] = fmaf(p, vv.w, accv[d4*4+3]);
            }
        }
    }

    float inv = 1.f / l;
    #pragma unroll
    for (int d4 = 0; d4 < 32; d4++) {
        float4 o;
        o.x = accv[d4*4+0] * inv;
        o.y = accv[d4*4+1] * inv;
        o.z = accv[d4*4+2] * inv;
        o.w = accv[d4*4+3] * inv;
        *(float4*)&out[(size_t)qi*DIM + h*HD + d4*4] = o;
    }
}

// ---------------------------------------------------------------------------
extern "C" void kernel_launch(void* const* d_in, const int* in_sizes, int n_in,
                              void* d_out, int out_size)
{
    const float* x    = (const float*)d_in[0];
    const float* fc   = (const float*)d_in[1];
    const float* fs   = (const float*)d_in[2];
    // d_in[3] mask, d_in[4] cache_k, d_in[5] cache_v: pos=0, full causal — unused
    const float* wk_w = (const float*)d_in[6];
    const float* wk_b = (const float*)d_in[7];
    const float* wv_w = (const float*)d_in[8];
    const float* wv_b = (const float*)d_in[9];
    const float* wo_w = (const float*)d_in[10];
    const float* wo_b = (const float*)d_in[11];
    float* out = (float*)d_out;

    float *q, *k, *v, *att;
    cudaGetSymbolAddress((void**)&q,   g_q);
    cudaGetSymbolAddress((void**)&k,   g_k);
    cudaGetSymbolAddress((void**)&v,   g_v);
    cudaGetSymbolAddress((void**)&att, g_att);

    // 1) fused QKV projection (q uses wo_w per reference)
    dim3 gqkv(48, 16);
    sgemm_kernel<<<gqkv, 256>>>(x, wo_w, wo_b, q, wk_w, wk_b, k, wv_w, wv_b, v);

    // 2) RoPE on q and k
    int ropeN = T_SEQ*NH*(HD/2) + T_SEQ*NKV*(HD/2);
    rope_kernel<<<(ropeN + 255)/256, 256>>>(fc, fs);

    // 3) causal GQA flash attention
    cudaFuncSetAttribute(flash_attn_kernel,
                         cudaFuncAttributeMaxDynamicSharedMemorySize, FA_SMEM);
    dim3 gfa(T_SEQ / FA_BM, NH);
    flash_attn_kernel<<<gfa, 128, FA_SMEM>>>(q, k, v, att);

    // 4) output projection
    dim3 go(32, 16);
    sgemm_kernel<<<go, 256>>>(att, wo_w, wo_b, out,
                              nullptr, nullptr, nullptr,
                              nullptr, nullptr, nullptr);
}

// round 3
// speedup vs baseline: 1.7353x; 1.7353x over previous
#include <cuda_runtime.h>
#include <cuda_bf16.h>
#include <math.h>
#include <stdint.h>

#define T_SEQ 2048
#define DIM   4096
#define NH    32
#define NKV   8
#define HD    128
#define KVD   1024
#define KDIM  4096

// ---------------- scratch (static __device__, no allocation) ----------------
__device__ float g_q  [T_SEQ * DIM];
__device__ float g_k  [T_SEQ * KVD];
__device__ float g_v  [T_SEQ * KVD];
__device__ float g_att[T_SEQ * DIM];

__device__ __nv_bfloat16 g_xhi [T_SEQ * DIM], g_xlo [T_SEQ * DIM];
__device__ __nv_bfloat16 g_wohi[DIM * DIM],   g_wolo[DIM * DIM];
__device__ __nv_bfloat16 g_wkhi[KVD * DIM],   g_wklo[KVD * DIM];
__device__ __nv_bfloat16 g_wvhi[KVD * DIM],   g_wvlo[KVD * DIM];
__device__ __nv_bfloat16 g_ahi [T_SEQ * DIM], g_alo [T_SEQ * DIM];

// ---------------- PTX helpers (baseline ISA only, no 'a' features) ---------
__device__ __forceinline__ uint32_t smem_u32(const void* p) {
    uint32_t a;
    asm("{ .reg .u64 t; cvta.to.shared.u64 t, %1; cvt.u32.u64 %0, t; }" : "=r"(a) : "l"(p));
    return a;
}
#define CP16(dst, src) asm volatile("cp.async.cg.shared.global [%0], [%1], 16;" :: "r"(dst), "l"(src))
#define CP_COMMIT()    asm volatile("cp.async.commit_group;" ::: "memory")
#define CP_WAIT1()     asm volatile("cp.async.wait_group 1;" ::: "memory")
#define CP_WAIT0()     asm volatile("cp.async.wait_group 0;" ::: "memory")

#define LDSM4(r, a) asm volatile( \
    "ldmatrix.sync.aligned.m8n8.x4.shared.b16 {%0,%1,%2,%3}, [%4];" \
    : "=r"((r)[0]), "=r"((r)[1]), "=r"((r)[2]), "=r"((r)[3]) : "r"(a))

#define MMA16816(c, a, b0, b1) asm volatile( \
    "mma.sync.aligned.m16n8k16.row.col.f32.bf16.bf16.f32 " \
    "{%0,%1,%2,%3},{%4,%5,%6,%7},{%8,%9},{%0,%1,%2,%3};" \
    : "+f"((c)[0]), "+f"((c)[1]), "+f"((c)[2]), "+f"((c)[3]) \
    : "r"((a)[0]), "r"((a)[1]), "r"((a)[2]), "r"((a)[3]), "r"(b0), "r"(b1))

// ---------------------------------------------------------------------------
// split fp32 -> bf16 hi + bf16 lo (residual)
// ---------------------------------------------------------------------------
__global__ void split_kernel(const float* __restrict__ src,
                             __nv_bfloat16* __restrict__ hi,
                             __nv_bfloat16* __restrict__ lo, int n4)
{
    int i = blockIdx.x * blockDim.x + threadIdx.x;
    if (i >= n4) return;
    float4 v = ((const float4*)src)[i];
    __nv_bfloat162 h01 = __floats2bfloat162_rn(v.x, v.y);
    __nv_bfloat162 h23 = __floats2bfloat162_rn(v.z, v.w);
    float lx = v.x - __low2float(h01);
    float ly = v.y - __high2float(h01);
    float lz = v.z - __low2float(h23);
    float lw = v.w - __high2float(h23);
    ((__nv_bfloat162*)hi)[2*i]   = h01;
    ((__nv_bfloat162*)hi)[2*i+1] = h23;
    ((__nv_bfloat162*)lo)[2*i]   = __floats2bfloat162_rn(lx, ly);
    ((__nv_bfloat162*)lo)[2*i+1] = __floats2bfloat162_rn(lz, lw);
}

// ---------------------------------------------------------------------------
// bf16-split tensor-core GEMM (mma.sync): C[M,N] = A[M,K] @ W[N,K]^T + bias
// 3-term: Ah*Wh + Ah*Wl + Al*Wh into fp32 accumulators.
// CTA tile 128x128, BK=32, 256 thr (8 warps: 2m x 4n, warp tile 64x32),
// 2-stage cp.async pipeline. SMEM rows padded to 80B (stride 5 mod 8 in
// 16B units -> conflict-free ldmatrix).
// Region select on blockIdx.x: [0,32)->W0/C0 ldc=4096, [32,40)->W1,
// [40,48)->W2 (ldc=1024).
// ---------------------------------------------------------------------------
#define ROWB   80u
#define A_HI   0u
#define A_LO   10240u
#define B_HI   20480u
#define B_LO   30720u
#define STAGEB 40960u
#define GSMEM  (2 * 40960)

__global__ __launch_bounds__(256, 1) void mma_gemm_kernel(
    const __nv_bfloat16* __restrict__ Ahi, const __nv_bfloat16* __restrict__ Alo,
    const __nv_bfloat16* __restrict__ W0hi, const __nv_bfloat16* __restrict__ W0lo,
    const float* __restrict__ b0, float* __restrict__ C0,
    const __nv_bfloat16* __restrict__ W1hi, const __nv_bfloat16* __restrict__ W1lo,
    const float* __restrict__ b1, float* __restrict__ C1,
    const __nv_bfloat16* __restrict__ W2hi, const __nv_bfloat16* __restrict__ W2lo,
    const float* __restrict__ b2, float* __restrict__ C2)
{
    extern __shared__ char dsm[];
    const uint32_t sb = smem_u32(dsm);

    int bx = blockIdx.x;
    const __nv_bfloat16 *Whi, *Wlo; const float* bias; float* C; int n0, ldc;
    if (bx < 32)      { Whi = W0hi; Wlo = W0lo; bias = b0; C = C0; n0 = bx * 128;        ldc = DIM; }
    else if (bx < 40) { Whi = W1hi; Wlo = W1lo; bias = b1; C = C1; n0 = (bx - 32) * 128; ldc = KVD; }
    else              { Whi = W2hi; Wlo = W2lo; bias = b2; C = C2; n0 = (bx - 40) * 128; ldc = KVD; }

    const int bm   = blockIdx.y * 128;
    const int tid  = threadIdx.x;
    const int wid  = tid >> 5;
    const int lane = tid & 31;
    const int wm   = wid & 1;        // 0..1  (64 rows each)
    const int wn   = wid >> 1;       // 0..3  (32 cols each)

    // cp.async geometry: 2 x 16B per array per chunk per thread
    const int r0 = tid >> 2, cc = tid & 3;
    const uint32_t so0 = (uint32_t)r0 * ROWB + cc * 16u;
    const uint32_t so1 = so0 + 64u * ROWB;
    const size_t  go0 = (size_t)r0 * 8192 + cc * 16;
    const size_t  go1 = go0 + (size_t)64 * 8192;

    const char* pAh = (const char*)Ahi + (size_t)bm * 8192;
    const char* pAl = (const char*)Alo + (size_t)bm * 8192;
    const char* pBh = (const char*)Whi + (size_t)n0 * 8192;
    const char* pBl = (const char*)Wlo + (size_t)n0 * 8192;

#define LOADCHUNK(cidx, s) do { \
    uint32_t _st = sb + (uint32_t)(s) * STAGEB; \
    size_t _kb = (size_t)(cidx) * 64; \
    CP16(_st + A_HI + so0, pAh + go0 + _kb); CP16(_st + A_HI + so1, pAh + go1 + _kb); \
    CP16(_st + A_LO + so0, pAl + go0 + _kb); CP16(_st + A_LO + so1, pAl + go1 + _kb); \
    CP16(_st + B_HI + so0, pBh + go0 + _kb); CP16(_st + B_HI + so1, pBh + go1 + _kb); \
    CP16(_st + B_LO + so0, pBl + go0 + _kb); CP16(_st + B_LO + so1, pBl + go1 + _kb); \
    } while (0)

    float acc[4][4][4];
    #pragma unroll
    for (int i = 0; i < 4; i++)
        #pragma unroll
        for (int j = 0; j < 4; j++)
            #pragma unroll
            for (int t = 0; t < 4; t++) acc[i][j][t] = 0.f;

    const int NC = KDIM / 32;   // 128 chunks

    LOADCHUNK(0, 0); CP_COMMIT();
    LOADCHUNK(1, 1); CP_COMMIT();

    // precomputed fragment address bases (per k16 inside loop)
    const uint32_t aRow = (uint32_t)(wm * 64 + (lane & 15)) * ROWB + ((lane >> 4) & 1) * 16u;
    const uint32_t bRow = (uint32_t)(wn * 32 + ((lane >> 4) << 3) + (lane & 7)) * ROWB
                        + ((lane >> 3) & 1) * 16u;

    for (int c = 0; c < NC; ++c) {
        if (c + 1 < NC) CP_WAIT1(); else CP_WAIT0();
        __syncthreads();

        const uint32_t stg = sb + (uint32_t)(c & 1) * STAGEB;
        #pragma unroll
        for (int k16 = 0; k16 < 2; ++k16) {
            const uint32_t kb = (uint32_t)k16 * 32u;
            uint32_t ah[4][4], al[4][4], bh[2][4], bl[2][4];
            #pragma unroll
            for (int i = 0; i < 4; i++) {
                uint32_t ra = stg + aRow + (uint32_t)(i * 16) * ROWB + kb;
                LDSM4(ah[i], ra + A_HI);
                LDSM4(al[i], ra + A_LO);
            }
            #pragma unroll
            for (int p = 0; p < 2; p++) {
                uint32_t rb = stg + bRow + (uint32_t)(p * 16) * ROWB + kb;
                LDSM4(bh[p], rb + B_HI);
                LDSM4(bl[p], rb + B_LO);
            }
            #pragma unroll
            for (int i = 0; i < 4; i++) {
                #pragma unroll
                for (int j = 0; j < 4; j++) {
                    const int p = j >> 1, f = (j & 1) * 2;
                    MMA16816(acc[i][j], ah[i], bh[p][f], bh[p][f + 1]);
                    MMA16816(acc[i][j], ah[i], bl[p][f], bl[p][f + 1]);
                    MMA16816(acc[i][j], al[i], bh[p][f], bh[p][f + 1]);
                }
            }
        }
        __syncthreads();
        if (c + 2 < NC) { LOADCHUNK(c + 2, c & 1); CP_COMMIT(); }
    }

    // epilogue: acc -> C (+bias). thread t: rows base+t/4, base+t/4+8; cols +(t%4)*2
    #pragma unroll
    for (int i = 0; i < 4; i++) {
        const int row0 = bm + wm * 64 + i * 16 + (lane >> 2);
        #pragma unroll
        for (int j = 0; j < 4; j++) {
            const int col = n0 + wn * 32 + j * 8 + (lane & 3) * 2;
            const float bx0 = bias[col], bx1 = bias[col + 1];
            float2 o0 = make_float2(acc[i][j][0] + bx0, acc[i][j][1] + bx1);
            float2 o1 = make_float2(acc[i][j][2] + bx0, acc[i][j][3] + bx1);
            *(float2*)&C[(size_t)row0 * ldc + col] = o0;
            *(float2*)&C[(size_t)(row0 + 8) * ldc + col] = o1;
        }
    }
#undef LOADCHUNK
}

// ---------------------------------------------------------------------------
// RoPE on g_q (T,NH,HD) and g_k (T,NKV,HD)
// ---------------------------------------------------------------------------
__global__ void rope_kernel(const float* __restrict__ fc, const float* __restrict__ fs)
{
    int idx = blockIdx.x * blockDim.x + threadIdx.x;
    const int QP = T_SEQ * NH  * (HD / 2);
    const int KP = T_SEQ * NKV * (HD / 2);
    if (idx < QP) {
        int t = idx / (NH * 64);
        int r = idx - t * (NH * 64);
        int h = r >> 6, i = r & 63;
        float c = fc[t * 64 + i], s = fs[t * 64 + i];
        float2* p = (float2*)&g_q[(size_t)t * DIM + h * HD + 2 * i];
        float2 v = *p;
        p->x = v.x * c - v.y * s;
        p->y = v.x * s + v.y * c;
    } else if (idx < QP + KP) {
        int j = idx - QP;
        int t = j / (NKV * 64);
        int r = j - t * (NKV * 64);
        int h = r >> 6, i = r & 63;
        float c = fc[t * 64 + i], s = fs[t * 64 + i];
        float2* p = (float2*)&g_k[(size_t)t * KVD + h * HD + 2 * i];
        float2 v = *p;
        p->x = v.x * c - v.y * s;
        p->y = v.x * s + v.y * c;
    }
}

// ---------------------------------------------------------------------------
// fp32 causal GQA flash attention (R1 version — passes; optimize next round)
// ---------------------------------------------------------------------------
#define FA_BM 128
#define FA_BN 32
#define FA_SMEM ((FA_BM + FA_BN + FA_BN) * HD * 4)

__global__ __launch_bounds__(128) void flash_attn_kernel(
    const float* __restrict__ q, const float* __restrict__ k,
    const float* __restrict__ v, float* __restrict__ out)
{
    extern __shared__ float smem[];
    float4* q_s = (float4*)smem;
    float4* k_s = q_s + FA_BM * 32;
    float4* v_s = k_s + FA_BN * 32;

    int qtile = gridDim.x - 1 - blockIdx.x;
    int h     = blockIdx.y;
    int kvh   = h >> 2;
    int tid   = threadIdx.x;
    int row   = tid;
    int qi    = qtile * FA_BM + row;

    for (int i = tid; i < FA_BM * 32; i += 128) {
        int r = i >> 5, c = i & 31;
        float4 val = *(const float4*)&q[(size_t)(qtile * FA_BM + r) * DIM + h * HD + c * 4];
        q_s[r * 32 + (c ^ (r & 7))] = val;
    }

    float m = -1e30f, l = 0.f;
    float accv[HD];
    #pragma unroll
    for (int d = 0; d < HD; d++) accv[d] = 0.f;

    const float scale = 0.08838834764831845f;
    int ntiles = (qtile + 1) * (FA_BM / FA_BN);
    int sw = row & 7;

    for (int jt = 0; jt < ntiles; jt++) {
        __syncthreads();
        for (int i = tid; i < FA_BN * 32; i += 128) {
            int r = i >> 5, c = i & 31;
            size_t goff = (size_t)(jt * FA_BN + r) * KVD + kvh * HD + c * 4;
            k_s[r * 32 + c] = *(const float4*)&k[goff];
            v_s[r * 32 + c] = *(const float4*)&v[goff];
        }
        __syncthreads();

        float s[FA_BN];
        #pragma unroll
        for (int j = 0; j < FA_BN; j++) s[j] = 0.f;
        #pragma unroll 8
        for (int d = 0; d < 32; d++) {
            float4 qv = q_s[row * 32 + (d ^ sw)];
            #pragma unroll
            for (int j = 0; j < FA_BN; j++) {
                float4 kv = k_s[j * 32 + d];
                s[j] = fmaf(qv.x, kv.x, s[j]);
                s[j] = fmaf(qv.y, kv.y, s[j]);
                s[j] = fmaf(qv.z, kv.z, s[j]);
                s[j] = fmaf(qv.w, kv.w, s[j]);
            }
        }

        int jbase = jt * FA_BN;
        float mt = m;
        #pragma unroll
        for (int j = 0; j < FA_BN; j++) {
            s[j] = (jbase + j <= qi) ? s[j] * scale : -1e30f;
            mt = fmaxf(mt, s[j]);
        }
        float corr = __expf(m - mt);
        float lsum = 0.f;
        #pragma unroll
        for (int j = 0; j < FA_BN; j++) { s[j] = __expf(s[j] - mt); lsum += s[j]; }
        m = mt;
        l = l * corr + lsum;
        #pragma unroll
        for (int d = 0; d < HD; d++) accv[d] *= corr;

        #pragma unroll
        for (int j = 0; j < FA_BN; j++) {
            float p = s[j];
            #pragma unroll
            for (int d4 = 0; d4 < 32; d4++) {
                float4 vv = v_s[j * 32 + d4];
                accv[d4*4+0] = fmaf(p, vv.x, accv[d4*4+0]);
                accv[d4*4+1] = fmaf(p, vv.y, accv[d4*4+1]);
                accv[d4*4+2] = fmaf(p, vv.z, accv[d4*4+2]);
                accv[d4*4+3] = fmaf(p, vv.w, accv[d4*4+3]);
            }
        }
    }

    float inv = 1.f / l;
    #pragma unroll
    for (int d4 = 0; d4 < 32; d4++) {
        float4 o;
        o.x = accv[d4*4+0] * inv;
        o.y = accv[d4*4+1] * inv;
        o.z = accv[d4*4+2] * inv;
        o.w = accv[d4*4+3] * inv;
        *(float4*)&out[(size_t)qi * DIM + h * HD + d4 * 4] = o;
    }
}

// ---------------------------------------------------------------------------
extern "C" void kernel_launch(void* const* d_in, const int* in_sizes, int n_in,
                              void* d_out, int out_size)
{
    const float* x    = (const float*)d_in[0];
    const float* fc   = (const float*)d_in[1];
    const float* fs   = (const float*)d_in[2];
    const float* wk_w = (const float*)d_in[6];
    const float* wk_b = (const float*)d_in[7];
    const float* wv_w = (const float*)d_in[8];
    const float* wv_b = (const float*)d_in[9];
    const float* wo_w = (const float*)d_in[10];
    const float* wo_b = (const float*)d_in[11];
    float* out = (float*)d_out;

    float *q, *k, *v, *att;
    cudaGetSymbolAddress((void**)&q,   g_q);
    cudaGetSymbolAddress((void**)&k,   g_k);
    cudaGetSymbolAddress((void**)&v,   g_v);
    cudaGetSymbolAddress((void**)&att, g_att);
    __nv_bfloat16 *xhi, *xlo, *wohi, *wolo, *wkhi, *wklo, *wvhi, *wvlo, *ahi, *alo;
    cudaGetSymbolAddress((void**)&xhi,  g_xhi);  cudaGetSymbolAddress((void**)&xlo,  g_xlo);
    cudaGetSymbolAddress((void**)&wohi, g_wohi); cudaGetSymbolAddress((void**)&wolo, g_wolo);
    cudaGetSymbolAddress((void**)&wkhi, g_wkhi); cudaGetSymbolAddress((void**)&wklo, g_wklo);
    cudaGetSymbolAddress((void**)&wvhi, g_wvhi); cudaGetSymbolAddress((void**)&wvlo, g_wvlo);
    cudaGetSymbolAddress((void**)&ahi,  g_ahi);  cudaGetSymbolAddress((void**)&alo,  g_alo);

    // 0) fp32 -> bf16 hi/lo splits
    split_kernel<<<(T_SEQ*DIM/4 + 255)/256, 256>>>(x,    xhi,  xlo,  T_SEQ*DIM/4);
    split_kernel<<<(DIM*DIM/4   + 255)/256, 256>>>(wo_w, wohi, wolo, DIM*DIM/4);
    split_kernel<<<(KVD*DIM/4   + 255)/256, 256>>>(wk_w, wkhi, wklo, KVD*DIM/4);
    split_kernel<<<(KVD*DIM/4   + 255)/256, 256>>>(wv_w, wvhi, wvlo, KVD*DIM/4);

    cudaFuncSetAttribute(mma_gemm_kernel,
                         cudaFuncAttributeMaxDynamicSharedMemorySize, GSMEM);

    // 1) fused QKV projection on tensor cores (q uses wo_w per reference)
    dim3 gqkv(48, 16);
    mma_gemm_kernel<<<gqkv, 256, GSMEM>>>(xhi, xlo,
                                          wohi, wolo, wo_b, q,
                                          wkhi, wklo, wk_b, k,
                                          wvhi, wvlo, wv_b, v);

    // 2) RoPE
    int ropeN = T_SEQ*NH*(HD/2) + T_SEQ*NKV*(HD/2);
    rope_kernel<<<(ropeN + 255)/256, 256>>>(fc, fs);

    // 3) causal GQA flash attention (fp32)
    cudaFuncSetAttribute(flash_attn_kernel,
                         cudaFuncAttributeMaxDynamicSharedMemorySize, FA_SMEM);
    dim3 gfa(T_SEQ / FA_BM, NH);
    flash_attn_kernel<<<gfa, 128, FA_SMEM>>>(q, k, v, att);

    // 4) output projection on tensor cores
    split_kernel<<<(T_SEQ*DIM/4 + 255)/256, 256>>>(att, ahi, alo, T_SEQ*DIM/4);
    dim3 go(32, 16);
    mma_gemm_kernel<<<go, 256, GSMEM>>>(ahi, alo,
                                        wohi, wolo, wo_b, out,
                                        wkhi, wklo, wk_b, q,
                                        wvhi, wvlo, wv_b, k);
}

// round 4
// speedup vs baseline: 3.0498x; 1.7575x over previous
#include <cuda_runtime.h>
#include <cuda_bf16.h>
#include <math.h>
#include <stdint.h>

#define T_SEQ 2048
#define DIM   4096
#define NH    32
#define NKV   8
#define HD    128
#define KVD   1024
#define KDIM  4096

// ---------------- scratch (static __device__, no allocation) ----------------
__device__ float g_q  [T_SEQ * DIM];
__device__ float g_k  [T_SEQ * KVD];
__device__ float g_v  [T_SEQ * KVD];
__device__ float g_att[T_SEQ * DIM];

__device__ __nv_bfloat16 g_xhi [T_SEQ * DIM], g_xlo [T_SEQ * DIM];   // x split, then reused as q split
__device__ __nv_bfloat16 g_wohi[DIM * DIM],   g_wolo[DIM * DIM];
__device__ __nv_bfloat16 g_wkhi[KVD * DIM],   g_wklo[KVD * DIM];     // reused as k split post-QKV
__device__ __nv_bfloat16 g_wvhi[KVD * DIM],   g_wvlo[KVD * DIM];     // reused as v split post-QKV
__device__ __nv_bfloat16 g_ahi [T_SEQ * DIM], g_alo [T_SEQ * DIM];

// ---------------- PTX helpers (baseline ISA only) ----------------
__device__ __forceinline__ uint32_t smem_u32(const void* p) {
    uint32_t a;
    asm("{ .reg .u64 t; cvta.to.shared.u64 t, %1; cvt.u32.u64 %0, t; }" : "=r"(a) : "l"(p));
    return a;
}
#define CP16(dst, src) asm volatile("cp.async.cg.shared.global [%0], [%1], 16;" :: "r"(dst), "l"(src))
#define CP_COMMIT()    asm volatile("cp.async.commit_group;" ::: "memory")
#define CP_WAIT1()     asm volatile("cp.async.wait_group 1;" ::: "memory")
#define CP_WAIT0()     asm volatile("cp.async.wait_group 0;" ::: "memory")

#define LDSM4(r, a) asm volatile( \
    "ldmatrix.sync.aligned.m8n8.x4.shared.b16 {%0,%1,%2,%3}, [%4];" \
    : "=r"((r)[0]), "=r"((r)[1]), "=r"((r)[2]), "=r"((r)[3]) : "r"(a))
#define LDSM4T(r, a) asm volatile( \
    "ldmatrix.sync.aligned.m8n8.x4.trans.shared.b16 {%0,%1,%2,%3}, [%4];" \
    : "=r"((r)[0]), "=r"((r)[1]), "=r"((r)[2]), "=r"((r)[3]) : "r"(a))

#define MMA16816(c, a, b0, b1) asm volatile( \
    "mma.sync.aligned.m16n8k16.row.col.f32.bf16.bf16.f32 " \
    "{%0,%1,%2,%3},{%4,%5,%6,%7},{%8,%9},{%0,%1,%2,%3};" \
    : "+f"((c)[0]), "+f"((c)[1]), "+f"((c)[2]), "+f"((c)[3]) \
    : "r"((a)[0]), "r"((a)[1]), "r"((a)[2]), "r"((a)[3]), "r"(b0), "r"(b1))

// ---------------------------------------------------------------------------
// split fp32 -> bf16 hi + bf16 lo (residual)
// ---------------------------------------------------------------------------
__global__ void split_kernel(const float* __restrict__ src,
                             __nv_bfloat16* __restrict__ hi,
                             __nv_bfloat16* __restrict__ lo, int n4)
{
    int i = blockIdx.x * blockDim.x + threadIdx.x;
    if (i >= n4) return;
    float4 v = ((const float4*)src)[i];
    __nv_bfloat162 h01 = __floats2bfloat162_rn(v.x, v.y);
    __nv_bfloat162 h23 = __floats2bfloat162_rn(v.z, v.w);
    float lx = v.x - __low2float(h01);
    float ly = v.y - __high2float(h01);
    float lz = v.z - __low2float(h23);
    float lw = v.w - __high2float(h23);
    ((__nv_bfloat162*)hi)[2*i]   = h01;
    ((__nv_bfloat162*)hi)[2*i+1] = h23;
    ((__nv_bfloat162*)lo)[2*i]   = __floats2bfloat162_rn(lx, ly);
    ((__nv_bfloat162*)lo)[2*i+1] = __floats2bfloat162_rn(lz, lw);
}

// ---------------------------------------------------------------------------
// bf16-split tensor-core GEMM (same as R3, passing at 258 TF/s effective)
// ---------------------------------------------------------------------------
#define ROWB   80u
#define A_HI   0u
#define A_LO   10240u
#define B_HI   20480u
#define B_LO   30720u
#define STAGEB 40960u
#define GSMEM  (2 * 40960)

__global__ __launch_bounds__(256, 1) void mma_gemm_kernel(
    const __nv_bfloat16* __restrict__ Ahi, const __nv_bfloat16* __restrict__ Alo,
    const __nv_bfloat16* __restrict__ W0hi, const __nv_bfloat16* __restrict__ W0lo,
    const float* __restrict__ b0, float* __restrict__ C0,
    const __nv_bfloat16* __restrict__ W1hi, const __nv_bfloat16* __restrict__ W1lo,
    const float* __restrict__ b1, float* __restrict__ C1,
    const __nv_bfloat16* __restrict__ W2hi, const __nv_bfloat16* __restrict__ W2lo,
    const float* __restrict__ b2, float* __restrict__ C2)
{
    extern __shared__ char dsm[];
    const uint32_t sb = smem_u32(dsm);

    int bx = blockIdx.x;
    const __nv_bfloat16 *Whi, *Wlo; const float* bias; float* C; int n0, ldc;
    if (bx < 32)      { Whi = W0hi; Wlo = W0lo; bias = b0; C = C0; n0 = bx * 128;        ldc = DIM; }
    else if (bx < 40) { Whi = W1hi; Wlo = W1lo; bias = b1; C = C1; n0 = (bx - 32) * 128; ldc = KVD; }
    else              { Whi = W2hi; Wlo = W2lo; bias = b2; C = C2; n0 = (bx - 40) * 128; ldc = KVD; }

    const int bm   = blockIdx.y * 128;
    const int tid  = threadIdx.x;
    const int lane = tid & 31;
    const int wid  = tid >> 5;
    const int wm   = wid & 1;
    const int wn   = wid >> 1;

    const int r0 = tid >> 2, cc = tid & 3;
    const uint32_t so0 = (uint32_t)r0 * ROWB + cc * 16u;
    const uint32_t so1 = so0 + 64u * ROWB;
    const size_t  go0 = (size_t)r0 * 8192 + cc * 16;
    const size_t  go1 = go0 + (size_t)64 * 8192;

    const char* pAh = (const char*)Ahi + (size_t)bm * 8192;
    const char* pAl = (const char*)Alo + (size_t)bm * 8192;
    const char* pBh = (const char*)Whi + (size_t)n0 * 8192;
    const char* pBl = (const char*)Wlo + (size_t)n0 * 8192;

#define LOADCHUNK(cidx, s) do { \
    uint32_t _st = sb + (uint32_t)(s) * STAGEB; \
    size_t _kb = (size_t)(cidx) * 64; \
    CP16(_st + A_HI + so0, pAh + go0 + _kb); CP16(_st + A_HI + so1, pAh + go1 + _kb); \
    CP16(_st + A_LO + so0, pAl + go0 + _kb); CP16(_st + A_LO + so1, pAl + go1 + _kb); \
    CP16(_st + B_HI + so0, pBh + go0 + _kb); CP16(_st + B_HI + so1, pBh + go1 + _kb); \
    CP16(_st + B_LO + so0, pBl + go0 + _kb); CP16(_st + B_LO + so1, pBl + go1 + _kb); \
    } while (0)

    float acc[4][4][4];
    #pragma unroll
    for (int i = 0; i < 4; i++)
        #pragma unroll
        for (int j = 0; j < 4; j++)
            #pragma unroll
            for (int t = 0; t < 4; t++) acc[i][j][t] = 0.f;

    const int NC = KDIM / 32;

    LOADCHUNK(0, 0); CP_COMMIT();
    LOADCHUNK(1, 1); CP_COMMIT();

    const uint32_t aRow = (uint32_t)(wm * 64 + (lane & 15)) * ROWB + ((lane >> 4) & 1) * 16u;
    const uint32_t bRow = (uint32_t)(wn * 32 + ((lane >> 4) << 3) + (lane & 7)) * ROWB
                        + ((lane >> 3) & 1) * 16u;

    for (int c = 0; c < NC; ++c) {
        if (c + 1 < NC) CP_WAIT1(); else CP_WAIT0();
        __syncthreads();

        const uint32_t stg = sb + (uint32_t)(c & 1) * STAGEB;
        #pragma unroll
        for (int k16 = 0; k16 < 2; ++k16) {
            const uint32_t kb = (uint32_t)k16 * 32u;
            uint32_t ah[4][4], al[4][4], bh[2][4], bl[2][4];
            #pragma unroll
            for (int i = 0; i < 4; i++) {
                uint32_t ra = stg + aRow + (uint32_t)(i * 16) * ROWB + kb;
                LDSM4(ah[i], ra + A_HI);
                LDSM4(al[i], ra + A_LO);
            }
            #pragma unroll
            for (int p = 0; p < 2; p++) {
                uint32_t rb = stg + bRow + (uint32_t)(p * 16) * ROWB + kb;
                LDSM4(bh[p], rb + B_HI);
                LDSM4(bl[p], rb + B_LO);
            }
            #pragma unroll
            for (int i = 0; i < 4; i++) {
                #pragma unroll
                for (int j = 0; j < 4; j++) {
                    const int p = j >> 1, f = (j & 1) * 2;
                    MMA16816(acc[i][j], ah[i], bh[p][f], bh[p][f + 1]);
                    MMA16816(acc[i][j], ah[i], bl[p][f], bl[p][f + 1]);
                    MMA16816(acc[i][j], al[i], bh[p][f], bh[p][f + 1]);
                }
            }
        }
        __syncthreads();
        if (c + 2 < NC) { LOADCHUNK(c + 2, c & 1); CP_COMMIT(); }
    }

    #pragma unroll
    for (int i = 0; i < 4; i++) {
        const int row0 = bm + wm * 64 + i * 16 + (lane >> 2);
        #pragma unroll
        for (int j = 0; j < 4; j++) {
            const int col = n0 + wn * 32 + j * 8 + (lane & 3) * 2;
            const float bx0 = bias[col], bx1 = bias[col + 1];
            float2 o0 = make_float2(acc[i][j][0] + bx0, acc[i][j][1] + bx1);
            float2 o1 = make_float2(acc[i][j][2] + bx0, acc[i][j][3] + bx1);
            *(float2*)&C[(size_t)row0 * ldc + col] = o0;
            *(float2*)&C[(size_t)(row0 + 8) * ldc + col] = o1;
        }
    }
#undef LOADCHUNK
}

// ---------------------------------------------------------------------------
// RoPE on g_q (T,NH,HD) and g_k (T,NKV,HD)
// ---------------------------------------------------------------------------
__global__ void rope_kernel(const float* __restrict__ fc, const float* __restrict__ fs)
{
    int idx = blockIdx.x * blockDim.x + threadIdx.x;
    const int QP = T_SEQ * NH  * (HD / 2);
    const int KP = T_SEQ * NKV * (HD / 2);
    if (idx < QP) {
        int t = idx / (NH * 64);
        int r = idx - t * (NH * 64);
        int h = r >> 6, i = r & 63;
        float c = fc[t * 64 + i], s = fs[t * 64 + i];
        float2* p = (float2*)&g_q[(size_t)t * DIM + h * HD + 2 * i];
        float2 v = *p;
        p->x = v.x * c - v.y * s;
        p->y = v.x * s + v.y * c;
    } else if (idx < QP + KP) {
        int j = idx - QP;
        int t = j / (NKV * 64);
        int r = j - t * (NKV * 64);
        int h = r >> 6, i = r & 63;
        float c = fc[t * 64 + i], s = fs[t * 64 + i];
        float2* p = (float2*)&g_k[(size_t)t * KVD + h * HD + 2 * i];
        float2 v = *p;
        p->x = v.x * c - v.y * s;
        p->y = v.x * s + v.y * c;
    }
}

// ---------------------------------------------------------------------------
// Tensor-core flash attention (bf16-split, fp32 softmax), causal, GQA.
// CTA = 128 q rows x 1 head, 8 warps (16 rows each), BN=64, double-buffered KV.
// ---------------------------------------------------------------------------
#define FROWB  272u                 // 128 bf16 (256B) + 16B pad, odd 16B stride
#define SQH    0u
#define SQL    34816u               // 128*272
#define SKV    69632u
#define KLOFF  17408u               // 64*272
#define VHOFF  34816u
#define VLOFF  52224u
#define KVSTG  69632u               // 4 arrays * 64*272
#define FA2SMEM (69632 + 2 * 69632) // 208896

__global__ __launch_bounds__(256, 1) void fa_mma_kernel(
    const __nv_bfloat16* __restrict__ qhi, const __nv_bfloat16* __restrict__ qlo,
    const __nv_bfloat16* __restrict__ khi, const __nv_bfloat16* __restrict__ klo,
    const __nv_bfloat16* __restrict__ vhi, const __nv_bfloat16* __restrict__ vlo,
    float* __restrict__ out)
{
    extern __shared__ char sm[];
    const uint32_t sb = smem_u32(sm);

    const int qtile = gridDim.x - 1 - blockIdx.x;     // heavy tiles first
    const int h = blockIdx.y, kvh = h >> 2;
    const int tid = threadIdx.x, wid = tid >> 5, lane = tid & 31;
    const int qbase = qtile * 128;

    // ---- Q tile load (rows 128, 16x16B chunks/row, hi+lo) ----
    {
        const char* gq0 = (const char*)qhi + ((size_t)qbase * DIM + h * HD) * 2;
        const char* gq1 = (const char*)qlo + ((size_t)qbase * DIM + h * HD) * 2;
        for (int i = tid; i < 2048; i += 256) {
            uint32_t r = i >> 4, c = i & 15;
            CP16(sb + SQH + r * FROWB + c * 16, gq0 + (size_t)r * 8192 + c * 16);
            CP16(sb + SQL + r * FROWB + c * 16, gq1 + (size_t)r * 8192 + c * 16);
        }
    }

#define LOADKV(jb, s) do { \
    uint32_t _st = sb + SKV + (uint32_t)(s) * KVSTG; \
    size_t _gb = ((size_t)(jb) * KVD + kvh * HD) * 2; \
    for (int _i = tid; _i < 1024; _i += 256) { \
        uint32_t _r = _i >> 4, _c = _i & 15; \
        uint32_t _d = _st + _r * FROWB + _c * 16; \
        size_t _s2 = _gb + (size_t)_r * 2048 + _c * 16; \
        CP16(_d,          (const char*)khi + _s2); \
        CP16(_d + KLOFF,  (const char*)klo + _s2); \
        CP16(_d + VHOFF,  (const char*)vhi + _s2); \
        CP16(_d + VLOFF,  (const char*)vlo + _s2); \
    } } while (0)

    const int NT = (qtile + 1) * 2;
    LOADKV(0, 0);
    CP_COMMIT();

    float m0 = -1e30f, m1 = -1e30f, l0 = 0.f, l1 = 0.f;
    float acc_o[16][4];
    #pragma unroll
    for (int n = 0; n < 16; n++)
        #pragma unroll
        for (int t = 0; t < 4; t++) acc_o[n][t] = 0.f;

    const float kl = 0.12751689f;  // (1/sqrt(128)) * log2(e)
    const uint32_t aoff = (uint32_t)(wid * 16 + (lane & 15)) * FROWB + (uint32_t)((lane >> 4) & 1) * 16u;
    const uint32_t boffBase = (uint32_t)(((lane >> 4) << 3) + (lane & 7)) * FROWB
                            + (uint32_t)((lane >> 3) & 1) * 16u;
    const uint32_t voffBase = (uint32_t)(lane & 15) * FROWB + (uint32_t)(lane >> 4) * 16u;
    const int r0g = qbase + wid * 16 + (lane >> 2);

    for (int c = 0; c < NT; ++c) {
        if (c + 1 < NT) { LOADKV((c + 1) * 64, (c + 1) & 1); CP_COMMIT(); CP_WAIT1(); }
        else           { CP_WAIT0(); }
        __syncthreads();

        const uint32_t stg = sb + SKV + (uint32_t)(c & 1) * KVSTG;

        // ---- S = Q K^T (3-term split) ----
        float s[8][4];
        #pragma unroll
        for (int j = 0; j < 8; j++)
            #pragma unroll
            for (int t = 0; t < 4; t++) s[j][t] = 0.f;

        #pragma unroll
        for (int kk = 0; kk < 8; ++kk) {
            uint32_t ah[4], al[4];
            LDSM4(ah, sb + SQH + aoff + kk * 32);
            LDSM4(al, sb + SQL + aoff + kk * 32);
            #pragma unroll
            for (int g = 0; g < 4; ++g) {
                uint32_t bh[4], bl[4];
                uint32_t bo = stg + (uint32_t)(g * 16) * FROWB + boffBase + kk * 32;
                LDSM4(bh, bo);
                LDSM4(bl, bo + KLOFF);
                MMA16816(s[2*g],   ah, bh[0], bh[1]);
                MMA16816(s[2*g],   ah, bl[0], bl[1]);
                MMA16816(s[2*g],   al, bh[0], bh[1]);
                MMA16816(s[2*g+1], ah, bh[2], bh[3]);
                MMA16816(s[2*g+1], ah, bl[2], bl[3]);
                MMA16816(s[2*g+1], al, bh[2], bh[3]);
            }
        }

        // ---- causal mask ----
        const int jbase = c * 64;
        if (jbase + 63 > qbase + wid * 16) {
            #pragma unroll
            for (int j = 0; j < 8; j++) {
                int col = jbase + j * 8 + (lane & 3) * 2;
                if (col     > r0g)     s[j][0] = -1e30f;
                if (col + 1 > r0g)     s[j][1] = -1e30f;
                if (col     > r0g + 8) s[j][2] = -1e30f;
                if (col + 1 > r0g + 8) s[j][3] = -1e30f;
            }
        }

        // ---- online softmax ----
        float mx0 = -1e30f, mx1 = -1e30f;
        #pragma unroll
        for (int j = 0; j < 8; j++) {
            mx0 = fmaxf(mx0, fmaxf(s[j][0], s[j][1]));
            mx1 = fmaxf(mx1, fmaxf(s[j][2], s[j][3]));
        }
        mx0 = fmaxf(mx0, __shfl_xor_sync(0xFFFFFFFFu, mx0, 1));
        mx0 = fmaxf(mx0, __shfl_xor_sync(0xFFFFFFFFu, mx0, 2));
        mx1 = fmaxf(mx1, __shfl_xor_sync(0xFFFFFFFFu, mx1, 1));
        mx1 = fmaxf(mx1, __shfl_xor_sync(0xFFFFFFFFu, mx1, 2));
        const float nm0 = fmaxf(m0, mx0), nm1 = fmaxf(m1, mx1);
        const float corr0 = exp2f((m0 - nm0) * kl), corr1 = exp2f((m1 - nm1) * kl);
        const float nb0 = -nm0 * kl, nb1 = -nm1 * kl;
        float sum0 = 0.f, sum1 = 0.f;
        #pragma unroll
        for (int j = 0; j < 8; j++) {
            s[j][0] = exp2f(fmaf(s[j][0], kl, nb0));
            s[j][1] = exp2f(fmaf(s[j][1], kl, nb0));
            s[j][2] = exp2f(fmaf(s[j][2], kl, nb1));
            s[j][3] = exp2f(fmaf(s[j][3], kl, nb1));
            sum0 += s[j][0] + s[j][1];
            sum1 += s[j][2] + s[j][3];
        }
        sum0 += __shfl_xor_sync(0xFFFFFFFFu, sum0, 1);
        sum0 += __shfl_xor_sync(0xFFFFFFFFu, sum0, 2);
        sum1 += __shfl_xor_sync(0xFFFFFFFFu, sum1, 1);
        sum1 += __shfl_xor_sync(0xFFFFFFFFu, sum1, 2);
        l0 = l0 * corr0 + sum0;
        l1 = l1 * corr1 + sum1;
        m0 = nm0; m1 = nm1;
        #pragma unroll
        for (int n = 0; n < 16; n++) {
            acc_o[n][0] *= corr0; acc_o[n][1] *= corr0;
            acc_o[n][2] *= corr1; acc_o[n][3] *= corr1;
        }

        // ---- P fragments (hi + lo residual) ----
        uint32_t aPh[4][4], aPl[4][4];
        #pragma unroll
        for (int g = 0; g < 4; ++g) {
            #pragma unroll
            for (int part = 0; part < 4; ++part) {
                const int j = 2 * g + (part >> 1);
                const int e = (part & 1) * 2;
                float x = s[j][e], y = s[j][e + 1];
                __nv_bfloat16 hx = __float2bfloat16(x), hy = __float2bfloat16(y);
                float rx = x - __bfloat162float(hx);
                float ry = y - __bfloat162float(hy);
                __nv_bfloat162 vh = __halves2bfloat162(hx, hy);
                __nv_bfloat162 vl = __floats2bfloat162_rn(rx, ry);
                aPh[g][part] = *(uint32_t*)&vh;
                aPl[g][part] = *(uint32_t*)&vl;
            }
        }

        // ---- O += P V (3-term split), V via ldmatrix.trans ----
        #pragma unroll
        for (int n16 = 0; n16 < 8; ++n16) {
            #pragma unroll
            for (int kk = 0; kk < 4; ++kk) {
                uint32_t vhf[4], vlf[4];
                uint32_t vo = stg + (uint32_t)(kk * 16) * FROWB + voffBase + n16 * 32;
                LDSM4T(vhf, vo + VHOFF);
                LDSM4T(vlf, vo + VLOFF);
                MMA16816(acc_o[2*n16],   aPh[kk], vhf[0], vhf[1]);
                MMA16816(acc_o[2*n16],   aPh[kk], vlf[0], vlf[1]);
                MMA16816(acc_o[2*n16],   aPl[kk], vhf[0], vhf[1]);
                MMA16816(acc_o[2*n16+1], aPh[kk], vhf[2], vhf[3]);
                MMA16816(acc_o[2*n16+1], aPh[kk], vlf[2], vlf[3]);
                MMA16816(acc_o[2*n16+1], aPl[kk], vhf[2], vhf[3]);
            }
        }
        __syncthreads();
    }

    // ---- epilogue ----
    const float inv0 = 1.f / l0, inv1 = 1.f / l1;
    #pragma unroll
    for (int n8 = 0; n8 < 16; ++n8) {
        const int col = h * HD + n8 * 8 + (lane & 3) * 2;
        float2 o0 = make_float2(acc_o[n8][0] * inv0, acc_o[n8][1] * inv0);
        float2 o1 = make_float2(acc_o[n8][2] * inv1, acc_o[n8][3] * inv1);
        *(float2*)&out[(size_t)r0g * DIM + col] = o0;
        *(float2*)&out[(size_t)(r0g + 8) * DIM + col] = o1;
    }
#undef LOADKV
}

// ---------------------------------------------------------------------------
extern "C" void kernel_launch(void* const* d_in, const int* in_sizes, int n_in,
                              void* d_out, int out_size)
{
    const float* x    = (const float*)d_in[0];
    const float* fc   = (const float*)d_in[1];
    const float* fs   = (const float*)d_in[2];
    const float* wk_w = (const float*)d_in[6];
    const float* wk_b = (const float*)d_in[7];
    const float* wv_w = (const float*)d_in[8];
    const float* wv_b = (const float*)d_in[9];
    const float* wo_w = (const float*)d_in[10];
    const float* wo_b = (const float*)d_in[11];
    float* out = (float*)d_out;

    float *q, *k, *v, *att;
    cudaGetSymbolAddress((void**)&q,   g_q);
    cudaGetSymbolAddress((void**)&k,   g_k);
    cudaGetSymbolAddress((void**)&v,   g_v);
    cudaGetSymbolAddress((void**)&att, g_att);
    __nv_bfloat16 *xhi, *xlo, *wohi, *wolo, *wkhi, *wklo, *wvhi, *wvlo, *ahi, *alo;
    cudaGetSymbolAddress((void**)&xhi,  g_xhi);  cudaGetSymbolAddress((void**)&xlo,  g_xlo);
    cudaGetSymbolAddress((void**)&wohi, g_wohi); cudaGetSymbolAddress((void**)&wolo, g_wolo);
    cudaGetSymbolAddress((void**)&wkhi, g_wkhi); cudaGetSymbolAddress((void**)&wklo, g_wklo);
    cudaGetSymbolAddress((void**)&wvhi, g_wvhi); cudaGetSymbolAddress((void**)&wvlo, g_wvlo);
    cudaGetSymbolAddress((void**)&ahi,  g_ahi);  cudaGetSymbolAddress((void**)&alo,  g_alo);

    // 0) fp32 -> bf16 hi/lo splits (inputs + weights)
    split_kernel<<<(T_SEQ*DIM/4 + 255)/256, 256>>>(x,    xhi,  xlo,  T_SEQ*DIM/4);
    split_kernel<<<(DIM*DIM/4   + 255)/256, 256>>>(wo_w, wohi, wolo, DIM*DIM/4);
    split_kernel<<<(KVD*DIM/4   + 255)/256, 256>>>(wk_w, wkhi, wklo, KVD*DIM/4);
    split_kernel<<<(KVD*DIM/4   + 255)/256, 256>>>(wv_w, wvhi, wvlo, KVD*DIM/4);

    cudaFuncSetAttribute(mma_gemm_kernel,
                         cudaFuncAttributeMaxDynamicSharedMemorySize, GSMEM);

    // 1) fused QKV projection (q uses wo_w per reference)
    dim3 gqkv(48, 16);
    mma_gemm_kernel<<<gqkv, 256, GSMEM>>>(xhi, xlo,
                                          wohi, wolo, wo_b, q,
                                          wkhi, wklo, wk_b, k,
                                          wvhi, wvlo, wv_b, v);

    // 2) RoPE on q, k (fp32 in-place)
    int ropeN = T_SEQ*NH*(HD/2) + T_SEQ*NKV*(HD/2);
    rope_kernel<<<(ropeN + 255)/256, 256>>>(fc, fs);

    // 3) split q/k/v to bf16 hi/lo (reuse x and wk/wv split buffers)
    split_kernel<<<(T_SEQ*DIM/4 + 255)/256, 256>>>(q, xhi,  xlo,  T_SEQ*DIM/4);
    split_kernel<<<(T_SEQ*KVD/4 + 255)/256, 256>>>(k, wkhi, wklo, T_SEQ*KVD/4);
    split_kernel<<<(T_SEQ*KVD/4 + 255)/256, 256>>>(v, wvhi, wvlo, T_SEQ*KVD/4);

    // 4) tensor-core causal GQA flash attention
    cudaFuncSetAttribute(fa_mma_kernel,
                         cudaFuncAttributeMaxDynamicSharedMemorySize, FA2SMEM);
    dim3 gfa(T_SEQ / 128, NH);
    fa_mma_kernel<<<gfa, 256, FA2SMEM>>>(xhi, xlo, wkhi, wklo, wvhi, wvlo, att);

    // 5) output projection
    split_kernel<<<(T_SEQ*DIM/4 + 255)/256, 256>>>(att, ahi, alo, T_SEQ*DIM/4);
    dim3 go(32, 16);
    mma_gemm_kernel<<<go, 256, GSMEM>>>(ahi, alo,
                                        wohi, wolo, wo_b, out,
                                        wkhi, wklo, wk_b, q,
                                        wvhi, wvlo, wv_b, k);
}

// round 5
// speedup vs baseline: 3.1417x; 1.0301x over previous
#include <cuda_runtime.h>
#include <cuda_bf16.h>
#include <math.h>
#include <stdint.h>

#define T_SEQ 2048
#define DIM   4096
#define NH    32
#define NKV   8
#define HD    128
#define KVD   1024
#define KDIM  4096

// ---------------- scratch (static __device__, no allocation) ----------------
__device__ __nv_bfloat16 g_xhi [T_SEQ * DIM], g_xlo [T_SEQ * DIM];
__device__ __nv_bfloat16 g_wohi[DIM * DIM],   g_wolo[DIM * DIM];
__device__ __nv_bfloat16 g_wkhi[KVD * DIM],   g_wklo[KVD * DIM];
__device__ __nv_bfloat16 g_wvhi[KVD * DIM],   g_wvlo[KVD * DIM];
__device__ __nv_bfloat16 g_qhi [T_SEQ * DIM], g_qlo [T_SEQ * DIM];
__device__ __nv_bfloat16 g_khi [T_SEQ * KVD], g_klo [T_SEQ * KVD];
__device__ __nv_bfloat16 g_vhi [T_SEQ * KVD], g_vlo [T_SEQ * KVD];
__device__ __nv_bfloat16 g_ahi [T_SEQ * DIM], g_alo [T_SEQ * DIM];

// ---------------- PTX helpers (baseline ISA only) ----------------
__device__ __forceinline__ uint32_t smem_u32(const void* p) {
    uint32_t a;
    asm("{ .reg .u64 t; cvta.to.shared.u64 t, %1; cvt.u32.u64 %0, t; }" : "=r"(a) : "l"(p));
    return a;
}
#define CP16(dst, src) asm volatile("cp.async.cg.shared.global [%0], [%1], 16;" :: "r"(dst), "l"(src))
#define CP_COMMIT()    asm volatile("cp.async.commit_group;" ::: "memory")
#define CP_WAIT2()     asm volatile("cp.async.wait_group 2;" ::: "memory")
#define CP_WAIT0()     asm volatile("cp.async.wait_group 0;" ::: "memory")

#define LDSM4(r, a) asm volatile( \
    "ldmatrix.sync.aligned.m8n8.x4.shared.b16 {%0,%1,%2,%3}, [%4];" \
    : "=r"((r)[0]), "=r"((r)[1]), "=r"((r)[2]), "=r"((r)[3]) : "r"(a))
#define LDSM4T(r, a) asm volatile( \
    "ldmatrix.sync.aligned.m8n8.x4.trans.shared.b16 {%0,%1,%2,%3}, [%4];" \
    : "=r"((r)[0]), "=r"((r)[1]), "=r"((r)[2]), "=r"((r)[3]) : "r"(a))

#define MMA16816(c, a, b0, b1) asm volatile( \
    "mma.sync.aligned.m16n8k16.row.col.f32.bf16.bf16.f32 " \
    "{%0,%1,%2,%3},{%4,%5,%6,%7},{%8,%9},{%0,%1,%2,%3};" \
    : "+f"((c)[0]), "+f"((c)[1]), "+f"((c)[2]), "+f"((c)[3]) \
    : "r"((a)[0]), "r"((a)[1]), "r"((a)[2]), "r"((a)[3]), "r"(b0), "r"(b1))

__device__ __forceinline__ uint32_t pack_hi(float x, float y, float& rx, float& ry) {
    __nv_bfloat16 hx = __float2bfloat16(x), hy = __float2bfloat16(y);
    rx = x - __bfloat162float(hx);
    ry = y - __bfloat162float(hy);
    __nv_bfloat162 h = __halves2bfloat162(hx, hy);
    return *(uint32_t*)&h;
}

// ---------------------------------------------------------------------------
// split fp32 -> bf16 hi + bf16 lo (residual)  [x + 3 weights only]
// ---------------------------------------------------------------------------
__global__ void split_kernel(const float* __restrict__ src,
                             __nv_bfloat16* __restrict__ hi,
                             __nv_bfloat16* __restrict__ lo, int n4)
{
    int i = blockIdx.x * blockDim.x + threadIdx.x;
    if (i >= n4) return;
    float4 v = ((const float4*)src)[i];
    __nv_bfloat162 h01 = __floats2bfloat162_rn(v.x, v.y);
    __nv_bfloat162 h23 = __floats2bfloat162_rn(v.z, v.w);
    float lx = v.x - __low2float(h01);
    float ly = v.y - __high2float(h01);
    float lz = v.z - __low2float(h23);
    float lw = v.w - __high2float(h23);
    ((__nv_bfloat162*)hi)[2*i]   = h01;
    ((__nv_bfloat162*)hi)[2*i+1] = h23;
    ((__nv_bfloat162*)lo)[2*i]   = __floats2bfloat162_rn(lx, ly);
    ((__nv_bfloat162*)lo)[2*i+1] = __floats2bfloat162_rn(lz, lw);
}

// ---------------------------------------------------------------------------
// bf16-split tensor-core GEMM, 4-stage cp.async pipeline, 1 sync/chunk.
// MODE 0 (QKV): epilogue = bias + RoPE(q,k) + bf16 hi/lo split writes.
// MODE 1 (out-proj): epilogue = bias + fp32 write.
// ---------------------------------------------------------------------------
#define ROWB   80u
#define A_HI   0u
#define A_LO   10240u
#define B_HI   20480u
#define B_LO   30720u
#define STAGEB 40960u
#define NSTG   4
#define GSMEM  (NSTG * 40960)

template<int MODE>
__global__ __launch_bounds__(256, 1) void mma_gemm_kernel(
    const __nv_bfloat16* __restrict__ Ahi, const __nv_bfloat16* __restrict__ Alo,
    const __nv_bfloat16* __restrict__ W0hi, const __nv_bfloat16* __restrict__ W0lo,
    const float* __restrict__ b0,
    const __nv_bfloat16* __restrict__ W1hi, const __nv_bfloat16* __restrict__ W1lo,
    const float* __restrict__ b1,
    const __nv_bfloat16* __restrict__ W2hi, const __nv_bfloat16* __restrict__ W2lo,
    const float* __restrict__ b2,
    float* __restrict__ Cout,
    __nv_bfloat16* __restrict__ C0hi, __nv_bfloat16* __restrict__ C0lo,
    __nv_bfloat16* __restrict__ C1hi, __nv_bfloat16* __restrict__ C1lo,
    __nv_bfloat16* __restrict__ C2hi, __nv_bfloat16* __restrict__ C2lo,
    const float* __restrict__ fc, const float* __restrict__ fs)
{
    extern __shared__ char dsm[];
    const uint32_t sb = smem_u32(dsm);

    const int bx = blockIdx.x;
    const __nv_bfloat16 *Whi, *Wlo; const float* bias; int n0, ldc, region;
    __nv_bfloat16 *Chi, *Clo;
    if (bx < 32)      { Whi = W0hi; Wlo = W0lo; bias = b0; n0 = bx * 128;        ldc = DIM; region = 0; Chi = C0hi; Clo = C0lo; }
    else if (bx < 40) { Whi = W1hi; Wlo = W1lo; bias = b1; n0 = (bx - 32) * 128; ldc = KVD; region = 1; Chi = C1hi; Clo = C1lo; }
    else              { Whi = W2hi; Wlo = W2lo; bias = b2; n0 = (bx - 40) * 128; ldc = KVD; region = 2; Chi = C2hi; Clo = C2lo; }

    const int bm   = blockIdx.y * 128;
    const int tid  = threadIdx.x;
    const int lane = tid & 31;
    const int wid  = tid >> 5;
    const int wm   = wid & 1;
    const int wn   = wid >> 1;

    const int r0 = tid >> 2, cc = tid & 3;
    const uint32_t so0 = (uint32_t)r0 * ROWB + cc * 16u;
    const uint32_t so1 = so0 + 64u * ROWB;
    const size_t  go0 = (size_t)r0 * 8192 + cc * 16;
    const size_t  go1 = go0 + (size_t)64 * 8192;

    const char* pAh = (const char*)Ahi + (size_t)bm * 8192;
    const char* pAl = (const char*)Alo + (size_t)bm * 8192;
    const char* pBh = (const char*)Whi + (size_t)n0 * 8192;
    const char* pBl = (const char*)Wlo + (size_t)n0 * 8192;

#define LOADCHUNK(cidx, s) do { \
    uint32_t _st = sb + (uint32_t)(s) * STAGEB; \
    size_t _kb = (size_t)(cidx) * 64; \
    CP16(_st + A_HI + so0, pAh + go0 + _kb); CP16(_st + A_HI + so1, pAh + go1 + _kb); \
    CP16(_st + A_LO + so0, pAl + go0 + _kb); CP16(_st + A_LO + so1, pAl + go1 + _kb); \
    CP16(_st + B_HI + so0, pBh + go0 + _kb); CP16(_st + B_HI + so1, pBh + go1 + _kb); \
    CP16(_st + B_LO + so0, pBl + go0 + _kb); CP16(_st + B_LO + so1, pBl + go1 + _kb); \
    } while (0)

    float acc[4][4][4];
    #pragma unroll
    for (int i = 0; i < 4; i++)
        #pragma unroll
        for (int j = 0; j < 4; j++)
            #pragma unroll
            for (int t = 0; t < 4; t++) acc[i][j][t] = 0.f;

    const int NC = KDIM / 32;   // 128 chunks

    LOADCHUNK(0, 0); CP_COMMIT();
    LOADCHUNK(1, 1); CP_COMMIT();
    LOADCHUNK(2, 2); CP_COMMIT();

    const uint32_t aRow = (uint32_t)(wm * 64 + (lane & 15)) * ROWB + ((lane >> 4) & 1) * 16u;
    const uint32_t bRow = (uint32_t)(wn * 32 + ((lane >> 4) << 3) + (lane & 7)) * ROWB
                        + ((lane >> 3) & 1) * 16u;

    for (int c = 0; c < NC; ++c) {
        CP_WAIT2();                       // chunk c resident (3 groups pending max)
        __syncthreads();                  // all warps done with stage (c-1)&3
        if (c + 3 < NC) LOADCHUNK(c + 3, (c + 3) & NSTG - 1);
        CP_COMMIT();                      // always commit: keeps wait_group exact

        const uint32_t stg = sb + (uint32_t)(c & (NSTG - 1)) * STAGEB;
        #pragma unroll
        for (int k16 = 0; k16 < 2; ++k16) {
            const uint32_t kb = (uint32_t)k16 * 32u;
            uint32_t ah[4][4], al[4][4], bh[2][4], bl[2][4];
            #pragma unroll
            for (int i = 0; i < 4; i++) {
                uint32_t ra = stg + aRow + (uint32_t)(i * 16) * ROWB + kb;
                LDSM4(ah[i], ra + A_HI);
                LDSM4(al[i], ra + A_LO);
            }
            #pragma unroll
            for (int p = 0; p < 2; p++) {
                uint32_t rb = stg + bRow + (uint32_t)(p * 16) * ROWB + kb;
                LDSM4(bh[p], rb + B_HI);
                LDSM4(bl[p], rb + B_LO);
            }
            #pragma unroll
            for (int i = 0; i < 4; i++) {
                #pragma unroll
                for (int j = 0; j < 4; j++) {
                    const int p = j >> 1, f = (j & 1) * 2;
                    MMA16816(acc[i][j], ah[i], bh[p][f], bh[p][f + 1]);
                    MMA16816(acc[i][j], ah[i], bl[p][f], bl[p][f + 1]);
                    MMA16816(acc[i][j], al[i], bh[p][f], bh[p][f + 1]);
                }
            }
        }
    }

    // ---- epilogue ----
    #pragma unroll
    for (int i = 0; i < 4; i++) {
        const int row0 = bm + wm * 64 + i * 16 + (lane >> 2);
        #pragma unroll
        for (int j = 0; j < 4; j++) {
            const int col = n0 + wn * 32 + j * 8 + (lane & 3) * 2;
            const float bv0 = bias[col], bv1 = bias[col + 1];
            #pragma unroll
            for (int t = 0; t < 2; t++) {
                const int row = row0 + t * 8;
                float v0 = acc[i][j][2 * t]     + bv0;
                float v1 = acc[i][j][2 * t + 1] + bv1;
                if (MODE == 0) {
                    if (region != 2) {       // RoPE on q and k
                        const int idx = (col & (HD - 1)) >> 1;
                        const float cs = fc[row * 64 + idx];
                        const float sn = fs[row * 64 + idx];
                        const float re = v0 * cs - v1 * sn;
                        const float im = v0 * sn + v1 * cs;
                        v0 = re; v1 = im;
                    }
                    float r0x, r1x;
                    uint32_t hi = pack_hi(v0, v1, r0x, r1x);
                    __nv_bfloat162 lo = __floats2bfloat162_rn(r0x, r1x);
                    const size_t off = (size_t)row * ldc + col;
                    *(uint32_t*)&Chi[off] = hi;
                    *(__nv_bfloat162*)&Clo[off] = lo;
                } else {
                    *(float2*)&Cout[(size_t)row * ldc + col] = make_float2(v0, v1);
                }
            }
        }
    }
#undef LOADCHUNK
}

// ---------------------------------------------------------------------------
// Tensor-core flash attention (bf16-split, fp32 softmax), causal, GQA.
// CTA = 128 q rows x 1 head, 8 warps, BN=64, 2-stage KV, 1 sync/tile.
// Epilogue writes att as bf16 hi/lo (feeds out-proj directly).
// ---------------------------------------------------------------------------
#define FROWB  272u
#define SQH    0u
#define SQL    34816u
#define SKV    69632u
#define KLOFF  17408u
#define VHOFF  34816u
#define VLOFF  52224u
#define KVSTG  69632u
#define FA2SMEM (69632 + 2 * 69632)

__global__ __launch_bounds__(256, 1) void fa_mma_kernel(
    const __nv_bfloat16* __restrict__ qhi, const __nv_bfloat16* __restrict__ qlo,
    const __nv_bfloat16* __restrict__ khi, const __nv_bfloat16* __restrict__ klo,
    const __nv_bfloat16* __restrict__ vhi, const __nv_bfloat16* __restrict__ vlo,
    __nv_bfloat16* __restrict__ ohi, __nv_bfloat16* __restrict__ olo)
{
    extern __shared__ char sm[];
    const uint32_t sb = smem_u32(sm);

    const int qtile = gridDim.x - 1 - blockIdx.x;
    const int h = blockIdx.y, kvh = h >> 2;
    const int tid = threadIdx.x, wid = tid >> 5, lane = tid & 31;
    const int qbase = qtile * 128;

    {   // Q tile load (group 0, waited with first KV chunk)
        const char* gq0 = (const char*)qhi + ((size_t)qbase * DIM + h * HD) * 2;
        const char* gq1 = (const char*)qlo + ((size_t)qbase * DIM + h * HD) * 2;
        for (int i = tid; i < 2048; i += 256) {
            uint32_t r = i >> 4, c = i & 15;
            CP16(sb + SQH + r * FROWB + c * 16, gq0 + (size_t)r * 8192 + c * 16);
            CP16(sb + SQL + r * FROWB + c * 16, gq1 + (size_t)r * 8192 + c * 16);
        }
    }

#define LOADKV(jb, s) do { \
    uint32_t _st = sb + SKV + (uint32_t)(s) * KVSTG; \
    size_t _gb = ((size_t)(jb) * KVD + kvh * HD) * 2; \
    for (int _i = tid; _i < 1024; _i += 256) { \
        uint32_t _r = _i >> 4, _c = _i & 15; \
        uint32_t _d = _st + _r * FROWB + _c * 16; \
        size_t _s2 = _gb + (size_t)_r * 2048 + _c * 16; \
        CP16(_d,          (const char*)khi + _s2); \
        CP16(_d + KLOFF,  (const char*)klo + _s2); \
        CP16(_d + VHOFF,  (const char*)vhi + _s2); \
        CP16(_d + VLOFF,  (const char*)vlo + _s2); \
    } } while (0)

    const int NT = (qtile + 1) * 2;
    LOADKV(0, 0);
    CP_COMMIT();

    float m0 = -1e30f, m1 = -1e30f, l0 = 0.f, l1 = 0.f;
    float acc_o[16][4];
    #pragma unroll
    for (int n = 0; n < 16; n++)
        #pragma unroll
        for (int t = 0; t < 4; t++) acc_o[n][t] = 0.f;

    const float kl = 0.12751689f;  // (1/sqrt(128)) * log2(e)
    const uint32_t aoff = (uint32_t)(wid * 16 + (lane & 15)) * FROWB + (uint32_t)((lane >> 4) & 1) * 16u;
    const uint32_t boffBase = (uint32_t)(((lane >> 4) << 3) + (lane & 7)) * FROWB
                            + (uint32_t)((lane >> 3) & 1) * 16u;
    const uint32_t voffBase = (uint32_t)(lane & 15) * FROWB + (uint32_t)(lane >> 4) * 16u;
    const int r0g = qbase + wid * 16 + (lane >> 2);

    for (int c = 0; c < NT; ++c) {
        CP_WAIT0();                       // chunk c (the only pending group)
        __syncthreads();                  // all warps done with stage (c-1)&1
        if (c + 1 < NT) { LOADKV((c + 1) * 64, (c + 1) & 1); CP_COMMIT(); }

        const uint32_t stg = sb + SKV + (uint32_t)(c & 1) * KVSTG;

        float s[8][4];
        #pragma unroll
        for (int j = 0; j < 8; j++)
            #pragma unroll
            for (int t = 0; t < 4; t++) s[j][t] = 0.f;

        #pragma unroll
        for (int kk = 0; kk < 8; ++kk) {
            uint32_t ah[4], al[4];
            LDSM4(ah, sb + SQH + aoff + kk * 32);
            LDSM4(al, sb + SQL + aoff + kk * 32);
            #pragma unroll
            for (int g = 0; g < 4; ++g) {
                uint32_t bh[4], bl[4];
                uint32_t bo = stg + (uint32_t)(g * 16) * FROWB + boffBase + kk * 32;
                LDSM4(bh, bo);
                LDSM4(bl, bo + KLOFF);
                MMA16816(s[2*g],   ah, bh[0], bh[1]);
                MMA16816(s[2*g],   ah, bl[0], bl[1]);
                MMA16816(s[2*g],   al, bh[0], bh[1]);
                MMA16816(s[2*g+1], ah, bh[2], bh[3]);
                MMA16816(s[2*g+1], ah, bl[2], bl[3]);
                MMA16816(s[2*g+1], al, bh[2], bh[3]);
            }
        }

        const int jbase = c * 64;
        if (jbase + 63 > qbase + wid * 16) {
            #pragma unroll
            for (int j = 0; j < 8; j++) {
                int col = jbase + j * 8 + (lane & 3) * 2;
                if (col     > r0g)     s[j][0] = -1e30f;
                if (col + 1 > r0g)     s[j][1] = -1e30f;
                if (col     > r0g + 8) s[j][2] = -1e30f;
                if (col + 1 > r0g + 8) s[j][3] = -1e30f;
            }
        }

        float mx0 = -1e30f, mx1 = -1e30f;
        #pragma unroll
        for (int j = 0; j < 8; j++) {
            mx0 = fmaxf(mx0, fmaxf(s[j][0], s[j][1]));
            mx1 = fmaxf(mx1, fmaxf(s[j][2], s[j][3]));
        }
        mx0 = fmaxf(mx0, __shfl_xor_sync(0xFFFFFFFFu, mx0, 1));
        mx0 = fmaxf(mx0, __shfl_xor_sync(0xFFFFFFFFu, mx0, 2));
        mx1 = fmaxf(mx1, __shfl_xor_sync(0xFFFFFFFFu, mx1, 1));
        mx1 = fmaxf(mx1, __shfl_xor_sync(0xFFFFFFFFu, mx1, 2));
        const float nm0 = fmaxf(m0, mx0), nm1 = fmaxf(m1, mx1);
        const float corr0 = exp2f((m0 - nm0) * kl), corr1 = exp2f((m1 - nm1) * kl);
        const float nb0 = -nm0 * kl, nb1 = -nm1 * kl;
        float sum0 = 0.f, sum1 = 0.f;
        #pragma unroll
        for (int j = 0; j < 8; j++) {
            s[j][0] = exp2f(fmaf(s[j][0], kl, nb0));
            s[j][1] = exp2f(fmaf(s[j][1], kl, nb0));
            s[j][2] = exp2f(fmaf(s[j][2], kl, nb1));
            s[j][3] = exp2f(fmaf(s[j][3], kl, nb1));
            sum0 += s[j][0] + s[j][1];
            sum1 += s[j][2] + s[j][3];
        }
        sum0 += __shfl_xor_sync(0xFFFFFFFFu, sum0, 1);
        sum0 += __shfl_xor_sync(0xFFFFFFFFu, sum0, 2);
        sum1 += __shfl_xor_sync(0xFFFFFFFFu, sum1, 1);
        sum1 += __shfl_xor_sync(0xFFFFFFFFu, sum1, 2);
        l0 = l0 * corr0 + sum0;
        l1 = l1 * corr1 + sum1;
        m0 = nm0; m1 = nm1;
        #pragma unroll
        for (int n = 0; n < 16; n++) {
            acc_o[n][0] *= corr0; acc_o[n][1] *= corr0;
            acc_o[n][2] *= corr1; acc_o[n][3] *= corr1;
        }

        uint32_t aPh[4][4], aPl[4][4];
        #pragma unroll
        for (int g = 0; g < 4; ++g) {
            #pragma unroll
            for (int part = 0; part < 4; ++part) {
                const int j = 2 * g + (part >> 1);
                const int e = (part & 1) * 2;
                float rx, ry;
                aPh[g][part] = pack_hi(s[j][e], s[j][e + 1], rx, ry);
                __nv_bfloat162 vl = __floats2bfloat162_rn(rx, ry);
                aPl[g][part] = *(uint32_t*)&vl;
            }
        }

        #pragma unroll
        for (int n16 = 0; n16 < 8; ++n16) {
            #pragma unroll
            for (int kk = 0; kk < 4; ++kk) {
                uint32_t vhf[4], vlf[4];
                uint32_t vo = stg + (uint32_t)(kk * 16) * FROWB + voffBase + n16 * 32;
                LDSM4T(vhf, vo + VHOFF);
                LDSM4T(vlf, vo + VLOFF);
                MMA16816(acc_o[2*n16],   aPh[kk], vhf[0], vhf[1]);
                MMA16816(acc_o[2*n16],   aPh[kk], vlf[0], vlf[1]);
                MMA16816(acc_o[2*n16],   aPl[kk], vhf[0], vhf[1]);
                MMA16816(acc_o[2*n16+1], aPh[kk], vhf[2], vhf[3]);
                MMA16816(acc_o[2*n16+1], aPh[kk], vlf[2], vlf[3]);
                MMA16816(acc_o[2*n16+1], aPl[kk], vhf[2], vhf[3]);
            }
        }
    }

    // ---- epilogue: normalize + bf16 hi/lo split write ----
    const float inv0 = 1.f / l0, inv1 = 1.f / l1;
    #pragma unroll
    for (int n8 = 0; n8 < 16; ++n8) {
        const int col = h * HD + n8 * 8 + (lane & 3) * 2;
        float rx, ry;
        const size_t off0 = (size_t)r0g * DIM + col;
        const size_t off1 = (size_t)(r0g + 8) * DIM + col;
        uint32_t h0 = pack_hi(acc_o[n8][0] * inv0, acc_o[n8][1] * inv0, rx, ry);
        __nv_bfloat162 l0v = __floats2bfloat162_rn(rx, ry);
        *(uint32_t*)&ohi[off0] = h0;
        *(__nv_bfloat162*)&olo[off0] = l0v;
        uint32_t h1 = pack_hi(acc_o[n8][2] * inv1, acc_o[n8][3] * inv1, rx, ry);
        __nv_bfloat162 l1v = __floats2bfloat162_rn(rx, ry);
        *(uint32_t*)&ohi[off1] = h1;
        *(__nv_bfloat162*)&olo[off1] = l1v;
    }
#undef LOADKV
}

// ---------------------------------------------------------------------------
extern "C" void kernel_launch(void* const* d_in, const int* in_sizes, int n_in,
                              void* d_out, int out_size)
{
    const float* x    = (const float*)d_in[0];
    const float* fc   = (const float*)d_in[1];
    const float* fs   = (const float*)d_in[2];
    const float* wk_w = (const float*)d_in[6];
    const float* wk_b = (const float*)d_in[7];
    const float* wv_w = (const float*)d_in[8];
    const float* wv_b = (const float*)d_in[9];
    const float* wo_w = (const float*)d_in[10];
    const float* wo_b = (const float*)d_in[11];
    float* out = (float*)d_out;

    __nv_bfloat16 *xhi, *xlo, *wohi, *wolo, *wkhi, *wklo, *wvhi, *wvlo;
    __nv_bfloat16 *qhi, *qlo, *khi, *klo, *vhi, *vlo, *ahi, *alo;
    cudaGetSymbolAddress((void**)&xhi,  g_xhi);  cudaGetSymbolAddress((void**)&xlo,  g_xlo);
    cudaGetSymbolAddress((void**)&wohi, g_wohi); cudaGetSymbolAddress((void**)&wolo, g_wolo);
    cudaGetSymbolAddress((void**)&wkhi, g_wkhi); cudaGetSymbolAddress((void**)&wklo, g_wklo);
    cudaGetSymbolAddress((void**)&wvhi, g_wvhi); cudaGetSymbolAddress((void**)&wvlo, g_wvlo);
    cudaGetSymbolAddress((void**)&qhi,  g_qhi);  cudaGetSymbolAddress((void**)&qlo,  g_qlo);
    cudaGetSymbolAddress((void**)&khi,  g_khi);  cudaGetSymbolAddress((void**)&klo,  g_klo);
    cudaGetSymbolAddress((void**)&vhi,  g_vhi);  cudaGetSymbolAddress((void**)&vlo,  g_vlo);
    cudaGetSymbolAddress((void**)&ahi,  g_ahi);  cudaGetSymbolAddress((void**)&alo,  g_alo);

    // 0) fp32 -> bf16 hi/lo splits (x + weights)
    split_kernel<<<(T_SEQ*DIM/4 + 255)/256, 256>>>(x,    xhi,  xlo,  T_SEQ*DIM/4);
    split_kernel<<<(DIM*DIM/4   + 255)/256, 256>>>(wo_w, wohi, wolo, DIM*DIM/4);
    split_kernel<<<(KVD*DIM/4   + 255)/256, 256>>>(wk_w, wkhi, wklo, KVD*DIM/4);
    split_kernel<<<(KVD*DIM/4   + 255)/256, 256>>>(wv_w, wvhi, wvlo, KVD*DIM/4);

    cudaFuncSetAttribute(mma_gemm_kernel<0>,
                         cudaFuncAttributeMaxDynamicSharedMemorySize, GSMEM);
    cudaFuncSetAttribute(mma_gemm_kernel<1>,
                         cudaFuncAttributeMaxDynamicSharedMemorySize, GSMEM);

    // 1) fused QKV projection + bias + RoPE + split (q uses wo_w per reference)
    dim3 gqkv(48, 16);
    mma_gemm_kernel<0><<<gqkv, 256, GSMEM>>>(xhi, xlo,
                                             wohi, wolo, wo_b,
                                             wkhi, wklo, wk_b,
                                             wvhi, wvlo, wv_b,
                                             nullptr,
                                             qhi, qlo, khi, klo, vhi, vlo,
                                             fc, fs);

    // 2) tensor-core causal GQA flash attention -> att bf16 hi/lo
    cudaFuncSetAttribute(fa_mma_kernel,
                         cudaFuncAttributeMaxDynamicSharedMemorySize, FA2SMEM);
    dim3 gfa(T_SEQ / 128, NH);
    fa_mma_kernel<<<gfa, 256, FA2SMEM>>>(qhi, qlo, khi, klo, vhi, vlo, ahi, alo);

    // 3) output projection -> fp32 out
    dim3 go(32, 16);
    mma_gemm_kernel<1><<<go, 256, GSMEM>>>(ahi, alo,
                                           wohi, wolo, wo_b,
                                           nullptr, nullptr, nullptr,
                                           nullptr, nullptr, nullptr,
                                           out,
                                           nullptr, nullptr, nullptr, nullptr, nullptr, nullptr,
                                           fc, fs);
}

// round 6
// speedup vs baseline: 7.2087x; 2.2945x over previous
#include <cuda_runtime.h>
#include <cuda_fp16.h>
#include <math.h>
#include <stdint.h>

#define T_SEQ 2048
#define DIM   4096
#define NH    32
#define NKV   8
#define HD    128
#define KVD   1024
#define KDIM  4096

// ---------------- scratch (static __device__, no allocation) ----------------
__device__ __half g_xh [T_SEQ * DIM];
__device__ __half g_woh[DIM * DIM];
__device__ __half g_wkh[KVD * DIM];
__device__ __half g_wvh[KVD * DIM];
__device__ __half g_qh [T_SEQ * DIM];
__device__ __half g_kh [T_SEQ * KVD];
__device__ __half g_vh [T_SEQ * KVD];
__device__ __half g_ah [T_SEQ * DIM];

// ---------------- PTX helpers (baseline ISA only) ----------------
__device__ __forceinline__ uint32_t smem_u32(const void* p) {
    uint32_t a;
    asm("{ .reg .u64 t; cvta.to.shared.u64 t, %1; cvt.u32.u64 %0, t; }" : "=r"(a) : "l"(p));
    return a;
}
#define CP16(dst, src) asm volatile("cp.async.cg.shared.global [%0], [%1], 16;" :: "r"(dst), "l"(src))
#define CP_COMMIT()    asm volatile("cp.async.commit_group;" ::: "memory")
#define CP_WAIT2()     asm volatile("cp.async.wait_group 2;" ::: "memory")
#define CP_WAIT0()     asm volatile("cp.async.wait_group 0;" ::: "memory")

#define LDSM4(r, a) asm volatile( \
    "ldmatrix.sync.aligned.m8n8.x4.shared.b16 {%0,%1,%2,%3}, [%4];" \
    : "=r"((r)[0]), "=r"((r)[1]), "=r"((r)[2]), "=r"((r)[3]) : "r"(a))
#define LDSM4T(r, a) asm volatile( \
    "ldmatrix.sync.aligned.m8n8.x4.trans.shared.b16 {%0,%1,%2,%3}, [%4];" \
    : "=r"((r)[0]), "=r"((r)[1]), "=r"((r)[2]), "=r"((r)[3]) : "r"(a))

#define MMAH(c, a, b0, b1) asm volatile( \
    "mma.sync.aligned.m16n8k16.row.col.f32.f16.f16.f32 " \
    "{%0,%1,%2,%3},{%4,%5,%6,%7},{%8,%9},{%0,%1,%2,%3};" \
    : "+f"((c)[0]), "+f"((c)[1]), "+f"((c)[2]), "+f"((c)[3]) \
    : "r"((a)[0]), "r"((a)[1]), "r"((a)[2]), "r"((a)[3]), "r"(b0), "r"(b1))

__device__ __forceinline__ uint32_t packh2(float x, float y) {
    __half2 h = __floats2half2_rn(x, y);
    return *(uint32_t*)&h;
}

// ---------------------------------------------------------------------------
// fp32 -> fp16 convert (x + weights)
// ---------------------------------------------------------------------------
__global__ void cvt_kernel(const float* __restrict__ src,
                           __half* __restrict__ dst, int n4)
{
    int i = blockIdx.x * blockDim.x + threadIdx.x;
    if (i >= n4) return;
    float4 v = ((const float4*)src)[i];
    ((__half2*)dst)[2*i]   = __floats2half2_rn(v.x, v.y);
    ((__half2*)dst)[2*i+1] = __floats2half2_rn(v.z, v.w);
}

// ---------------------------------------------------------------------------
// fp16 tensor-core GEMM: C[M,N] = A[M,K] @ W[N,K]^T + bias
// CTA 128x128, BK=32, 256 thr (8 warps, warp tile 64x32), 4-stage cp.async.
// MODE 0 (QKV): epilogue = bias + RoPE(q,k) + fp16 write.
// MODE 1 (out-proj): epilogue = bias + fp32 write.
// ---------------------------------------------------------------------------
#define ROWB   80u
#define B_OFF  10240u
#define STAGEB 20480u
#define NSTG   4
#define GSMEM  (NSTG * 20480)

template<int MODE>
__global__ __launch_bounds__(256) void mma_gemm_kernel(
    const __half* __restrict__ A,
    const __half* __restrict__ W0, const float* __restrict__ b0,
    const __half* __restrict__ W1, const float* __restrict__ b1,
    const __half* __restrict__ W2, const float* __restrict__ b2,
    float* __restrict__ Cout,
    __half* __restrict__ C0, __half* __restrict__ C1, __half* __restrict__ C2,
    const float* __restrict__ fc, const float* __restrict__ fs)
{
    extern __shared__ char dsm[];
    const uint32_t sb = smem_u32(dsm);

    const int bx = blockIdx.x;
    const __half* W; const float* bias; int n0, ldc, region; __half* Ch;
    if (bx < 32)      { W = W0; bias = b0; n0 = bx * 128;        ldc = DIM; region = 0; Ch = C0; }
    else if (bx < 40) { W = W1; bias = b1; n0 = (bx - 32) * 128; ldc = KVD; region = 1; Ch = C1; }
    else              { W = W2; bias = b2; n0 = (bx - 40) * 128; ldc = KVD; region = 2; Ch = C2; }

    const int bm   = blockIdx.y * 128;
    const int tid  = threadIdx.x;
    const int lane = tid & 31;
    const int wid  = tid >> 5;
    const int wm   = wid & 1;
    const int wn   = wid >> 1;

    // cp.async geometry: rows 0..63 (so0) and 64..127 (so1), 4x16B per row-chunk
    const int r0 = tid >> 2, cc = tid & 3;
    const uint32_t so0 = (uint32_t)r0 * ROWB + cc * 16u;
    const uint32_t so1 = so0 + 64u * ROWB;
    const size_t  go0 = (size_t)r0 * 8192 + cc * 16;
    const size_t  go1 = go0 + (size_t)64 * 8192;

    const char* pA = (const char*)A + (size_t)bm * 8192;
    const char* pB = (const char*)W + (size_t)n0 * 8192;

#define LOADCHUNK(cidx, s) do { \
    uint32_t _st = sb + (uint32_t)(s) * STAGEB; \
    size_t _kb = (size_t)(cidx) * 64; \
    CP16(_st + so0,         pA + go0 + _kb); CP16(_st + so1,         pA + go1 + _kb); \
    CP16(_st + B_OFF + so0, pB + go0 + _kb); CP16(_st + B_OFF + so1, pB + go1 + _kb); \
    } while (0)

    float acc[4][4][4];
    #pragma unroll
    for (int i = 0; i < 4; i++)
        #pragma unroll
        for (int j = 0; j < 4; j++)
            #pragma unroll
            for (int t = 0; t < 4; t++) acc[i][j][t] = 0.f;

    const int NC = KDIM / 32;   // 128 chunks

    LOADCHUNK(0, 0); CP_COMMIT();
    LOADCHUNK(1, 1); CP_COMMIT();
    LOADCHUNK(2, 2); CP_COMMIT();

    const uint32_t aRow = (uint32_t)(wm * 64 + (lane & 15)) * ROWB + ((lane >> 4) & 1) * 16u;
    const uint32_t bRow = (uint32_t)(wn * 32 + ((lane >> 4) << 3) + (lane & 7)) * ROWB
                        + ((lane >> 3) & 1) * 16u;

    for (int c = 0; c < NC; ++c) {
        CP_WAIT2();
        __syncthreads();
        if (c + 3 < NC) LOADCHUNK(c + 3, (c + 3) & (NSTG - 1));
        CP_COMMIT();

        const uint32_t stg = sb + (uint32_t)(c & (NSTG - 1)) * STAGEB;
        #pragma unroll
        for (int k16 = 0; k16 < 2; ++k16) {
            const uint32_t kb = (uint32_t)k16 * 32u;
            uint32_t ah[4][4], bh[2][4];
            #pragma unroll
            for (int i = 0; i < 4; i++)
                LDSM4(ah[i], stg + aRow + (uint32_t)(i * 16) * ROWB + kb);
            #pragma unroll
            for (int p = 0; p < 2; p++)
                LDSM4(bh[p], stg + B_OFF + bRow + (uint32_t)(p * 16) * ROWB + kb);
            #pragma unroll
            for (int i = 0; i < 4; i++) {
                #pragma unroll
                for (int j = 0; j < 4; j++) {
                    const int p = j >> 1, f = (j & 1) * 2;
                    MMAH(acc[i][j], ah[i], bh[p][f], bh[p][f + 1]);
                }
            }
        }
    }

    // ---- epilogue ----
    #pragma unroll
    for (int i = 0; i < 4; i++) {
        const int row0 = bm + wm * 64 + i * 16 + (lane >> 2);
        #pragma unroll
        for (int j = 0; j < 4; j++) {
            const int col = n0 + wn * 32 + j * 8 + (lane & 3) * 2;
            const float bv0 = bias[col], bv1 = bias[col + 1];
            #pragma unroll
            for (int t = 0; t < 2; t++) {
                const int row = row0 + t * 8;
                float v0 = acc[i][j][2 * t]     + bv0;
                float v1 = acc[i][j][2 * t + 1] + bv1;
                if (MODE == 0) {
                    if (region != 2) {       // RoPE on q and k
                        const int idx = (col & (HD - 1)) >> 1;
                        const float cs = fc[row * 64 + idx];
                        const float sn = fs[row * 64 + idx];
                        const float re = v0 * cs - v1 * sn;
                        const float im = v0 * sn + v1 * cs;
                        v0 = re; v1 = im;
                    }
                    *(uint32_t*)&Ch[(size_t)row * ldc + col] = packh2(v0, v1);
                } else {
                    *(float2*)&Cout[(size_t)row * ldc + col] = make_float2(v0, v1);
                }
            }
        }
    }
#undef LOADCHUNK
}

// ---------------------------------------------------------------------------
// fp16 tensor-core flash attention (fp32 softmax), causal, GQA.
// CTA = 128 q rows x 1 head, 8 warps, BN=64, 2-stage KV, 1 sync/tile.
// ---------------------------------------------------------------------------
#define FROWB  272u
#define SQ_    0u
#define SKV    34816u
#define VOFF   17408u
#define KVSTG  34816u
#define FA2SMEM (34816 + 2 * 34816)

__global__ __launch_bounds__(256) void fa_mma_kernel(
    const __half* __restrict__ qh, const __half* __restrict__ kh,
    const __half* __restrict__ vh, __half* __restrict__ oh)
{
    extern __shared__ char sm[];
    const uint32_t sb = smem_u32(sm);

    const int qtile = gridDim.x - 1 - blockIdx.x;
    const int h = blockIdx.y, kvh = h >> 2;
    const int tid = threadIdx.x, wid = tid >> 5, lane = tid & 31;
    const int qbase = qtile * 128;

    {   // Q tile load (group 0 with first KV chunk)
        const char* gq = (const char*)qh + ((size_t)qbase * DIM + h * HD) * 2;
        for (int i = tid; i < 2048; i += 256) {
            uint32_t r = i >> 4, c = i & 15;
            CP16(sb + SQ_ + r * FROWB + c * 16, gq + (size_t)r * 8192 + c * 16);
        }
    }

#define LOADKV(jb, s) do { \
    uint32_t _st = sb + SKV + (uint32_t)(s) * KVSTG; \
    size_t _gb = ((size_t)(jb) * KVD + kvh * HD) * 2; \
    for (int _i = tid; _i < 1024; _i += 256) { \
        uint32_t _r = _i >> 4, _c = _i & 15; \
        uint32_t _d = _st + _r * FROWB + _c * 16; \
        size_t _s2 = _gb + (size_t)_r * 2048 + _c * 16; \
        CP16(_d,        (const char*)kh + _s2); \
        CP16(_d + VOFF, (const char*)vh + _s2); \
    } } while (0)

    const int NT = (qtile + 1) * 2;
    LOADKV(0, 0);
    CP_COMMIT();

    float m0 = -1e30f, m1 = -1e30f, l0 = 0.f, l1 = 0.f;
    float acc_o[16][4];
    #pragma unroll
    for (int n = 0; n < 16; n++)
        #pragma unroll
        for (int t = 0; t < 4; t++) acc_o[n][t] = 0.f;

    const float kl = 0.12751689f;  // (1/sqrt(128)) * log2(e)
    const uint32_t aoff = (uint32_t)(wid * 16 + (lane & 15)) * FROWB + (uint32_t)((lane >> 4) & 1) * 16u;
    const uint32_t boffBase = (uint32_t)(((lane >> 4) << 3) + (lane & 7)) * FROWB
                            + (uint32_t)((lane >> 3) & 1) * 16u;
    const uint32_t voffBase = (uint32_t)(lane & 15) * FROWB + (uint32_t)(lane >> 4) * 16u;
    const int r0g = qbase + wid * 16 + (lane >> 2);

    for (int c = 0; c < NT; ++c) {
        CP_WAIT0();
        __syncthreads();
        if (c + 1 < NT) { LOADKV((c + 1) * 64, (c + 1) & 1); CP_COMMIT(); }

        const uint32_t stg = sb + SKV + (uint32_t)(c & 1) * KVSTG;

        float s[8][4];
        #pragma unroll
        for (int j = 0; j < 8; j++)
            #pragma unroll
            for (int t = 0; t < 4; t++) s[j][t] = 0.f;

        #pragma unroll
        for (int kk = 0; kk < 8; ++kk) {
            uint32_t ah[4];
            LDSM4(ah, sb + SQ_ + aoff + kk * 32);
            #pragma unroll
            for (int g = 0; g < 4; ++g) {
                uint32_t bh[4];
                LDSM4(bh, stg + (uint32_t)(g * 16) * FROWB + boffBase + kk * 32);
                MMAH(s[2*g],   ah, bh[0], bh[1]);
                MMAH(s[2*g+1], ah, bh[2], bh[3]);
            }
        }

        const int jbase = c * 64;
        if (jbase + 63 > qbase + wid * 16) {
            #pragma unroll
            for (int j = 0; j < 8; j++) {
                int col = jbase + j * 8 + (lane & 3) * 2;
                if (col     > r0g)     s[j][0] = -1e30f;
                if (col + 1 > r0g)     s[j][1] = -1e30f;
                if (col     > r0g + 8) s[j][2] = -1e30f;
                if (col + 1 > r0g + 8) s[j][3] = -1e30f;
            }
        }

        float mx0 = -1e30f, mx1 = -1e30f;
        #pragma unroll
        for (int j = 0; j < 8; j++) {
            mx0 = fmaxf(mx0, fmaxf(s[j][0], s[j][1]));
            mx1 = fmaxf(mx1, fmaxf(s[j][2], s[j][3]));
        }
        mx0 = fmaxf(mx0, __shfl_xor_sync(0xFFFFFFFFu, mx0, 1));
        mx0 = fmaxf(mx0, __shfl_xor_sync(0xFFFFFFFFu, mx0, 2));
        mx1 = fmaxf(mx1, __shfl_xor_sync(0xFFFFFFFFu, mx1, 1));
        mx1 = fmaxf(mx1, __shfl_xor_sync(0xFFFFFFFFu, mx1, 2));
        const float nm0 = fmaxf(m0, mx0), nm1 = fmaxf(m1, mx1);
        const float corr0 = exp2f((m0 - nm0) * kl), corr1 = exp2f((m1 - nm1) * kl);
        const float nb0 = -nm0 * kl, nb1 = -nm1 * kl;
        float sum0 = 0.f, sum1 = 0.f;
        #pragma unroll
        for (int j = 0; j < 8; j++) {
            s[j][0] = exp2f(fmaf(s[j][0], kl, nb0));
            s[j][1] = exp2f(fmaf(s[j][1], kl, nb0));
            s[j][2] = exp2f(fmaf(s[j][2], kl, nb1));
            s[j][3] = exp2f(fmaf(s[j][3], kl, nb1));
            sum0 += s[j][0] + s[j][1];
            sum1 += s[j][2] + s[j][3];
        }
        sum0 += __shfl_xor_sync(0xFFFFFFFFu, sum0, 1);
        sum0 += __shfl_xor_sync(0xFFFFFFFFu, sum0, 2);
        sum1 += __shfl_xor_sync(0xFFFFFFFFu, sum1, 1);
        sum1 += __shfl_xor_sync(0xFFFFFFFFu, sum1, 2);
        l0 = l0 * corr0 + sum0;
        l1 = l1 * corr1 + sum1;
        m0 = nm0; m1 = nm1;
        #pragma unroll
        for (int n = 0; n < 16; n++) {
            acc_o[n][0] *= corr0; acc_o[n][1] *= corr0;
            acc_o[n][2] *= corr1; acc_o[n][3] *= corr1;
        }

        uint32_t aP[4][4];
        #pragma unroll
        for (int g = 0; g < 4; ++g) {
            #pragma unroll
            for (int part = 0; part < 4; ++part) {
                const int j = 2 * g + (part >> 1);
                const int e = (part & 1) * 2;
                aP[g][part] = packh2(s[j][e], s[j][e + 1]);
            }
        }

        #pragma unroll
        for (int n16 = 0; n16 < 8; ++n16) {
            #pragma unroll
            for (int kk = 0; kk < 4; ++kk) {
                uint32_t vf[4];
                LDSM4T(vf, stg + VOFF + (uint32_t)(kk * 16) * FROWB + voffBase + n16 * 32);
                MMAH(acc_o[2*n16],   aP[kk], vf[0], vf[1]);
                MMAH(acc_o[2*n16+1], aP[kk], vf[2], vf[3]);
            }
        }
    }

    // ---- epilogue: normalize + fp16 write ----
    const float inv0 = 1.f / l0, inv1 = 1.f / l1;
    #pragma unroll
    for (int n8 = 0; n8 < 16; ++n8) {
        const int col = h * HD + n8 * 8 + (lane & 3) * 2;
        *(uint32_t*)&oh[(size_t)r0g * DIM + col] =
            packh2(acc_o[n8][0] * inv0, acc_o[n8][1] * inv0);
        *(uint32_t*)&oh[(size_t)(r0g + 8) * DIM + col] =
            packh2(acc_o[n8][2] * inv1, acc_o[n8][3] * inv1);
    }
#undef LOADKV
}

// ---------------------------------------------------------------------------
extern "C" void kernel_launch(void* const* d_in, const int* in_sizes, int n_in,
                              void* d_out, int out_size)
{
    const float* x    = (const float*)d_in[0];
    const float* fc   = (const float*)d_in[1];
    const float* fs   = (const float*)d_in[2];
    const float* wk_w = (const float*)d_in[6];
    const float* wk_b = (const float*)d_in[7];
    const float* wv_w = (const float*)d_in[8];
    const float* wv_b = (const float*)d_in[9];
    const float* wo_w = (const float*)d_in[10];
    const float* wo_b = (const float*)d_in[11];
    float* out = (float*)d_out;

    __half *xh, *woh, *wkh, *wvh, *qh, *kh, *vh, *ah;
    cudaGetSymbolAddress((void**)&xh,  g_xh);
    cudaGetSymbolAddress((void**)&woh, g_woh);
    cudaGetSymbolAddress((void**)&wkh, g_wkh);
    cudaGetSymbolAddress((void**)&wvh, g_wvh);
    cudaGetSymbolAddress((void**)&qh,  g_qh);
    cudaGetSymbolAddress((void**)&kh,  g_kh);
    cudaGetSymbolAddress((void**)&vh,  g_vh);
    cudaGetSymbolAddress((void**)&ah,  g_ah);

    // 0) fp32 -> fp16 converts (x + weights)
    cvt_kernel<<<(T_SEQ*DIM/4 + 255)/256, 256>>>(x,    xh,  T_SEQ*DIM/4);
    cvt_kernel<<<(DIM*DIM/4   + 255)/256, 256>>>(wo_w, woh, DIM*DIM/4);
    cvt_kernel<<<(KVD*DIM/4   + 255)/256, 256>>>(wk_w, wkh, KVD*DIM/4);
    cvt_kernel<<<(KVD*DIM/4   + 255)/256, 256>>>(wv_w, wvh, KVD*DIM/4);

    cudaFuncSetAttribute(mma_gemm_kernel<0>,
                         cudaFuncAttributeMaxDynamicSharedMemorySize, GSMEM);
    cudaFuncSetAttribute(mma_gemm_kernel<1>,
                         cudaFuncAttributeMaxDynamicSharedMemorySize, GSMEM);

    // 1) fused QKV projection + bias + RoPE -> fp16 q/k/v (q uses wo_w per ref)
    dim3 gqkv(48, 16);
    mma_gemm_kernel<0><<<gqkv, 256, GSMEM>>>(xh,
                                             woh, wo_b,
                                             wkh, wk_b,
                                             wvh, wv_b,
                                             nullptr,
                                             qh, kh, vh,
                                             fc, fs);

    // 2) fp16 tensor-core causal GQA flash attention -> fp16 att
    cudaFuncSetAttribute(fa_mma_kernel,
                         cudaFuncAttributeMaxDynamicSharedMemorySize, FA2SMEM);
    dim3 gfa(T_SEQ / 128, NH);
    fa_mma_kernel<<<gfa, 256, FA2SMEM>>>(qh, kh, vh, ah);

    // 3) output projection -> fp32 out
    dim3 go(32, 16);
    mma_gemm_kernel<1><<<go, 256, GSMEM>>>(ah,
                                           woh, wo_b,
                                           nullptr, nullptr,
                                           nullptr, nullptr,
                                           out,
                                           nullptr, nullptr, nullptr,
                                           fc, fs);
}

// round 7
// speedup vs baseline: 7.7153x; 1.0703x over previous
#include <cuda_runtime.h>
#include <cuda_fp16.h>
#include <math.h>
#include <stdint.h>

#define T_SEQ 2048
#define DIM   4096
#define NH    32
#define NKV   8
#define HD    128
#define KVD   1024
#define KDIM  4096

// ---------------- scratch (static __device__, no allocation) ----------------
__device__ __half g_xh [T_SEQ * DIM];
__device__ __half g_woh[DIM * DIM];
__device__ __half g_wkh[KVD * DIM];
__device__ __half g_wvh[KVD * DIM];
__device__ __half g_qh [T_SEQ * DIM];
__device__ __half g_kh [T_SEQ * KVD];
__device__ __half g_vh [T_SEQ * KVD];
__device__ __half g_ah [T_SEQ * DIM];

// ---------------- PTX helpers (baseline ISA only) ----------------
__device__ __forceinline__ uint32_t smem_u32(const void* p) {
    uint32_t a;
    asm("{ .reg .u64 t; cvta.to.shared.u64 t, %1; cvt.u32.u64 %0, t; }" : "=r"(a) : "l"(p));
    return a;
}
#define CP16(dst, src) asm volatile("cp.async.cg.shared.global [%0], [%1], 16;" :: "r"(dst), "l"(src))
#define CP_COMMIT()    asm volatile("cp.async.commit_group;" ::: "memory")
#define CP_WAIT2()     asm volatile("cp.async.wait_group 2;" ::: "memory")
#define CP_WAIT0()     asm volatile("cp.async.wait_group 0;" ::: "memory")

#define LDSM4(r, a) asm volatile( \
    "ldmatrix.sync.aligned.m8n8.x4.shared.b16 {%0,%1,%2,%3}, [%4];" \
    : "=r"((r)[0]), "=r"((r)[1]), "=r"((r)[2]), "=r"((r)[3]) : "r"(a))
#define LDSM4T(r, a) asm volatile( \
    "ldmatrix.sync.aligned.m8n8.x4.trans.shared.b16 {%0,%1,%2,%3}, [%4];" \
    : "=r"((r)[0]), "=r"((r)[1]), "=r"((r)[2]), "=r"((r)[3]) : "r"(a))

#define MMAH(c, a, b0, b1) asm volatile( \
    "mma.sync.aligned.m16n8k16.row.col.f32.f16.f16.f32 " \
    "{%0,%1,%2,%3},{%4,%5,%6,%7},{%8,%9},{%0,%1,%2,%3};" \
    : "+f"((c)[0]), "+f"((c)[1]), "+f"((c)[2]), "+f"((c)[3]) \
    : "r"((a)[0]), "r"((a)[1]), "r"((a)[2]), "r"((a)[3]), "r"(b0), "r"(b1))

__device__ __forceinline__ uint32_t packh2(float x, float y) {
    __half2 h = __floats2half2_rn(x, y);
    return *(uint32_t*)&h;
}

// ---------------------------------------------------------------------------
// merged fp32 -> fp16 convert for x, wo, wk, wv (2 x float4 per thread)
// f4 layout: x [0,2M), wo [2M,6M), wk [6M,7M), wv [7M,8M)
// ---------------------------------------------------------------------------
__global__ __launch_bounds__(256) void cvt_all_kernel(
    const float* __restrict__ x,  const float* __restrict__ wo,
    const float* __restrict__ wk, const float* __restrict__ wv,
    __half* __restrict__ xh,  __half* __restrict__ woh,
    __half* __restrict__ wkh, __half* __restrict__ wvh)
{
    const long i = (long)blockIdx.x * blockDim.x + threadIdx.x;  // 2-f4 unit
    const long j = i * 2;                                        // f4 index
    const float4* s; __half2* d; long base;
    if (j < 2L*1024*1024)      { s = (const float4*)x;  d = (__half2*)xh;  base = j; }
    else if (j < 6L*1024*1024) { s = (const float4*)wo; d = (__half2*)woh; base = j - 2L*1024*1024; }
    else if (j < 7L*1024*1024) { s = (const float4*)wk; d = (__half2*)wkh; base = j - 6L*1024*1024; }
    else                       { s = (const float4*)wv; d = (__half2*)wvh; base = j - 7L*1024*1024; }
    #pragma unroll
    for (int t = 0; t < 2; t++) {
        float4 v = s[base + t];
        d[(base + t) * 2]     = __floats2half2_rn(v.x, v.y);
        d[(base + t) * 2 + 1] = __floats2half2_rn(v.z, v.w);
    }
}

// ---------------------------------------------------------------------------
// fp16 tensor-core GEMM core: C[128, 8*NJ*4] tile of A[M,K] @ W[N,K]^T + bias
// NJ = n8-fragments per warp (4 -> BN=128, 2 -> BN=64). 8 warps: 2m x 4n.
// 4-stage cp.async pipeline, 1 sync per 32-K chunk.
// ---------------------------------------------------------------------------
#define ROWB   80u
#define B_OFF  10240u
#define STAGEB 20480u
#define NSTG   4
#define GSMEM  (NSTG * 20480)

template<int NJ, bool ROPE, bool F32OUT>
__device__ __forceinline__ void gemm_core(
    const __half* __restrict__ A, const __half* __restrict__ W,
    const float* __restrict__ bias,
    float* __restrict__ Cout, __half* __restrict__ Ch,
    const float* __restrict__ fc, const float* __restrict__ fs,
    int bm, int n0, int ldc, uint32_t sb)
{
    const int tid  = threadIdx.x;
    const int lane = tid & 31;
    const int wid  = tid >> 5;
    const int wm   = wid & 1;
    const int wn   = wid >> 1;
    const int BN   = NJ * 32;      // 128 or 64

    const int r0 = tid >> 2, cc = tid & 3;
    const uint32_t so0 = (uint32_t)r0 * ROWB + cc * 16u;
    const uint32_t so1 = so0 + 64u * ROWB;
    const size_t  go0 = (size_t)r0 * 8192 + cc * 16;
    const size_t  go1 = go0 + (size_t)64 * 8192;

    const char* pA = (const char*)A + (size_t)bm * 8192;
    const char* pB = (const char*)W + (size_t)n0 * 8192;

#define LOADCHUNK(cidx, s) do { \
    uint32_t _st = sb + (uint32_t)(s) * STAGEB; \
    size_t _kb = (size_t)(cidx) * 64; \
    CP16(_st + so0,         pA + go0 + _kb); CP16(_st + so1, pA + go1 + _kb); \
    CP16(_st + B_OFF + so0, pB + go0 + _kb); \
    if (NJ == 4) { CP16(_st + B_OFF + so1, pB + go1 + _kb); } \
    } while (0)

    float acc[4][NJ][4];
    #pragma unroll
    for (int i = 0; i < 4; i++)
        #pragma unroll
        for (int j = 0; j < NJ; j++)
            #pragma unroll
            for (int t = 0; t < 4; t++) acc[i][j][t] = 0.f;

    const int NC = KDIM / 32;   // 128 chunks

    LOADCHUNK(0, 0); CP_COMMIT();
    LOADCHUNK(1, 1); CP_COMMIT();
    LOADCHUNK(2, 2); CP_COMMIT();

    const uint32_t aRow = (uint32_t)(wm * 64 + (lane & 15)) * ROWB + ((lane >> 4) & 1) * 16u;
    const uint32_t bRow = (uint32_t)(wn * (8 * NJ) + ((lane >> 4) << 3) + (lane & 7)) * ROWB
                        + ((lane >> 3) & 1) * 16u;

    for (int c = 0; c < NC; ++c) {
        CP_WAIT2();
        __syncthreads();
        if (c + 3 < NC) LOADCHUNK(c + 3, (c + 3) & (NSTG - 1));
        CP_COMMIT();

        const uint32_t stg = sb + (uint32_t)(c & (NSTG - 1)) * STAGEB;
        #pragma unroll
        for (int k16 = 0; k16 < 2; ++k16) {
            const uint32_t kb = (uint32_t)k16 * 32u;
            uint32_t ah[4][4], bh[NJ / 2][4];
            #pragma unroll
            for (int i = 0; i < 4; i++)
                LDSM4(ah[i], stg + aRow + (uint32_t)(i * 16) * ROWB + kb);
            #pragma unroll
            for (int p = 0; p < NJ / 2; p++)
                LDSM4(bh[p], stg + B_OFF + bRow + (uint32_t)(p * 16) * ROWB + kb);
            #pragma unroll
            for (int i = 0; i < 4; i++) {
                #pragma unroll
                for (int j = 0; j < NJ; j++) {
                    const int p = j >> 1, f = (j & 1) * 2;
                    MMAH(acc[i][j], ah[i], bh[p][f], bh[p][f + 1]);
                }
            }
        }
    }

    // ---- epilogue ----
    #pragma unroll
    for (int i = 0; i < 4; i++) {
        const int row0 = bm + wm * 64 + i * 16 + (lane >> 2);
        #pragma unroll
        for (int j = 0; j < NJ; j++) {
            const int col = n0 + wn * (8 * NJ) + j * 8 + (lane & 3) * 2;
            const float bv0 = bias[col], bv1 = bias[col + 1];
            #pragma unroll
            for (int t = 0; t < 2; t++) {
                const int row = row0 + t * 8;
                float v0 = acc[i][j][2 * t]     + bv0;
                float v1 = acc[i][j][2 * t + 1] + bv1;
                if (F32OUT) {
                    *(float2*)&Cout[(size_t)row * ldc + col] = make_float2(v0, v1);
                } else {
                    if (ROPE) {
                        const int idx = (col & (HD - 1)) >> 1;
                        const float cs = fc[row * 64 + idx];
                        const float sn = fs[row * 64 + idx];
                        const float re = v0 * cs - v1 * sn;
                        const float im = v0 * sn + v1 * cs;
                        v0 = re; v1 = im;
                    }
                    *(uint32_t*)&Ch[(size_t)row * ldc + col] = packh2(v0, v1);
                }
            }
        }
    }
#undef LOADCHUNK
}

// QKV: grid (64, 16). bx<32: q (BN=128, RoPE); [32,48): k (BN=64, RoPE);
// [48,64): v (BN=64). All three regions share the wave pool.
__global__ __launch_bounds__(256) void qkv_gemm_kernel(
    const __half* __restrict__ A,
    const __half* __restrict__ Wq, const float* __restrict__ bq, __half* __restrict__ Cq,
    const __half* __restrict__ Wk, const float* __restrict__ bk, __half* __restrict__ Ck,
    const __half* __restrict__ Wv, const float* __restrict__ bv, __half* __restrict__ Cv,
    const float* __restrict__ fc, const float* __restrict__ fs)
{
    extern __shared__ char dsm[];
    const uint32_t sb = smem_u32(dsm);
    const int bx = blockIdx.x;
    const int bm = blockIdx.y * 128;
    if (bx < 32) {
        gemm_core<4, true, false>(A, Wq, bq, nullptr, Cq, fc, fs, bm, bx * 128, DIM, sb);
    } else if (bx < 48) {
        gemm_core<2, true, false>(A, Wk, bk, nullptr, Ck, fc, fs, bm, (bx - 32) * 64, KVD, sb);
    } else {
        gemm_core<2, false, false>(A, Wv, bv, nullptr, Cv, fc, fs, bm, (bx - 48) * 64, KVD, sb);
    }
}

// Out-proj: grid (64, 16), BN=64, fp32 output.
__global__ __launch_bounds__(256) void out_gemm_kernel(
    const __half* __restrict__ A,
    const __half* __restrict__ W, const float* __restrict__ bias,
    float* __restrict__ Cout)
{
    extern __shared__ char dsm[];
    const uint32_t sb = smem_u32(dsm);
    gemm_core<2, false, true>(A, W, bias, Cout, nullptr, nullptr, nullptr,
                              blockIdx.y * 128, blockIdx.x * 64, DIM, sb);
}

// ---------------------------------------------------------------------------
// fp16 tensor-core flash attention (fp32 softmax), causal, GQA.  (unchanged)
// ---------------------------------------------------------------------------
#define FROWB  272u
#define SQ_    0u
#define SKV    34816u
#define VOFF   17408u
#define KVSTG  34816u
#define FA2SMEM (34816 + 2 * 34816)

__global__ __launch_bounds__(256) void fa_mma_kernel(
    const __half* __restrict__ qh, const __half* __restrict__ kh,
    const __half* __restrict__ vh, __half* __restrict__ oh)
{
    extern __shared__ char sm[];
    const uint32_t sb = smem_u32(sm);

    const int qtile = gridDim.x - 1 - blockIdx.x;
    const int h = blockIdx.y, kvh = h >> 2;
    const int tid = threadIdx.x, wid = tid >> 5, lane = tid & 31;
    const int qbase = qtile * 128;

    {
        const char* gq = (const char*)qh + ((size_t)qbase * DIM + h * HD) * 2;
        for (int i = tid; i < 2048; i += 256) {
            uint32_t r = i >> 4, c = i & 15;
            CP16(sb + SQ_ + r * FROWB + c * 16, gq + (size_t)r * 8192 + c * 16);
        }
    }

#define LOADKV(jb, s) do { \
    uint32_t _st = sb + SKV + (uint32_t)(s) * KVSTG; \
    size_t _gb = ((size_t)(jb) * KVD + kvh * HD) * 2; \
    for (int _i = tid; _i < 1024; _i += 256) { \
        uint32_t _r = _i >> 4, _c = _i & 15; \
        uint32_t _d = _st + _r * FROWB + _c * 16; \
        size_t _s2 = _gb + (size_t)_r * 2048 + _c * 16; \
        CP16(_d,        (const char*)kh + _s2); \
        CP16(_d + VOFF, (const char*)vh + _s2); \
    } } while (0)

    const int NT = (qtile + 1) * 2;
    LOADKV(0, 0);
    CP_COMMIT();

    float m0 = -1e30f, m1 = -1e30f, l0 = 0.f, l1 = 0.f;
    float acc_o[16][4];
    #pragma unroll
    for (int n = 0; n < 16; n++)
        #pragma unroll
        for (int t = 0; t < 4; t++) acc_o[n][t] = 0.f;

    const float kl = 0.12751689f;  // (1/sqrt(128)) * log2(e)
    const uint32_t aoff = (uint32_t)(wid * 16 + (lane & 15)) * FROWB + (uint32_t)((lane >> 4) & 1) * 16u;
    const uint32_t boffBase = (uint32_t)(((lane >> 4) << 3) + (lane & 7)) * FROWB
                            + (uint32_t)((lane >> 3) & 1) * 16u;
    const uint32_t voffBase = (uint32_t)(lane & 15) * FROWB + (uint32_t)(lane >> 4) * 16u;
    const int r0g = qbase + wid * 16 + (lane >> 2);

    for (int c = 0; c < NT; ++c) {
        CP_WAIT0();
        __syncthreads();
        if (c + 1 < NT) { LOADKV((c + 1) * 64, (c + 1) & 1); CP_COMMIT(); }

        const uint32_t stg = sb + SKV + (uint32_t)(c & 1) * KVSTG;

        float s[8][4];
        #pragma unroll
        for (int j = 0; j < 8; j++)
            #pragma unroll
            for (int t = 0; t < 4; t++) s[j][t] = 0.f;

        #pragma unroll
        for (int kk = 0; kk < 8; ++kk) {
            uint32_t ah[4];
            LDSM4(ah, sb + SQ_ + aoff + kk * 32);
            #pragma unroll
            for (int g = 0; g < 4; ++g) {
                uint32_t bh[4];
                LDSM4(bh, stg + (uint32_t)(g * 16) * FROWB + boffBase + kk * 32);
                MMAH(s[2*g],   ah, bh[0], bh[1]);
                MMAH(s[2*g+1], ah, bh[2], bh[3]);
            }
        }

        const int jbase = c * 64;
        if (jbase + 63 > qbase + wid * 16) {
            #pragma unroll
            for (int j = 0; j < 8; j++) {
                int col = jbase + j * 8 + (lane & 3) * 2;
                if (col     > r0g)     s[j][0] = -1e30f;
                if (col + 1 > r0g)     s[j][1] = -1e30f;
                if (col     > r0g + 8) s[j][2] = -1e30f;
                if (col + 1 > r0g + 8) s[j][3] = -1e30f;
            }
        }

        float mx0 = -1e30f, mx1 = -1e30f;
        #pragma unroll
        for (int j = 0; j < 8; j++) {
            mx0 = fmaxf(mx0, fmaxf(s[j][0], s[j][1]));
            mx1 = fmaxf(mx1, fmaxf(s[j][2], s[j][3]));
        }
        mx0 = fmaxf(mx0, __shfl_xor_sync(0xFFFFFFFFu, mx0, 1));
        mx0 = fmaxf(mx0, __shfl_xor_sync(0xFFFFFFFFu, mx0, 2));
        mx1 = fmaxf(mx1, __shfl_xor_sync(0xFFFFFFFFu, mx1, 1));
        mx1 = fmaxf(mx1, __shfl_xor_sync(0xFFFFFFFFu, mx1, 2));
        const float nm0 = fmaxf(m0, mx0), nm1 = fmaxf(m1, mx1);
        const float corr0 = exp2f((m0 - nm0) * kl), corr1 = exp2f((m1 - nm1) * kl);
        const float nb0 = -nm0 * kl, nb1 = -nm1 * kl;
        float sum0 = 0.f, sum1 = 0.f;
        #pragma unroll
        for (int j = 0; j < 8; j++) {
            s[j][0] = exp2f(fmaf(s[j][0], kl, nb0));
            s[j][1] = exp2f(fmaf(s[j][1], kl, nb0));
            s[j][2] = exp2f(fmaf(s[j][2], kl, nb1));
            s[j][3] = exp2f(fmaf(s[j][3], kl, nb1));
            sum0 += s[j][0] + s[j][1];
            sum1 += s[j][2] + s[j][3];
        }
        sum0 += __shfl_xor_sync(0xFFFFFFFFu, sum0, 1);
        sum0 += __shfl_xor_sync(0xFFFFFFFFu, sum0, 2);
        sum1 += __shfl_xor_sync(0xFFFFFFFFu, sum1, 1);
        sum1 += __shfl_xor_sync(0xFFFFFFFFu, sum1, 2);
        l0 = l0 * corr0 + sum0;
        l1 = l1 * corr1 + sum1;
        m0 = nm0; m1 = nm1;
        #pragma unroll
        for (int n = 0; n < 16; n++) {
            acc_o[n][0] *= corr0; acc_o[n][1] *= corr0;
            acc_o[n][2] *= corr1; acc_o[n][3] *= corr1;
        }

        uint32_t aP[4][4];
        #pragma unroll
        for (int g = 0; g < 4; ++g) {
            #pragma unroll
            for (int part = 0; part < 4; ++part) {
                const int j = 2 * g + (part >> 1);
                const int e = (part & 1) * 2;
                aP[g][part] = packh2(s[j][e], s[j][e + 1]);
            }
        }

        #pragma unroll
        for (int n16 = 0; n16 < 8; ++n16) {
            #pragma unroll
            for (int kk = 0; kk < 4; ++kk) {
                uint32_t vf[4];
                LDSM4T(vf, stg + VOFF + (uint32_t)(kk * 16) * FROWB + voffBase + n16 * 32);
                MMAH(acc_o[2*n16],   aP[kk], vf[0], vf[1]);
                MMAH(acc_o[2*n16+1], aP[kk], vf[2], vf[3]);
            }
        }
    }

    const float inv0 = 1.f / l0, inv1 = 1.f / l1;
    #pragma unroll
    for (int n8 = 0; n8 < 16; ++n8) {
        const int col = h * HD + n8 * 8 + (lane & 3) * 2;
        *(uint32_t*)&oh[(size_t)r0g * DIM + col] =
            packh2(acc_o[n8][0] * inv0, acc_o[n8][1] * inv0);
        *(uint32_t*)&oh[(size_t)(r0g + 8) * DIM + col] =
            packh2(acc_o[n8][2] * inv1, acc_o[n8][3] * inv1);
    }
#undef LOADKV
}

// ---------------------------------------------------------------------------
extern "C" void kernel_launch(void* const* d_in, const int* in_sizes, int n_in,
                              void* d_out, int out_size)
{
    const float* x    = (const float*)d_in[0];
    const float* fc   = (const float*)d_in[1];
    const float* fs   = (const float*)d_in[2];
    const float* wk_w = (const float*)d_in[6];
    const float* wk_b = (const float*)d_in[7];
    const float* wv_w = (const float*)d_in[8];
    const float* wv_b = (const float*)d_in[9];
    const float* wo_w = (const float*)d_in[10];
    const float* wo_b = (const float*)d_in[11];
    float* out = (float*)d_out;

    __half *xh, *woh, *wkh, *wvh, *qh, *kh, *vh, *ah;
    cudaGetSymbolAddress((void**)&xh,  g_xh);
    cudaGetSymbolAddress((void**)&woh, g_woh);
    cudaGetSymbolAddress((void**)&wkh, g_wkh);
    cudaGetSymbolAddress((void**)&wvh, g_wvh);
    cudaGetSymbolAddress((void**)&qh,  g_qh);
    cudaGetSymbolAddress((void**)&kh,  g_kh);
    cudaGetSymbolAddress((void**)&vh,  g_vh);
    cudaGetSymbolAddress((void**)&ah,  g_ah);

    // 0) merged fp32 -> fp16 converts (x + 3 weights), 8M float4 total
    cvt_all_kernel<<<16384, 256>>>(x, wo_w, wk_w, wv_w, xh, woh, wkh, wvh);

    cudaFuncSetAttribute(qkv_gemm_kernel,
                         cudaFuncAttributeMaxDynamicSharedMemorySize, GSMEM);
    cudaFuncSetAttribute(out_gemm_kernel,
                         cudaFuncAttributeMaxDynamicSharedMemorySize, GSMEM);
    cudaFuncSetAttribute(fa_mma_kernel,
                         cudaFuncAttributeMaxDynamicSharedMemorySize, FA2SMEM);

    // 1) fused QKV projection + bias + RoPE -> fp16 q/k/v (q uses wo_w per ref)
    //    mixed tiles: q 128x128 (512 CTAs) + k/v 128x64 (512 CTAs)
    dim3 gqkv(64, 16);
    qkv_gemm_kernel<<<gqkv, 256, GSMEM>>>(xh,
                                          woh, wo_b, qh,
                                          wkh, wk_b, kh,
                                          wvh, wv_b, vh,
                                          fc, fs);

    // 2) fp16 tensor-core causal GQA flash attention -> fp16 att
    dim3 gfa(T_SEQ / 128, NH);
    fa_mma_kernel<<<gfa, 256, FA2SMEM>>>(qh, kh, vh, ah);

    // 3) output projection -> fp32 out, 128x64 tiles (1024 CTAs, 3.5 equiv waves)
    dim3 go(64, 16);
    out_gemm_kernel<<<go, 256, GSMEM>>>(ah, woh, wo_b, out);
}

// round 8
// speedup vs baseline: 8.1017x; 1.0501x over previous
#include <cuda_runtime.h>
#include <cuda_fp16.h>
#include <math.h>
#include <stdint.h>

#define T_SEQ 2048
#define DIM   4096
#define NH    32
#define NKV   8
#define HD    128
#define KVD   1024
#define KDIM  4096

// ---------------- scratch (static __device__, no allocation) ----------------
__device__ __half g_xh [T_SEQ * DIM];
__device__ __half g_woh[DIM * DIM];
__device__ __half g_wkh[KVD * DIM];
__device__ __half g_wvh[KVD * DIM];
__device__ __half g_qh [T_SEQ * DIM];
__device__ __half g_kh [T_SEQ * KVD];
__device__ __half g_vh [T_SEQ * KVD];
__device__ __half g_ah [T_SEQ * DIM];

// ---------------- PTX helpers (baseline ISA only) ----------------
__device__ __forceinline__ uint32_t smem_u32(const void* p) {
    uint32_t a;
    asm("{ .reg .u64 t; cvta.to.shared.u64 t, %1; cvt.u32.u64 %0, t; }" : "=r"(a) : "l"(p));
    return a;
}
#define CP16(dst, src) asm volatile("cp.async.cg.shared.global [%0], [%1], 16;" :: "r"(dst), "l"(src))
#define CP_COMMIT()    asm volatile("cp.async.commit_group;" ::: "memory")
#define CP_WAIT1()     asm volatile("cp.async.wait_group 1;" ::: "memory")
#define CP_WAIT0()     asm volatile("cp.async.wait_group 0;" ::: "memory")

#define LDSM4(r, a) asm volatile( \
    "ldmatrix.sync.aligned.m8n8.x4.shared.b16 {%0,%1,%2,%3}, [%4];" \
    : "=r"((r)[0]), "=r"((r)[1]), "=r"((r)[2]), "=r"((r)[3]) : "r"(a))
#define LDSM4T(r, a) asm volatile( \
    "ldmatrix.sync.aligned.m8n8.x4.trans.shared.b16 {%0,%1,%2,%3}, [%4];" \
    : "=r"((r)[0]), "=r"((r)[1]), "=r"((r)[2]), "=r"((r)[3]) : "r"(a))

#define MMAH(c, a, b0, b1) asm volatile( \
    "mma.sync.aligned.m16n8k16.row.col.f32.f16.f16.f32 " \
    "{%0,%1,%2,%3},{%4,%5,%6,%7},{%8,%9},{%0,%1,%2,%3};" \
    : "+f"((c)[0]), "+f"((c)[1]), "+f"((c)[2]), "+f"((c)[3]) \
    : "r"((a)[0]), "r"((a)[1]), "r"((a)[2]), "r"((a)[3]), "r"(b0), "r"(b1))

__device__ __forceinline__ uint32_t packh2(float x, float y) {
    __half2 h = __floats2half2_rn(x, y);
    return *(uint32_t*)&h;
}

// ---------------------------------------------------------------------------
// merged fp32 -> fp16 convert for x, wo, wk, wv (2 x float4 per thread)
// ---------------------------------------------------------------------------
__global__ __launch_bounds__(256) void cvt_all_kernel(
    const float* __restrict__ x,  const float* __restrict__ wo,
    const float* __restrict__ wk, const float* __restrict__ wv,
    __half* __restrict__ xh,  __half* __restrict__ woh,
    __half* __restrict__ wkh, __half* __restrict__ wvh)
{
    const long i = (long)blockIdx.x * blockDim.x + threadIdx.x;
    const long j = i * 2;
    const float4* s; __half2* d; long base;
    if (j < 2L*1024*1024)      { s = (const float4*)x;  d = (__half2*)xh;  base = j; }
    else if (j < 6L*1024*1024) { s = (const float4*)wo; d = (__half2*)woh; base = j - 2L*1024*1024; }
    else if (j < 7L*1024*1024) { s = (const float4*)wk; d = (__half2*)wkh; base = j - 6L*1024*1024; }
    else                       { s = (const float4*)wv; d = (__half2*)wvh; base = j - 7L*1024*1024; }
    #pragma unroll
    for (int t = 0; t < 2; t++) {
        float4 v = s[base + t];
        d[(base + t) * 2]     = __floats2half2_rn(v.x, v.y);
        d[(base + t) * 2 + 1] = __floats2half2_rn(v.z, v.w);
    }
}

// ---------------------------------------------------------------------------
// fp16 tensor-core GEMM core. NJ n8-frags/warp (4 -> BN=128, 2 -> BN=64).
// 3-stage cp.async pipeline (60KB smem) -> 2 CTAs/SM co-resident.
// ---------------------------------------------------------------------------
#define ROWB   80u
#define B_OFF  10240u
#define STAGEB 20480u
#define NSTG   3
#define GSMEM  (NSTG * 20480)

template<int NJ, bool ROPE, bool F32OUT>
__device__ __forceinline__ void gemm_core(
    const __half* __restrict__ A, const __half* __restrict__ W,
    const float* __restrict__ bias,
    float* __restrict__ Cout, __half* __restrict__ Ch,
    const float* __restrict__ fc, const float* __restrict__ fs,
    int bm, int n0, int ldc, uint32_t sb)
{
    const int tid  = threadIdx.x;
    const int lane = tid & 31;
    const int wid  = tid >> 5;
    const int wm   = wid & 1;
    const int wn   = wid >> 1;

    const int r0 = tid >> 2, cc = tid & 3;
    const uint32_t so0 = (uint32_t)r0 * ROWB + cc * 16u;
    const uint32_t so1 = so0 + 64u * ROWB;
    const size_t  go0 = (size_t)r0 * 8192 + cc * 16;
    const size_t  go1 = go0 + (size_t)64 * 8192;

    const char* pA = (const char*)A + (size_t)bm * 8192;
    const char* pB = (const char*)W + (size_t)n0 * 8192;

#define LOADCHUNK(cidx, s) do { \
    uint32_t _st = sb + (uint32_t)(s) * STAGEB; \
    size_t _kb = (size_t)(cidx) * 64; \
    CP16(_st + so0,         pA + go0 + _kb); CP16(_st + so1, pA + go1 + _kb); \
    CP16(_st + B_OFF + so0, pB + go0 + _kb); \
    if (NJ == 4) { CP16(_st + B_OFF + so1, pB + go1 + _kb); } \
    } while (0)

    float acc[4][NJ][4];
    #pragma unroll
    for (int i = 0; i < 4; i++)
        #pragma unroll
        for (int j = 0; j < NJ; j++)
            #pragma unroll
            for (int t = 0; t < 4; t++) acc[i][j][t] = 0.f;

    const int NC = KDIM / 32;   // 128 chunks

    LOADCHUNK(0, 0); CP_COMMIT();
    LOADCHUNK(1, 1); CP_COMMIT();

    const uint32_t aRow = (uint32_t)(wm * 64 + (lane & 15)) * ROWB + ((lane >> 4) & 1) * 16u;
    const uint32_t bRow = (uint32_t)(wn * (8 * NJ) + ((lane >> 4) << 3) + (lane & 7)) * ROWB
                        + ((lane >> 3) & 1) * 16u;

    int stage = 0;         // stage of chunk c
    for (int c = 0; c < NC; ++c) {
        CP_WAIT1();                       // chunk c copies (this thread) done
        __syncthreads();                  // everyone's chunk-c copies visible;
                                          // all warps done computing chunk c-1
        {
            int ls = stage + 2; if (ls >= NSTG) ls -= NSTG;   // (c+2)%3
            if (c + 2 < NC) LOADCHUNK(c + 2, ls);
            CP_COMMIT();                  // always commit (keeps wait count exact)
        }

        const uint32_t stg = sb + (uint32_t)stage * STAGEB;
        #pragma unroll
        for (int k16 = 0; k16 < 2; ++k16) {
            const uint32_t kb = (uint32_t)k16 * 32u;
            uint32_t ah[4][4], bh[NJ / 2][4];
            #pragma unroll
            for (int i = 0; i < 4; i++)
                LDSM4(ah[i], stg + aRow + (uint32_t)(i * 16) * ROWB + kb);
            #pragma unroll
            for (int p = 0; p < NJ / 2; p++)
                LDSM4(bh[p], stg + B_OFF + bRow + (uint32_t)(p * 16) * ROWB + kb);
            #pragma unroll
            for (int i = 0; i < 4; i++) {
                #pragma unroll
                for (int j = 0; j < NJ; j++) {
                    const int p = j >> 1, f = (j & 1) * 2;
                    MMAH(acc[i][j], ah[i], bh[p][f], bh[p][f + 1]);
                }
            }
        }
        if (++stage == NSTG) stage = 0;
    }

    // ---- epilogue ----
    #pragma unroll
    for (int i = 0; i < 4; i++) {
        const int row0 = bm + wm * 64 + i * 16 + (lane >> 2);
        #pragma unroll
        for (int j = 0; j < NJ; j++) {
            const int col = n0 + wn * (8 * NJ) + j * 8 + (lane & 3) * 2;
            const float bv0 = bias[col], bv1 = bias[col + 1];
            #pragma unroll
            for (int t = 0; t < 2; t++) {
                const int row = row0 + t * 8;
                float v0 = acc[i][j][2 * t]     + bv0;
                float v1 = acc[i][j][2 * t + 1] + bv1;
                if (F32OUT) {
                    *(float2*)&Cout[(size_t)row * ldc + col] = make_float2(v0, v1);
                } else {
                    if (ROPE) {
                        const int idx = (col & (HD - 1)) >> 1;
                        const float cs = fc[row * 64 + idx];
                        const float sn = fs[row * 64 + idx];
                        const float re = v0 * cs - v1 * sn;
                        const float im = v0 * sn + v1 * cs;
                        v0 = re; v1 = im;
                    }
                    *(uint32_t*)&Ch[(size_t)row * ldc + col] = packh2(v0, v1);
                }
            }
        }
    }
#undef LOADCHUNK
}

// QKV: grid (64, 16). bx<32: q (BN=128, RoPE); [32,48): k (BN=64, RoPE);
// [48,64): v (BN=64).
__global__ __launch_bounds__(256, 2) void qkv_gemm_kernel(
    const __half* __restrict__ A,
    const __half* __restrict__ Wq, const float* __restrict__ bq, __half* __restrict__ Cq,
    const __half* __restrict__ Wk, const float* __restrict__ bk, __half* __restrict__ Ck,
    const __half* __restrict__ Wv, const float* __restrict__ bv, __half* __restrict__ Cv,
    const float* __restrict__ fc, const float* __restrict__ fs)
{
    extern __shared__ char dsm[];
    const uint32_t sb = smem_u32(dsm);
    const int bx = blockIdx.x;
    const int bm = blockIdx.y * 128;
    if (bx < 32) {
        gemm_core<4, true, false>(A, Wq, bq, nullptr, Cq, fc, fs, bm, bx * 128, DIM, sb);
    } else if (bx < 48) {
        gemm_core<2, true, false>(A, Wk, bk, nullptr, Ck, fc, fs, bm, (bx - 32) * 64, KVD, sb);
    } else {
        gemm_core<2, false, false>(A, Wv, bv, nullptr, Cv, fc, fs, bm, (bx - 48) * 64, KVD, sb);
    }
}

// Out-proj: grid (64, 16), BN=64, fp32 output.
__global__ __launch_bounds__(256, 2) void out_gemm_kernel(
    const __half* __restrict__ A,
    const __half* __restrict__ W, const float* __restrict__ bias,
    float* __restrict__ Cout)
{
    extern __shared__ char dsm[];
    const uint32_t sb = smem_u32(dsm);
    gemm_core<2, false, true>(A, W, bias, Cout, nullptr, nullptr, nullptr,
                              blockIdx.y * 128, blockIdx.x * 64, DIM, sb);
}

// ---------------------------------------------------------------------------
// fp16 tensor-core flash attention (fp32 softmax), causal, GQA.  (unchanged)
// ---------------------------------------------------------------------------
#define FROWB  272u
#define SQ_    0u
#define SKV    34816u
#define VOFF   17408u
#define KVSTG  34816u
#define FA2SMEM (34816 + 2 * 34816)

__global__ __launch_bounds__(256) void fa_mma_kernel(
    const __half* __restrict__ qh, const __half* __restrict__ kh,
    const __half* __restrict__ vh, __half* __restrict__ oh)
{
    extern __shared__ char sm[];
    const uint32_t sb = smem_u32(sm);

    const int qtile = gridDim.x - 1 - blockIdx.x;
    const int h = blockIdx.y, kvh = h >> 2;
    const int tid = threadIdx.x, wid = tid >> 5, lane = tid & 31;
    const int qbase = qtile * 128;

    {
        const char* gq = (const char*)qh + ((size_t)qbase * DIM + h * HD) * 2;
        for (int i = tid; i < 2048; i += 256) {
            uint32_t r = i >> 4, c = i & 15;
            CP16(sb + SQ_ + r * FROWB + c * 16, gq + (size_t)r * 8192 + c * 16);
        }
    }

#define LOADKV(jb, s) do { \
    uint32_t _st = sb + SKV + (uint32_t)(s) * KVSTG; \
    size_t _gb = ((size_t)(jb) * KVD + kvh * HD) * 2; \
    for (int _i = tid; _i < 1024; _i += 256) { \
        uint32_t _r = _i >> 4, _c = _i & 15; \
        uint32_t _d = _st + _r * FROWB + _c * 16; \
        size_t _s2 = _gb + (size_t)_r * 2048 + _c * 16; \
        CP16(_d,        (const char*)kh + _s2); \
        CP16(_d + VOFF, (const char*)vh + _s2); \
    } } while (0)

    const int NT = (qtile + 1) * 2;
    LOADKV(0, 0);
    CP_COMMIT();

    float m0 = -1e30f, m1 = -1e30f, l0 = 0.f, l1 = 0.f;
    float acc_o[16][4];
    #pragma unroll
    for (int n = 0; n < 16; n++)
        #pragma unroll
        for (int t = 0; t < 4; t++) acc_o[n][t] = 0.f;

    const float kl = 0.12751689f;  // (1/sqrt(128)) * log2(e)
    const uint32_t aoff = (uint32_t)(wid * 16 + (lane & 15)) * FROWB + (uint32_t)((lane >> 4) & 1) * 16u;
    const uint32_t boffBase = (uint32_t)(((lane >> 4) << 3) + (lane & 7)) * FROWB
                            + (uint32_t)((lane >> 3) & 1) * 16u;
    const uint32_t voffBase = (uint32_t)(lane & 15) * FROWB + (uint32_t)(lane >> 4) * 16u;
    const int r0g = qbase + wid * 16 + (lane >> 2);

    for (int c = 0; c < NT; ++c) {
        CP_WAIT0();
        __syncthreads();
        if (c + 1 < NT) { LOADKV((c + 1) * 64, (c + 1) & 1); CP_COMMIT(); }

        const uint32_t stg = sb + SKV + (uint32_t)(c & 1) * KVSTG;

        float s[8][4];
        #pragma unroll
        for (int j = 0; j < 8; j++)
            #pragma unroll
            for (int t = 0; t < 4; t++) s[j][t] = 0.f;

        #pragma unroll
        for (int kk = 0; kk < 8; ++kk) {
            uint32_t ah[4];
            LDSM4(ah, sb + SQ_ + aoff + kk * 32);
            #pragma unroll
            for (int g = 0; g < 4; ++g) {
                uint32_t bh[4];
                LDSM4(bh, stg + (uint32_t)(g * 16) * FROWB + boffBase + kk * 32);
                MMAH(s[2*g],   ah, bh[0], bh[1]);
                MMAH(s[2*g+1], ah, bh[2], bh[3]);
            }
        }

        const int jbase = c * 64;
        if (jbase + 63 > qbase + wid * 16) {
            #pragma unroll
            for (int j = 0; j < 8; j++) {
                int col = jbase + j * 8 + (lane & 3) * 2;
                if (col     > r0g)     s[j][0] = -1e30f;
                if (col + 1 > r0g)     s[j][1] = -1e30f;
                if (col     > r0g + 8) s[j][2] = -1e30f;
                if (col + 1 > r0g + 8) s[j][3] = -1e30f;
            }
        }

        float mx0 = -1e30f, mx1 = -1e30f;
        #pragma unroll
        for (int j = 0; j < 8; j++) {
            mx0 = fmaxf(mx0, fmaxf(s[j][0], s[j][1]));
            mx1 = fmaxf(mx1, fmaxf(s[j][2], s[j][3]));
        }
        mx0 = fmaxf(mx0, __shfl_xor_sync(0xFFFFFFFFu, mx0, 1));
        mx0 = fmaxf(mx0, __shfl_xor_sync(0xFFFFFFFFu, mx0, 2));
        mx1 = fmaxf(mx1, __shfl_xor_sync(0xFFFFFFFFu, mx1, 1));
        mx1 = fmaxf(mx1, __shfl_xor_sync(0xFFFFFFFFu, mx1, 2));
        const float nm0 = fmaxf(m0, mx0), nm1 = fmaxf(m1, mx1);
        const float corr0 = exp2f((m0 - nm0) * kl), corr1 = exp2f((m1 - nm1) * kl);
        const float nb0 = -nm0 * kl, nb1 = -nm1 * kl;
        float sum0 = 0.f, sum1 = 0.f;
        #pragma unroll
        for (int j = 0; j < 8; j++) {
            s[j][0] = exp2f(fmaf(s[j][0], kl, nb0));
            s[j][1] = exp2f(fmaf(s[j][1], kl, nb0));
            s[j][2] = exp2f(fmaf(s[j][2], kl, nb1));
            s[j][3] = exp2f(fmaf(s[j][3], kl, nb1));
            sum0 += s[j][0] + s[j][1];
            sum1 += s[j][2] + s[j][3];
        }
        sum0 += __shfl_xor_sync(0xFFFFFFFFu, sum0, 1);
        sum0 += __shfl_xor_sync(0xFFFFFFFFu, sum0, 2);
        sum1 += __shfl_xor_sync(0xFFFFFFFFu, sum1, 1);
        sum1 += __shfl_xor_sync(0xFFFFFFFFu, sum1, 2);
        l0 = l0 * corr0 + sum0;
        l1 = l1 * corr1 + sum1;
        m0 = nm0; m1 = nm1;
        #pragma unroll
        for (int n = 0; n < 16; n++) {
            acc_o[n][0] *= corr0; acc_o[n][1] *= corr0;
            acc_o[n][2] *= corr1; acc_o[n][3] *= corr1;
        }

        uint32_t aP[4][4];
        #pragma unroll
        for (int g = 0; g < 4; ++g) {
            #pragma unroll
            for (int part = 0; part < 4; ++part) {
                const int j = 2 * g + (part >> 1);
                const int e = (part & 1) * 2;
                aP[g][part] = packh2(s[j][e], s[j][e + 1]);
            }
        }

        #pragma unroll
        for (int n16 = 0; n16 < 8; ++n16) {
            #pragma unroll
            for (int kk = 0; kk < 4; ++kk) {
                uint32_t vf[4];
                LDSM4T(vf, stg + VOFF + (uint32_t)(kk * 16) * FROWB + voffBase + n16 * 32);
                MMAH(acc_o[2*n16],   aP[kk], vf[0], vf[1]);
                MMAH(acc_o[2*n16+1], aP[kk], vf[2], vf[3]);
            }
        }
    }

    const float inv0 = 1.f / l0, inv1 = 1.f / l1;
    #pragma unroll
    for (int n8 = 0; n8 < 16; ++n8) {
        const int col = h * HD + n8 * 8 + (lane & 3) * 2;
        *(uint32_t*)&oh[(size_t)r0g * DIM + col] =
            packh2(acc_o[n8][0] * inv0, acc_o[n8][1] * inv0);
        *(uint32_t*)&oh[(size_t)(r0g + 8) * DIM + col] =
            packh2(acc_o[n8][2] * inv1, acc_o[n8][3] * inv1);
    }
#undef LOADKV
}

// ---------------------------------------------------------------------------
extern "C" void kernel_launch(void* const* d_in, const int* in_sizes, int n_in,
                              void* d_out, int out_size)
{
    const float* x    = (const float*)d_in[0];
    const float* fc   = (const float*)d_in[1];
    const float* fs   = (const float*)d_in[2];
    const float* wk_w = (const float*)d_in[6];
    const float* wk_b = (const float*)d_in[7];
    const float* wv_w = (const float*)d_in[8];
    const float* wv_b = (const float*)d_in[9];
    const float* wo_w = (const float*)d_in[10];
    const float* wo_b = (const float*)d_in[11];
    float* out = (float*)d_out;

    __half *xh, *woh, *wkh, *wvh, *qh, *kh, *vh, *ah;
    cudaGetSymbolAddress((void**)&xh,  g_xh);
    cudaGetSymbolAddress((void**)&woh, g_woh);
    cudaGetSymbolAddress((void**)&wkh, g_wkh);
    cudaGetSymbolAddress((void**)&wvh, g_wvh);
    cudaGetSymbolAddress((void**)&qh,  g_qh);
    cudaGetSymbolAddress((void**)&kh,  g_kh);
    cudaGetSymbolAddress((void**)&vh,  g_vh);
    cudaGetSymbolAddress((void**)&ah,  g_ah);

    // 0) merged fp32 -> fp16 converts
    cvt_all_kernel<<<16384, 256>>>(x, wo_w, wk_w, wv_w, xh, woh, wkh, wvh);

    cudaFuncSetAttribute(qkv_gemm_kernel,
                         cudaFuncAttributeMaxDynamicSharedMemorySize, GSMEM);
    cudaFuncSetAttribute(out_gemm_kernel,
                         cudaFuncAttributeMaxDynamicSharedMemorySize, GSMEM);
    cudaFuncSetAttribute(fa_mma_kernel,
                         cudaFuncAttributeMaxDynamicSharedMemorySize, FA2SMEM);

    // 1) fused QKV projection + bias + RoPE -> fp16 q/k/v
    dim3 gqkv(64, 16);
    qkv_gemm_kernel<<<gqkv, 256, GSMEM>>>(xh,
                                          woh, wo_b, qh,
                                          wkh, wk_b, kh,
                                          wvh, wv_b, vh,
                                          fc, fs);

    // 2) fp16 tensor-core causal GQA flash attention -> fp16 att
    dim3 gfa(T_SEQ / 128, NH);
    fa_mma_kernel<<<gfa, 256, FA2SMEM>>>(qh, kh, vh, ah);

    // 3) output projection -> fp32 out (128x64 tiles, 2 CTAs/SM)
    dim3 go(64, 16);
    out_gemm_kernel<<<go, 256, GSMEM>>>(ah, woh, wo_b, out);
}

// round 9
// speedup vs baseline: 8.3158x; 1.0264x over previous
#include <cuda_runtime.h>
#include <cuda_fp16.h>
#include <math.h>
#include <stdint.h>

#define T_SEQ 2048
#define DIM   4096
#define NH    32
#define NKV   8
#define HD    128
#define KVD   1024
#define KDIM  4096

// ---------------- scratch (static __device__, no allocation) ----------------
__device__ __half g_xh [T_SEQ * DIM];
__device__ __half g_woh[DIM * DIM];
__device__ __half g_wkh[KVD * DIM];
__device__ __half g_wvh[KVD * DIM];
__device__ __half g_qh [T_SEQ * DIM];
__device__ __half g_kh [T_SEQ * KVD];
__device__ __half g_vh [T_SEQ * KVD];
__device__ __half g_ah [T_SEQ * DIM];

// ---------------- PTX helpers (baseline ISA only) ----------------
__device__ __forceinline__ uint32_t smem_u32(const void* p) {
    uint32_t a;
    asm("{ .reg .u64 t; cvta.to.shared.u64 t, %1; cvt.u32.u64 %0, t; }" : "=r"(a) : "l"(p));
    return a;
}
#define CP16(dst, src) asm volatile("cp.async.cg.shared.global [%0], [%1], 16;" :: "r"(dst), "l"(src))
#define CP_COMMIT()    asm volatile("cp.async.commit_group;" ::: "memory")
#define CP_WAIT1()     asm volatile("cp.async.wait_group 1;" ::: "memory")
#define CP_WAIT0()     asm volatile("cp.async.wait_group 0;" ::: "memory")

#define LDSM4(r, a) asm volatile( \
    "ldmatrix.sync.aligned.m8n8.x4.shared.b16 {%0,%1,%2,%3}, [%4];" \
    : "=r"((r)[0]), "=r"((r)[1]), "=r"((r)[2]), "=r"((r)[3]) : "r"(a))
#define LDSM4T(r, a) asm volatile( \
    "ldmatrix.sync.aligned.m8n8.x4.trans.shared.b16 {%0,%1,%2,%3}, [%4];" \
    : "=r"((r)[0]), "=r"((r)[1]), "=r"((r)[2]), "=r"((r)[3]) : "r"(a))

#define MMAH(c, a, b0, b1) asm volatile( \
    "mma.sync.aligned.m16n8k16.row.col.f32.f16.f16.f32 " \
    "{%0,%1,%2,%3},{%4,%5,%6,%7},{%8,%9},{%0,%1,%2,%3};" \
    : "+f"((c)[0]), "+f"((c)[1]), "+f"((c)[2]), "+f"((c)[3]) \
    : "r"((a)[0]), "r"((a)[1]), "r"((a)[2]), "r"((a)[3]), "r"(b0), "r"(b1))

__device__ __forceinline__ uint32_t packh2(float x, float y) {
    __half2 h = __floats2half2_rn(x, y);
    return *(uint32_t*)&h;
}

// ---------------------------------------------------------------------------
// merged fp32 -> fp16 convert for x, wo, wk, wv (2 x float4 per thread)
// ---------------------------------------------------------------------------
__global__ __launch_bounds__(256) void cvt_all_kernel(
    const float* __restrict__ x,  const float* __restrict__ wo,
    const float* __restrict__ wk, const float* __restrict__ wv,
    __half* __restrict__ xh,  __half* __restrict__ woh,
    __half* __restrict__ wkh, __half* __restrict__ wvh)
{
    const long i = (long)blockIdx.x * blockDim.x + threadIdx.x;
    const long j = i * 2;
    const float4* s; __half2* d; long base;
    if (j < 2L*1024*1024)      { s = (const float4*)x;  d = (__half2*)xh;  base = j; }
    else if (j < 6L*1024*1024) { s = (const float4*)wo; d = (__half2*)woh; base = j - 2L*1024*1024; }
    else if (j < 7L*1024*1024) { s = (const float4*)wk; d = (__half2*)wkh; base = j - 6L*1024*1024; }
    else                       { s = (const float4*)wv; d = (__half2*)wvh; base = j - 7L*1024*1024; }
    #pragma unroll
    for (int t = 0; t < 2; t++) {
        float4 v = s[base + t];
        d[(base + t) * 2]     = __floats2half2_rn(v.x, v.y);
        d[(base + t) * 2 + 1] = __floats2half2_rn(v.z, v.w);
    }
}

// ---------------------------------------------------------------------------
// fp16 tensor-core GEMM core, NJ=4 (BN=128, warp tile 64x32).
// 3-stage cp.async pipeline (60KB) -> 2 CTAs/SM.
// ---------------------------------------------------------------------------
#define ROWB   80u
#define B_OFF  10240u
#define STAGEB 20480u
#define NSTG   3
#define GSMEM  (NSTG * 20480)

template<bool ROPE, bool F32OUT>
__device__ __forceinline__ void gemm_core(
    const __half* __restrict__ A, const __half* __restrict__ W,
    const float* __restrict__ bias,
    float* __restrict__ Cout, __half* __restrict__ Ch,
    const float* __restrict__ fc, const float* __restrict__ fs,
    int bm, int n0, int ldc, uint32_t sb)
{
    const int tid  = threadIdx.x;
    const int lane = tid & 31;
    const int wid  = tid >> 5;
    const int wm   = wid & 1;
    const int wn   = wid >> 1;

    const int r0 = tid >> 2, cc = tid & 3;
    const uint32_t so0 = (uint32_t)r0 * ROWB + cc * 16u;
    const uint32_t so1 = so0 + 64u * ROWB;
    const size_t  go0 = (size_t)r0 * 8192 + cc * 16;
    const size_t  go1 = go0 + (size_t)64 * 8192;

    const char* pA = (const char*)A + (size_t)bm * 8192;
    const char* pB = (const char*)W + (size_t)n0 * 8192;

#define LOADCHUNK(cidx, s) do { \
    uint32_t _st = sb + (uint32_t)(s) * STAGEB; \
    size_t _kb = (size_t)(cidx) * 64; \
    CP16(_st + so0,         pA + go0 + _kb); CP16(_st + so1,         pA + go1 + _kb); \
    CP16(_st + B_OFF + so0, pB + go0 + _kb); CP16(_st + B_OFF + so1, pB + go1 + _kb); \
    } while (0)

    float acc[4][4][4];
    #pragma unroll
    for (int i = 0; i < 4; i++)
        #pragma unroll
        for (int j = 0; j < 4; j++)
            #pragma unroll
            for (int t = 0; t < 4; t++) acc[i][j][t] = 0.f;

    const int NC = KDIM / 32;   // 128 chunks

    LOADCHUNK(0, 0); CP_COMMIT();
    LOADCHUNK(1, 1); CP_COMMIT();

    const uint32_t aRow = (uint32_t)(wm * 64 + (lane & 15)) * ROWB + ((lane >> 4) & 1) * 16u;
    const uint32_t bRow = (uint32_t)(wn * 32 + ((lane >> 4) << 3) + (lane & 7)) * ROWB
                        + ((lane >> 3) & 1) * 16u;

    int stage = 0;
    for (int c = 0; c < NC; ++c) {
        CP_WAIT1();
        __syncthreads();
        {
            int ls = stage + 2; if (ls >= NSTG) ls -= NSTG;
            if (c + 2 < NC) LOADCHUNK(c + 2, ls);
            CP_COMMIT();
        }

        const uint32_t stg = sb + (uint32_t)stage * STAGEB;
        #pragma unroll
        for (int k16 = 0; k16 < 2; ++k16) {
            const uint32_t kb = (uint32_t)k16 * 32u;
            uint32_t ah[4][4], bh[2][4];
            #pragma unroll
            for (int i = 0; i < 4; i++)
                LDSM4(ah[i], stg + aRow + (uint32_t)(i * 16) * ROWB + kb);
            #pragma unroll
            for (int p = 0; p < 2; p++)
                LDSM4(bh[p], stg + B_OFF + bRow + (uint32_t)(p * 16) * ROWB + kb);
            #pragma unroll
            for (int i = 0; i < 4; i++) {
                #pragma unroll
                for (int j = 0; j < 4; j++) {
                    const int p = j >> 1, f = (j & 1) * 2;
                    MMAH(acc[i][j], ah[i], bh[p][f], bh[p][f + 1]);
                }
            }
        }
        if (++stage == NSTG) stage = 0;
    }

    // ---- epilogue ----
    #pragma unroll
    for (int i = 0; i < 4; i++) {
        const int row0 = bm + wm * 64 + i * 16 + (lane >> 2);
        #pragma unroll
        for (int j = 0; j < 4; j++) {
            const int col = n0 + wn * 32 + j * 8 + (lane & 3) * 2;
            const float bv0 = bias[col], bv1 = bias[col + 1];
            #pragma unroll
            for (int t = 0; t < 2; t++) {
                const int row = row0 + t * 8;
                float v0 = acc[i][j][2 * t]     + bv0;
                float v1 = acc[i][j][2 * t + 1] + bv1;
                if (F32OUT) {
                    *(float2*)&Cout[(size_t)row * ldc + col] = make_float2(v0, v1);
                } else {
                    if (ROPE) {
                        const int idx = (col & (HD - 1)) >> 1;
                        const float cs = fc[row * 64 + idx];
                        const float sn = fs[row * 64 + idx];
                        const float re = v0 * cs - v1 * sn;
                        const float im = v0 * sn + v1 * cs;
                        v0 = re; v1 = im;
                    }
                    *(uint32_t*)&Ch[(size_t)row * ldc + col] = packh2(v0, v1);
                }
            }
        }
    }
#undef LOADCHUNK
}

// QKV: grid (48, 16), all BN=128. bx<32: q (RoPE); [32,40): k (RoPE); [40,48): v.
__global__ __launch_bounds__(256, 2) void qkv_gemm_kernel(
    const __half* __restrict__ A,
    const __half* __restrict__ Wq, const float* __restrict__ bq, __half* __restrict__ Cq,
    const __half* __restrict__ Wk, const float* __restrict__ bk, __half* __restrict__ Ck,
    const __half* __restrict__ Wv, const float* __restrict__ bv, __half* __restrict__ Cv,
    const float* __restrict__ fc, const float* __restrict__ fs)
{
    extern __shared__ char dsm[];
    const uint32_t sb = smem_u32(dsm);
    const int bx = blockIdx.x;
    const int bm = blockIdx.y * 128;
    if (bx < 32) {
        gemm_core<true, false>(A, Wq, bq, nullptr, Cq, fc, fs, bm, bx * 128, DIM, sb);
    } else if (bx < 40) {
        gemm_core<true, false>(A, Wk, bk, nullptr, Ck, fc, fs, bm, (bx - 32) * 128, KVD, sb);
    } else {
        gemm_core<false, false>(A, Wv, bv, nullptr, Cv, fc, fs, bm, (bx - 40) * 128, KVD, sb);
    }
}

// Out-proj: grid (32, 16), BN=128, fp32 output.
__global__ __launch_bounds__(256, 2) void out_gemm_kernel(
    const __half* __restrict__ A,
    const __half* __restrict__ W, const float* __restrict__ bias,
    float* __restrict__ Cout)
{
    extern __shared__ char dsm[];
    const uint32_t sb = smem_u32(dsm);
    gemm_core<false, true>(A, W, bias, Cout, nullptr, nullptr, nullptr,
                           blockIdx.y * 128, blockIdx.x * 128, DIM, sb);
}

// ---------------------------------------------------------------------------
// fp16 tensor-core flash attention (fp32 softmax), causal, GQA.  (unchanged)
// ---------------------------------------------------------------------------
#define FROWB  272u
#define SQ_    0u
#define SKV    34816u
#define VOFF   17408u
#define KVSTG  34816u
#define FA2SMEM (34816 + 2 * 34816)

__global__ __launch_bounds__(256) void fa_mma_kernel(
    const __half* __restrict__ qh, const __half* __restrict__ kh,
    const __half* __restrict__ vh, __half* __restrict__ oh)
{
    extern __shared__ char sm[];
    const uint32_t sb = smem_u32(sm);

    const int qtile = gridDim.x - 1 - blockIdx.x;
    const int h = blockIdx.y, kvh = h >> 2;
    const int tid = threadIdx.x, wid = tid >> 5, lane = tid & 31;
    const int qbase = qtile * 128;

    {
        const char* gq = (const char*)qh + ((size_t)qbase * DIM + h * HD) * 2;
        for (int i = tid; i < 2048; i += 256) {
            uint32_t r = i >> 4, c = i & 15;
            CP16(sb + SQ_ + r * FROWB + c * 16, gq + (size_t)r * 8192 + c * 16);
        }
    }

#define LOADKV(jb, s) do { \
    uint32_t _st = sb + SKV + (uint32_t)(s) * KVSTG; \
    size_t _gb = ((size_t)(jb) * KVD + kvh * HD) * 2; \
    for (int _i = tid; _i < 1024; _i += 256) { \
        uint32_t _r = _i >> 4, _c = _i & 15; \
        uint32_t _d = _st + _r * FROWB + _c * 16; \
        size_t _s2 = _gb + (size_t)_r * 2048 + _c * 16; \
        CP16(_d,        (const char*)kh + _s2); \
        CP16(_d + VOFF, (const char*)vh + _s2); \
    } } while (0)

    const int NT = (qtile + 1) * 2;
    LOADKV(0, 0);
    CP_COMMIT();

    float m0 = -1e30f, m1 = -1e30f, l0 = 0.f, l1 = 0.f;
    float acc_o[16][4];
    #pragma unroll
    for (int n = 0; n < 16; n++)
        #pragma unroll
        for (int t = 0; t < 4; t++) acc_o[n][t] = 0.f;

    const float kl = 0.12751689f;  // (1/sqrt(128)) * log2(e)
    const uint32_t aoff = (uint32_t)(wid * 16 + (lane & 15)) * FROWB + (uint32_t)((lane >> 4) & 1) * 16u;
    const uint32_t boffBase = (uint32_t)(((lane >> 4) << 3) + (lane & 7)) * FROWB
                            + (uint32_t)((lane >> 3) & 1) * 16u;
    const uint32_t voffBase = (uint32_t)(lane & 15) * FROWB + (uint32_t)(lane >> 4) * 16u;
    const int r0g = qbase + wid * 16 + (lane >> 2);

    for (int c = 0; c < NT; ++c) {
        CP_WAIT0();
        __syncthreads();
        if (c + 1 < NT) { LOADKV((c + 1) * 64, (c + 1) & 1); CP_COMMIT(); }

        const uint32_t stg = sb + SKV + (uint32_t)(c & 1) * KVSTG;

        float s[8][4];
        #pragma unroll
        for (int j = 0; j < 8; j++)
            #pragma unroll
            for (int t = 0; t < 4; t++) s[j][t] = 0.f;

        #pragma unroll
        for (int kk = 0; kk < 8; ++kk) {
            uint32_t ah[4];
            LDSM4(ah, sb + SQ_ + aoff + kk * 32);
            #pragma unroll
            for (int g = 0; g < 4; ++g) {
                uint32_t bh[4];
                LDSM4(bh, stg + (uint32_t)(g * 16) * FROWB + boffBase + kk * 32);
                MMAH(s[2*g],   ah, bh[0], bh[1]);
                MMAH(s[2*g+1], ah, bh[2], bh[3]);
            }
        }

        const int jbase = c * 64;
        if (jbase + 63 > qbase + wid * 16) {
            #pragma unroll
            for (int j = 0; j < 8; j++) {
                int col = jbase + j * 8 + (lane & 3) * 2;
                if (col     > r0g)     s[j][0] = -1e30f;
                if (col + 1 > r0g)     s[j][1] = -1e30f;
                if (col     > r0g + 8) s[j][2] = -1e30f;
                if (col + 1 > r0g + 8) s[j][3] = -1e30f;
            }
        }

        float mx0 = -1e30f, mx1 = -1e30f;
        #pragma unroll
        for (int j = 0; j < 8; j++) {
            mx0 = fmaxf(mx0, fmaxf(s[j][0], s[j][1]));
            mx1 = fmaxf(mx1, fmaxf(s[j][2], s[j][3]));
        }
        mx0 = fmaxf(mx0, __shfl_xor_sync(0xFFFFFFFFu, mx0, 1));
        mx0 = fmaxf(mx0, __shfl_xor_sync(0xFFFFFFFFu, mx0, 2));
        mx1 = fmaxf(mx1, __shfl_xor_sync(0xFFFFFFFFu, mx1, 1));
        mx1 = fmaxf(mx1, __shfl_xor_sync(0xFFFFFFFFu, mx1, 2));
        const float nm0 = fmaxf(m0, mx0), nm1 = fmaxf(m1, mx1);
        const float corr0 = exp2f((m0 - nm0) * kl), corr1 = exp2f((m1 - nm1) * kl);
        const float nb0 = -nm0 * kl, nb1 = -nm1 * kl;
        float sum0 = 0.f, sum1 = 0.f;
        #pragma unroll
        for (int j = 0; j < 8; j++) {
            s[j][0] = exp2f(fmaf(s[j][0], kl, nb0));
            s[j][1] = exp2f(fmaf(s[j][1], kl, nb0));
            s[j][2] = exp2f(fmaf(s[j][2], kl, nb1));
            s[j][3] = exp2f(fmaf(s[j][3], kl, nb1));
            sum0 += s[j][0] + s[j][1];
            sum1 += s[j][2] + s[j][3];
        }
        sum0 += __shfl_xor_sync(0xFFFFFFFFu, sum0, 1);
        sum0 += __shfl_xor_sync(0xFFFFFFFFu, sum0, 2);
        sum1 += __shfl_xor_sync(0xFFFFFFFFu, sum1, 1);
        sum1 += __shfl_xor_sync(0xFFFFFFFFu, sum1, 2);
        l0 = l0 * corr0 + sum0;
        l1 = l1 * corr1 + sum1;
        m0 = nm0; m1 = nm1;
        #pragma unroll
        for (int n = 0; n < 16; n++) {
            acc_o[n][0] *= corr0; acc_o[n][1] *= corr0;
            acc_o[n][2] *= corr1; acc_o[n][3] *= corr1;
        }

        uint32_t aP[4][4];
        #pragma unroll
        for (int g = 0; g < 4; ++g) {
            #pragma unroll
            for (int part = 0; part < 4; ++part) {
                const int j = 2 * g + (part >> 1);
                const int e = (part & 1) * 2;
                aP[g][part] = packh2(s[j][e], s[j][e + 1]);
            }
        }

        #pragma unroll
        for (int n16 = 0; n16 < 8; ++n16) {
            #pragma unroll
            for (int kk = 0; kk < 4; ++kk) {
                uint32_t vf[4];
                LDSM4T(vf, stg + VOFF + (uint32_t)(kk * 16) * FROWB + voffBase + n16 * 32);
                MMAH(acc_o[2*n16],   aP[kk], vf[0], vf[1]);
                MMAH(acc_o[2*n16+1], aP[kk], vf[2], vf[3]);
            }
        }
    }

    const float inv0 = 1.f / l0, inv1 = 1.f / l1;
    #pragma unroll
    for (int n8 = 0; n8 < 16; ++n8) {
        const int col = h * HD + n8 * 8 + (lane & 3) * 2;
        *(uint32_t*)&oh[(size_t)r0g * DIM + col] =
            packh2(acc_o[n8][0] * inv0, acc_o[n8][1] * inv0);
        *(uint32_t*)&oh[(size_t)(r0g + 8) * DIM + col] =
            packh2(acc_o[n8][2] * inv1, acc_o[n8][3] * inv1);
    }
#undef LOADKV
}

// ---------------------------------------------------------------------------
extern "C" void kernel_launch(void* const* d_in, const int* in_sizes, int n_in,
                              void* d_out, int out_size)
{
    const float* x    = (const float*)d_in[0];
    const float* fc   = (const float*)d_in[1];
    const float* fs   = (const float*)d_in[2];
    const float* wk_w = (const float*)d_in[6];
    const float* wk_b = (const float*)d_in[7];
    const float* wv_w = (const float*)d_in[8];
    const float* wv_b = (const float*)d_in[9];
    const float* wo_w = (const float*)d_in[10];
    const float* wo_b = (const float*)d_in[11];
    float* out = (float*)d_out;

    __half *xh, *woh, *wkh, *wvh, *qh, *kh, *vh, *ah;
    cudaGetSymbolAddress((void**)&xh,  g_xh);
    cudaGetSymbolAddress((void**)&woh, g_woh);
    cudaGetSymbolAddress((void**)&wkh, g_wkh);
    cudaGetSymbolAddress((void**)&wvh, g_wvh);
    cudaGetSymbolAddress((void**)&qh,  g_qh);
    cudaGetSymbolAddress((void**)&kh,  g_kh);
    cudaGetSymbolAddress((void**)&vh,  g_vh);
    cudaGetSymbolAddress((void**)&ah,  g_ah);

    // 0) merged fp32 -> fp16 converts
    cvt_all_kernel<<<16384, 256>>>(x, wo_w, wk_w, wv_w, xh, woh, wkh, wvh);

    cudaFuncSetAttribute(qkv_gemm_kernel,
                         cudaFuncAttributeMaxDynamicSharedMemorySize, GSMEM);
    cudaFuncSetAttribute(out_gemm_kernel,
                         cudaFuncAttributeMaxDynamicSharedMemorySize, GSMEM);
    cudaFuncSetAttribute(fa_mma_kernel,
                         cudaFuncAttributeMaxDynamicSharedMemorySize, FA2SMEM);

    // 1) fused QKV projection + bias + RoPE -> fp16 q/k/v (uniform BN=128)
    dim3 gqkv(48, 16);
    qkv_gemm_kernel<<<gqkv, 256, GSMEM>>>(xh,
                                          woh, wo_b, qh,
                                          wkh, wk_b, kh,
                                          wvh, wv_b, vh,
                                          fc, fs);

    // 2) fp16 tensor-core causal GQA flash attention -> fp16 att
    dim3 gfa(T_SEQ / 128, NH);
    fa_mma_kernel<<<gfa, 256, FA2SMEM>>>(qh, kh, vh, ah);

    // 3) output projection -> fp32 out (BN=128, 2 CTAs/SM)
    dim3 go(32, 16);
    out_gemm_kernel<<<go, 256, GSMEM>>>(ah, woh, wo_b, out);
}

// round 10
// speedup vs baseline: 8.7537x; 1.0527x over previous
#include <cuda_runtime.h>
#include <cuda_fp16.h>
#include <math.h>
#include <stdint.h>

#define T_SEQ 2048
#define DIM   4096
#define NH    32
#define NKV   8
#define HD    128
#define KVD   1024
#define KDIM  4096

// ---------------- scratch (static __device__, no allocation) ----------------
__device__ __half g_xh [T_SEQ * DIM];
__device__ __half g_woh[DIM * DIM];
__device__ __half g_wkh[KVD * DIM];
__device__ __half g_wvh[KVD * DIM];
__device__ __half g_qh [T_SEQ * DIM];
__device__ __half g_kh [T_SEQ * KVD];
__device__ __half g_vh [T_SEQ * KVD];
__device__ __half g_ah [T_SEQ * DIM];

// ---------------- PTX helpers (baseline ISA only) ----------------
__device__ __forceinline__ uint32_t smem_u32(const void* p) {
    uint32_t a;
    asm("{ .reg .u64 t; cvta.to.shared.u64 t, %1; cvt.u32.u64 %0, t; }" : "=r"(a) : "l"(p));
    return a;
}
#define CP16(dst, src) asm volatile("cp.async.cg.shared.global [%0], [%1], 16;" :: "r"(dst), "l"(src))
#define CP_COMMIT()    asm volatile("cp.async.commit_group;" ::: "memory")
#define CP_WAIT0()     asm volatile("cp.async.wait_group 0;" ::: "memory")

#define LDSM4(r, a) asm volatile( \
    "ldmatrix.sync.aligned.m8n8.x4.shared.b16 {%0,%1,%2,%3}, [%4];" \
    : "=r"((r)[0]), "=r"((r)[1]), "=r"((r)[2]), "=r"((r)[3]) : "r"(a))
#define LDSM4T(r, a) asm volatile( \
    "ldmatrix.sync.aligned.m8n8.x4.trans.shared.b16 {%0,%1,%2,%3}, [%4];" \
    : "=r"((r)[0]), "=r"((r)[1]), "=r"((r)[2]), "=r"((r)[3]) : "r"(a))

#define MMAH(c, a, b0, b1) asm volatile( \
    "mma.sync.aligned.m16n8k16.row.col.f32.f16.f16.f32 " \
    "{%0,%1,%2,%3},{%4,%5,%6,%7},{%8,%9},{%0,%1,%2,%3};" \
    : "+f"((c)[0]), "+f"((c)[1]), "+f"((c)[2]), "+f"((c)[3]) \
    : "r"((a)[0]), "r"((a)[1]), "r"((a)[2]), "r"((a)[3]), "r"(b0), "r"(b1))

__device__ __forceinline__ uint32_t packh2(float x, float y) {
    __half2 h = __floats2half2_rn(x, y);
    return *(uint32_t*)&h;
}

// ---------------------------------------------------------------------------
// merged fp32 -> fp16 convert, 4 independent float4 per thread (MLP=4)
// f4 layout: x [0,2M), wo [2M,6M), wk [6M,7M), wv [7M,8M)
// ---------------------------------------------------------------------------
__global__ __launch_bounds__(256) void cvt_all_kernel(
    const float* __restrict__ x,  const float* __restrict__ wo,
    const float* __restrict__ wk, const float* __restrict__ wv,
    __half* __restrict__ xh,  __half* __restrict__ woh,
    __half* __restrict__ wkh, __half* __restrict__ wvh)
{
    const long i = (long)blockIdx.x * blockDim.x + threadIdx.x;
    const long j = i * 4;
    const float4* s; __half2* d; long base;
    if (j < 2L*1024*1024)      { s = (const float4*)x;  d = (__half2*)xh;  base = j; }
    else if (j < 6L*1024*1024) { s = (const float4*)wo; d = (__half2*)woh; base = j - 2L*1024*1024; }
    else if (j < 7L*1024*1024) { s = (const float4*)wk; d = (__half2*)wkh; base = j - 6L*1024*1024; }
    else                       { s = (const float4*)wv; d = (__half2*)wvh; base = j - 7L*1024*1024; }
    float4 v0 = s[base], v1 = s[base+1], v2 = s[base+2], v3 = s[base+3];
    d[base*2+0] = __floats2half2_rn(v0.x, v0.y); d[base*2+1] = __floats2half2_rn(v0.z, v0.w);
    d[base*2+2] = __floats2half2_rn(v1.x, v1.y); d[base*2+3] = __floats2half2_rn(v1.z, v1.w);
    d[base*2+4] = __floats2half2_rn(v2.x, v2.y); d[base*2+5] = __floats2half2_rn(v2.z, v2.w);
    d[base*2+6] = __floats2half2_rn(v3.x, v3.y); d[base*2+7] = __floats2half2_rn(v3.z, v3.w);
}

// ---------------------------------------------------------------------------
// fp16 tensor-core GEMM core, BN=128, warp tile 64x32, BK=64 chunks,
// 2-stage double buffer (72KB smem) -> 2 CTAs/SM. 64 sync points.
// ---------------------------------------------------------------------------
#define ROWB   144u                  // 128B data + 16B pad (odd 16B stride)
#define B_OFF  (128u * 144u)         // 18432
#define STAGEB (2u * 128u * 144u)    // 36864
#define GSMEM  (2 * 36864)           // 73728

template<bool ROPE, bool F32OUT>
__device__ __forceinline__ void gemm_core(
    const __half* __restrict__ A, const __half* __restrict__ W,
    const float* __restrict__ bias,
    float* __restrict__ Cout, __half* __restrict__ Ch,
    const float* __restrict__ fc, const float* __restrict__ fs,
    int bm, int n0, int ldc, uint32_t sb)
{
    const int tid  = threadIdx.x;
    const int lane = tid & 31;
    const int wid  = tid >> 5;
    const int wm   = wid & 1;
    const int wn   = wid >> 1;

    // cp.async geometry: thread covers rows {r0, r0+32, r0+64, r0+96}, 16B col cc
    const int r0 = tid >> 3, cc = tid & 7;
    const uint32_t so = (uint32_t)r0 * ROWB + cc * 16u;
    const size_t  go = (size_t)r0 * 8192 + cc * 16;

    const char* pA = (const char*)A + (size_t)bm * 8192;
    const char* pB = (const char*)W + (size_t)n0 * 8192;

#define LOADCHUNK(cidx, s) do { \
    uint32_t _st = sb + (uint32_t)(s) * STAGEB; \
    size_t _kb = (size_t)(cidx) * 128; \
    _Pragma("unroll") \
    for (int _p = 0; _p < 4; _p++) { \
        CP16(_st + so + _p * (32u * ROWB),         pA + go + (size_t)_p * (32 * 8192) + _kb); \
        CP16(_st + B_OFF + so + _p * (32u * ROWB), pB + go + (size_t)_p * (32 * 8192) + _kb); \
    } } while (0)

    float acc[4][4][4];
    #pragma unroll
    for (int i = 0; i < 4; i++)
        #pragma unroll
        for (int j = 0; j < 4; j++)
            #pragma unroll
            for (int t = 0; t < 4; t++) acc[i][j][t] = 0.f;

    const int NC = KDIM / 64;   // 64 chunks

    LOADCHUNK(0, 0); CP_COMMIT();

    const uint32_t aRow = (uint32_t)(wm * 64 + (lane & 15)) * ROWB + ((lane >> 4) & 1) * 16u;
    const uint32_t bRow = (uint32_t)(wn * 32 + ((lane >> 4) << 3) + (lane & 7)) * ROWB
                        + ((lane >> 3) & 1) * 16u;

    for (int c = 0; c < NC; ++c) {
        CP_WAIT0();                       // chunk c resident
        __syncthreads();                  // all warps done with stage (c-1)&1
        if (c + 1 < NC) { LOADCHUNK(c + 1, (c + 1) & 1); CP_COMMIT(); }

        const uint32_t stg = sb + (uint32_t)(c & 1) * STAGEB;
        #pragma unroll
        for (int k16 = 0; k16 < 4; ++k16) {
            const uint32_t kb = (uint32_t)k16 * 32u;
            uint32_t ah[4][4], bh[2][4];
            #pragma unroll
            for (int i = 0; i < 4; i++)
                LDSM4(ah[i], stg + aRow + (uint32_t)(i * 16) * ROWB + kb);
            #pragma unroll
            for (int p = 0; p < 2; p++)
                LDSM4(bh[p], stg + B_OFF + bRow + (uint32_t)(p * 16) * ROWB + kb);
            #pragma unroll
            for (int i = 0; i < 4; i++) {
                #pragma unroll
                for (int j = 0; j < 4; j++) {
                    const int p = j >> 1, f = (j & 1) * 2;
                    MMAH(acc[i][j], ah[i], bh[p][f], bh[p][f + 1]);
                }
            }
        }
    }

    // ---- epilogue ----
    #pragma unroll
    for (int i = 0; i < 4; i++) {
        const int row0 = bm + wm * 64 + i * 16 + (lane >> 2);
        #pragma unroll
        for (int j = 0; j < 4; j++) {
            const int col = n0 + wn * 32 + j * 8 + (lane & 3) * 2;
            const float bv0 = bias[col], bv1 = bias[col + 1];
            #pragma unroll
            for (int t = 0; t < 2; t++) {
                const int row = row0 + t * 8;
                float v0 = acc[i][j][2 * t]     + bv0;
                float v1 = acc[i][j][2 * t + 1] + bv1;
                if (F32OUT) {
                    *(float2*)&Cout[(size_t)row * ldc + col] = make_float2(v0, v1);
                } else {
                    if (ROPE) {
                        const int idx = (col & (HD - 1)) >> 1;
                        const float cs = fc[row * 64 + idx];
                        const float sn = fs[row * 64 + idx];
                        const float re = v0 * cs - v1 * sn;
                        const float im = v0 * sn + v1 * cs;
                        v0 = re; v1 = im;
                    }
                    *(uint32_t*)&Ch[(size_t)row * ldc + col] = packh2(v0, v1);
                }
            }
        }
    }
#undef LOADCHUNK
}

// QKV: grid (48, 16), BN=128. bx<32: q (RoPE); [32,40): k (RoPE); [40,48): v.
__global__ __launch_bounds__(256, 2) void qkv_gemm_kernel(
    const __half* __restrict__ A,
    const __half* __restrict__ Wq, const float* __restrict__ bq, __half* __restrict__ Cq,
    const __half* __restrict__ Wk, const float* __restrict__ bk, __half* __restrict__ Ck,
    const __half* __restrict__ Wv, const float* __restrict__ bv, __half* __restrict__ Cv,
    const float* __restrict__ fc, const float* __restrict__ fs)
{
    extern __shared__ char dsm[];
    const uint32_t sb = smem_u32(dsm);
    const int bx = blockIdx.x;
    const int bm = blockIdx.y * 128;
    if (bx < 32) {
        gemm_core<true, false>(A, Wq, bq, nullptr, Cq, fc, fs, bm, bx * 128, DIM, sb);
    } else if (bx < 40) {
        gemm_core<true, false>(A, Wk, bk, nullptr, Ck, fc, fs, bm, (bx - 32) * 128, KVD, sb);
    } else {
        gemm_core<false, false>(A, Wv, bv, nullptr, Cv, fc, fs, bm, (bx - 40) * 128, KVD, sb);
    }
}

// Out-proj: grid (32, 16), BN=128, fp32 output.
__global__ __launch_bounds__(256, 2) void out_gemm_kernel(
    const __half* __restrict__ A,
    const __half* __restrict__ W, const float* __restrict__ bias,
    float* __restrict__ Cout)
{
    extern __shared__ char dsm[];
    const uint32_t sb = smem_u32(dsm);
    gemm_core<false, true>(A, W, bias, Cout, nullptr, nullptr, nullptr,
                           blockIdx.y * 128, blockIdx.x * 128, DIM, sb);
}

// ---------------------------------------------------------------------------
// fp16 tensor-core flash attention (fp32 softmax), causal, GQA.  (unchanged)
// ---------------------------------------------------------------------------
#define FROWB  272u
#define SQ_    0u
#define SKV    34816u
#define VOFF   17408u
#define KVSTG  34816u
#define FA2SMEM (34816 + 2 * 34816)

__global__ __launch_bounds__(256) void fa_mma_kernel(
    const __half* __restrict__ qh, const __half* __restrict__ kh,
    const __half* __restrict__ vh, __half* __restrict__ oh)
{
    extern __shared__ char sm[];
    const uint32_t sb = smem_u32(sm);

    const int qtile = gridDim.x - 1 - blockIdx.x;
    const int h = blockIdx.y, kvh = h >> 2;
    const int tid = threadIdx.x, wid = tid >> 5, lane = tid & 31;
    const int qbase = qtile * 128;

    {
        const char* gq = (const char*)qh + ((size_t)qbase * DIM + h * HD) * 2;
        for (int i = tid; i < 2048; i += 256) {
            uint32_t r = i >> 4, c = i & 15;
            CP16(sb + SQ_ + r * FROWB + c * 16, gq + (size_t)r * 8192 + c * 16);
        }
    }

#define LOADKV(jb, s) do { \
    uint32_t _st = sb + SKV + (uint32_t)(s) * KVSTG; \
    size_t _gb = ((size_t)(jb) * KVD + kvh * HD) * 2; \
    for (int _i = tid; _i < 1024; _i += 256) { \
        uint32_t _r = _i >> 4, _c = _i & 15; \
        uint32_t _d = _st + _r * FROWB + _c * 16; \
        size_t _s2 = _gb + (size_t)_r * 2048 + _c * 16; \
        CP16(_d,        (const char*)kh + _s2); \
        CP16(_d + VOFF, (const char*)vh + _s2); \
    } } while (0)

    const int NT = (qtile + 1) * 2;
    LOADKV(0, 0);
    CP_COMMIT();

    float m0 = -1e30f, m1 = -1e30f, l0 = 0.f, l1 = 0.f;
    float acc_o[16][4];
    #pragma unroll
    for (int n = 0; n < 16; n++)
        #pragma unroll
        for (int t = 0; t < 4; t++) acc_o[n][t] = 0.f;

    const float kl = 0.12751689f;  // (1/sqrt(128)) * log2(e)
    const uint32_t aoff = (uint32_t)(wid * 16 + (lane & 15)) * FROWB + (uint32_t)((lane >> 4) & 1) * 16u;
    const uint32_t boffBase = (uint32_t)(((lane >> 4) << 3) + (lane & 7)) * FROWB
                            + (uint32_t)((lane >> 3) & 1) * 16u;
    const uint32_t voffBase = (uint32_t)(lane & 15) * FROWB + (uint32_t)(lane >> 4) * 16u;
    const int r0g = qbase + wid * 16 + (lane >> 2);

    for (int c = 0; c < NT; ++c) {
        CP_WAIT0();
        __syncthreads();
        if (c + 1 < NT) { LOADKV((c + 1) * 64, (c + 1) & 1); CP_COMMIT(); }

        const uint32_t stg = sb + SKV + (uint32_t)(c & 1) * KVSTG;

        float s[8][4];
        #pragma unroll
        for (int j = 0; j < 8; j++)
            #pragma unroll
            for (int t = 0; t < 4; t++) s[j][t] = 0.f;

        #pragma unroll
        for (int kk = 0; kk < 8; ++kk) {
            uint32_t ah[4];
            LDSM4(ah, sb + SQ_ + aoff + kk * 32);
            #pragma unroll
            for (int g = 0; g < 4; ++g) {
                uint32_t bh[4];
                LDSM4(bh, stg + (uint32_t)(g * 16) * FROWB + boffBase + kk * 32);
                MMAH(s[2*g],   ah, bh[0], bh[1]);
                MMAH(s[2*g+1], ah, bh[2], bh[3]);
            }
        }

        const int jbase = c * 64;
        if (jbase + 63 > qbase + wid * 16) {
            #pragma unroll
            for (int j = 0; j < 8; j++) {
                int col = jbase + j * 8 + (lane & 3) * 2;
                if (col     > r0g)     s[j][0] = -1e30f;
                if (col + 1 > r0g)     s[j][1] = -1e30f;
                if (col     > r0g + 8) s[j][2] = -1e30f;
                if (col + 1 > r0g + 8) s[j][3] = -1e30f;
            }
        }

        float mx0 = -1e30f, mx1 = -1e30f;
        #pragma unroll
        for (int j = 0; j < 8; j++) {
            mx0 = fmaxf(mx0, fmaxf(s[j][0], s[j][1]));
            mx1 = fmaxf(mx1, fmaxf(s[j][2], s[j][3]));
        }
        mx0 = fmaxf(mx0, __shfl_xor_sync(0xFFFFFFFFu, mx0, 1));
        mx0 = fmaxf(mx0, __shfl_xor_sync(0xFFFFFFFFu, mx0, 2));
        mx1 = fmaxf(mx1, __shfl_xor_sync(0xFFFFFFFFu, mx1, 1));
        mx1 = fmaxf(mx1, __shfl_xor_sync(0xFFFFFFFFu, mx1, 2));
        const float nm0 = fmaxf(m0, mx0), nm1 = fmaxf(m1, mx1);
        const float corr0 = exp2f((m0 - nm0) * kl), corr1 = exp2f((m1 - nm1) * kl);
        const float nb0 = -nm0 * kl, nb1 = -nm1 * kl;
        float sum0 = 0.f, sum1 = 0.f;
        #pragma unroll
        for (int j = 0; j < 8; j++) {
            s[j][0] = exp2f(fmaf(s[j][0], kl, nb0));
            s[j][1] = exp2f(fmaf(s[j][1], kl, nb0));
            s[j][2] = exp2f(fmaf(s[j][2], kl, nb1));
            s[j][3] = exp2f(fmaf(s[j][3], kl, nb1));
            sum0 += s[j][0] + s[j][1];
            sum1 += s[j][2] + s[j][3];
        }
        sum0 += __shfl_xor_sync(0xFFFFFFFFu, sum0, 1);
        sum0 += __shfl_xor_sync(0xFFFFFFFFu, sum0, 2);
        sum1 += __shfl_xor_sync(0xFFFFFFFFu, sum1, 1);
        sum1 += __shfl_xor_sync(0xFFFFFFFFu, sum1, 2);
        l0 = l0 * corr0 + sum0;
        l1 = l1 * corr1 + sum1;
        m0 = nm0; m1 = nm1;
        #pragma unroll
        for (int n = 0; n < 16; n++) {
            acc_o[n][0] *= corr0; acc_o[n][1] *= corr0;
            acc_o[n][2] *= corr1; acc_o[n][3] *= corr1;
        }

        uint32_t aP[4][4];
        #pragma unroll
        for (int g = 0; g < 4; ++g) {
            #pragma unroll
            for (int part = 0; part < 4; ++part) {
                const int j = 2 * g + (part >> 1);
                const int e = (part & 1) * 2;
                aP[g][part] = packh2(s[j][e], s[j][e + 1]);
            }
        }

        #pragma unroll
        for (int n16 = 0; n16 < 8; ++n16) {
            #pragma unroll
            for (int kk = 0; kk < 4; ++kk) {
                uint32_t vf[4];
                LDSM4T(vf, stg + VOFF + (uint32_t)(kk * 16) * FROWB + voffBase + n16 * 32);
                MMAH(acc_o[2*n16],   aP[kk], vf[0], vf[1]);
                MMAH(acc_o[2*n16+1], aP[kk], vf[2], vf[3]);
            }
        }
    }

    const float inv0 = 1.f / l0, inv1 = 1.f / l1;
    #pragma unroll
    for (int n8 = 0; n8 < 16; ++n8) {
        const int col = h * HD + n8 * 8 + (lane & 3) * 2;
        *(uint32_t*)&oh[(size_t)r0g * DIM + col] =
            packh2(acc_o[n8][0] * inv0, acc_o[n8][1] * inv0);
        *(uint32_t*)&oh[(size_t)(r0g + 8) * DIM + col] =
            packh2(acc_o[n8][2] * inv1, acc_o[n8][3] * inv1);
    }
#undef LOADKV
}

// ---------------------------------------------------------------------------
extern "C" void kernel_launch(void* const* d_in, const int* in_sizes, int n_in,
                              void* d_out, int out_size)
{
    const float* x    = (const float*)d_in[0];
    const float* fc   = (const float*)d_in[1];
    const float* fs   = (const float*)d_in[2];
    const float* wk_w = (const float*)d_in[6];
    const float* wk_b = (const float*)d_in[7];
    const float* wv_w = (const float*)d_in[8];
    const float* wv_b = (const float*)d_in[9];
    const float* wo_w = (const float*)d_in[10];
    const float* wo_b = (const float*)d_in[11];
    float* out = (float*)d_out;

    __half *xh, *woh, *wkh, *wvh, *qh, *kh, *vh, *ah;
    cudaGetSymbolAddress((void**)&xh,  g_xh);
    cudaGetSymbolAddress((void**)&woh, g_woh);
    cudaGetSymbolAddress((void**)&wkh, g_wkh);
    cudaGetSymbolAddress((void**)&wvh, g_wvh);
    cudaGetSymbolAddress((void**)&qh,  g_qh);
    cudaGetSymbolAddress((void**)&kh,  g_kh);
    cudaGetSymbolAddress((void**)&vh,  g_vh);
    cudaGetSymbolAddress((void**)&ah,  g_ah);

    // 0) merged fp32 -> fp16 converts (MLP=4 per thread)
    cvt_all_kernel<<<8192, 256>>>(x, wo_w, wk_w, wv_w, xh, woh, wkh, wvh);

    cudaFuncSetAttribute(qkv_gemm_kernel,
                         cudaFuncAttributeMaxDynamicSharedMemorySize, GSMEM);
    cudaFuncSetAttribute(out_gemm_kernel,
                         cudaFuncAttributeMaxDynamicSharedMemorySize, GSMEM);
    cudaFuncSetAttribute(fa_mma_kernel,
                         cudaFuncAttributeMaxDynamicSharedMemorySize, FA2SMEM);

    // 1) fused QKV projection + bias + RoPE -> fp16 q/k/v (BK=64, 2-stage)
    dim3 gqkv(48, 16);
    qkv_gemm_kernel<<<gqkv, 256, GSMEM>>>(xh,
                                          woh, wo_b, qh,
                                          wkh, wk_b, kh,
                                          wvh, wv_b, vh,
                                          fc, fs);

    // 2) fp16 tensor-core causal GQA flash attention -> fp16 att
    dim3 gfa(T_SEQ / 128, NH);
    fa_mma_kernel<<<gfa, 256, FA2SMEM>>>(qh, kh, vh, ah);

    // 3) output projection -> fp32 out (BK=64, 2-stage, 2 CTAs/SM)
    dim3 go(32, 16);
    out_gemm_kernel<<<go, 256, GSMEM>>>(ah, woh, wo_b, out);
}

// round 11
// speedup vs baseline: 9.9988x; 1.1422x over previous
#include <cuda_runtime.h>
#include <cuda_fp16.h>
#include <math.h>
#include <stdint.h>

#define T_SEQ 2048
#define DIM   4096
#define NH    32
#define NKV   8
#define HD    128
#define KVD   1024
#define KDIM  4096

// ---------------- scratch (static __device__, no allocation) ----------------
__device__ __half g_xh [T_SEQ * DIM];
__device__ __half g_woh[DIM * DIM];
__device__ __half g_wkh[KVD * DIM];
__device__ __half g_wvh[KVD * DIM];
__device__ __half g_qh [T_SEQ * DIM];
__device__ __half g_kh [T_SEQ * KVD];
__device__ __half g_vh [T_SEQ * KVD];
__device__ __half g_ah [T_SEQ * DIM];

// ---------------- PTX helpers (baseline ISA only) ----------------
__device__ __forceinline__ uint32_t smem_u32(const void* p) {
    uint32_t a;
    asm("{ .reg .u64 t; cvta.to.shared.u64 t, %1; cvt.u32.u64 %0, t; }" : "=r"(a) : "l"(p));
    return a;
}
#define CP16(dst, src) asm volatile("cp.async.cg.shared.global [%0], [%1], 16;" :: "r"(dst), "l"(src))
#define CP_COMMIT()    asm volatile("cp.async.commit_group;" ::: "memory")
#define CP_WAIT0()     asm volatile("cp.async.wait_group 0;" ::: "memory")

#define LDSM4(r, a) asm volatile( \
    "ldmatrix.sync.aligned.m8n8.x4.shared.b16 {%0,%1,%2,%3}, [%4];" \
    : "=r"((r)[0]), "=r"((r)[1]), "=r"((r)[2]), "=r"((r)[3]) : "r"(a))
#define LDSM4T(r, a) asm volatile( \
    "ldmatrix.sync.aligned.m8n8.x4.trans.shared.b16 {%0,%1,%2,%3}, [%4];" \
    : "=r"((r)[0]), "=r"((r)[1]), "=r"((r)[2]), "=r"((r)[3]) : "r"(a))

#define MMAH(c, a, b0, b1) asm volatile( \
    "mma.sync.aligned.m16n8k16.row.col.f32.f16.f16.f32 " \
    "{%0,%1,%2,%3},{%4,%5,%6,%7},{%8,%9},{%0,%1,%2,%3};" \
    : "+f"((c)[0]), "+f"((c)[1]), "+f"((c)[2]), "+f"((c)[3]) \
    : "r"((a)[0]), "r"((a)[1]), "r"((a)[2]), "r"((a)[3]), "r"(b0), "r"(b1))

__device__ __forceinline__ uint32_t packh2(float x, float y) {
    __half2 h = __floats2half2_rn(x, y);
    return *(uint32_t*)&h;
}

// ---------------------------------------------------------------------------
// merged fp32 -> fp16 convert, 4 independent float4 per thread (MLP=4)
// ---------------------------------------------------------------------------
__global__ __launch_bounds__(256) void cvt_all_kernel(
    const float* __restrict__ x,  const float* __restrict__ wo,
    const float* __restrict__ wk, const float* __restrict__ wv,
    __half* __restrict__ xh,  __half* __restrict__ woh,
    __half* __restrict__ wkh, __half* __restrict__ wvh)
{
    const long i = (long)blockIdx.x * blockDim.x + threadIdx.x;
    const long j = i * 4;
    const float4* s; __half2* d; long base;
    if (j < 2L*1024*1024)      { s = (const float4*)x;  d = (__half2*)xh;  base = j; }
    else if (j < 6L*1024*1024) { s = (const float4*)wo; d = (__half2*)woh; base = j - 2L*1024*1024; }
    else if (j < 7L*1024*1024) { s = (const float4*)wk; d = (__half2*)wkh; base = j - 6L*1024*1024; }
    else                       { s = (const float4*)wv; d = (__half2*)wvh; base = j - 7L*1024*1024; }
    float4 v0 = s[base], v1 = s[base+1], v2 = s[base+2], v3 = s[base+3];
    d[base*2+0] = __floats2half2_rn(v0.x, v0.y); d[base*2+1] = __floats2half2_rn(v0.z, v0.w);
    d[base*2+2] = __floats2half2_rn(v1.x, v1.y); d[base*2+3] = __floats2half2_rn(v1.z, v1.w);
    d[base*2+4] = __floats2half2_rn(v2.x, v2.y); d[base*2+5] = __floats2half2_rn(v2.z, v2.w);
    d[base*2+6] = __floats2half2_rn(v3.x, v3.y); d[base*2+7] = __floats2half2_rn(v3.z, v3.w);
}

// ---------------------------------------------------------------------------
// fp16 tensor-core GEMM core, BN=128, BK=64, 2-stage (72KB) -> 2 CTAs/SM.
// cp.async for chunk c+1 interleaved into the k16 MMA stream (2 per k16).
// ---------------------------------------------------------------------------
#define ROWB   144u                  // 128B data + 16B pad
#define B_OFF  (128u * 144u)
#define STAGEB (2u * 128u * 144u)
#define GSMEM  (2 * 36864)

template<bool ROPE, bool F32OUT>
__device__ __forceinline__ void gemm_core(
    const __half* __restrict__ A, const __half* __restrict__ W,
    const float* __restrict__ bias,
    float* __restrict__ Cout, __half* __restrict__ Ch,
    const float* __restrict__ fc, const float* __restrict__ fs,
    int bm, int n0, int ldc, uint32_t sb)
{
    const int tid  = threadIdx.x;
    const int lane = tid & 31;
    const int wid  = tid >> 5;
    const int wm   = wid & 1;
    const int wn   = wid >> 1;

    // cp.async geometry: thread covers rows {r0, r0+32, r0+64, r0+96}, 16B col cc
    const int r0 = tid >> 3, cc = tid & 7;
    const uint32_t so = (uint32_t)r0 * ROWB + cc * 16u;
    const size_t  go = (size_t)r0 * 8192 + cc * 16;

    const char* pA = (const char*)A + (size_t)bm * 8192;
    const char* pB = (const char*)W + (size_t)n0 * 8192;

    float acc[4][4][4];
    #pragma unroll
    for (int i = 0; i < 4; i++)
        #pragma unroll
        for (int j = 0; j < 4; j++)
            #pragma unroll
            for (int t = 0; t < 4; t++) acc[i][j][t] = 0.f;

    const int NC = KDIM / 64;   // 64 chunks

    // prologue: chunk 0 (burst; nothing to overlap with)
    {
        #pragma unroll
        for (int p = 0; p < 4; p++) {
            CP16(sb + so + p * (32u * ROWB),         pA + go + (size_t)p * (32 * 8192));
            CP16(sb + B_OFF + so + p * (32u * ROWB), pB + go + (size_t)p * (32 * 8192));
        }
        CP_COMMIT();
    }

    const uint32_t aRow = (uint32_t)(wm * 64 + (lane & 15)) * ROWB + ((lane >> 4) & 1) * 16u;
    const uint32_t bRow = (uint32_t)(wn * 32 + ((lane >> 4) << 3) + (lane & 7)) * ROWB
                        + ((lane >> 3) & 1) * 16u;

    for (int c = 0; c < NC; ++c) {
        CP_WAIT0();                       // chunk c resident
        __syncthreads();                  // stage (c-1)&1 free, chunk c visible

        const uint32_t stg = sb + (uint32_t)(c & 1) * STAGEB;
        const bool more = (c + 1 < NC);
        const uint32_t nst = sb + (uint32_t)((c + 1) & 1) * STAGEB;
        const size_t  nkb = (size_t)(c + 1) * 128;

        #pragma unroll
        for (int k16 = 0; k16 < 4; ++k16) {
            // interleave 2 of the 8 next-chunk cp.async into this k16 slot
            if (more) {
                CP16(nst + so + (uint32_t)k16 * (32u * ROWB),
                     pA + go + (size_t)k16 * (32 * 8192) + nkb);
                CP16(nst + B_OFF + so + (uint32_t)k16 * (32u * ROWB),
                     pB + go + (size_t)k16 * (32 * 8192) + nkb);
            }
            const uint32_t kb = (uint32_t)k16 * 32u;
            uint32_t ah[4][4], bh[2][4];
            #pragma unroll
            for (int i = 0; i < 4; i++)
                LDSM4(ah[i], stg + aRow + (uint32_t)(i * 16) * ROWB + kb);
            #pragma unroll
            for (int p = 0; p < 2; p++)
                LDSM4(bh[p], stg + B_OFF + bRow + (uint32_t)(p * 16) * ROWB + kb);
            #pragma unroll
            for (int i = 0; i < 4; i++) {
                #pragma unroll
                for (int j = 0; j < 4; j++) {
                    const int p = j >> 1, f = (j & 1) * 2;
                    MMAH(acc[i][j], ah[i], bh[p][f], bh[p][f + 1]);
                }
            }
        }
        if (more) CP_COMMIT();
    }

    // ---- epilogue ----
    #pragma unroll
    for (int i = 0; i < 4; i++) {
        const int row0 = bm + wm * 64 + i * 16 + (lane >> 2);
        #pragma unroll
        for (int j = 0; j < 4; j++) {
            const int col = n0 + wn * 32 + j * 8 + (lane & 3) * 2;
            const float bv0 = bias[col], bv1 = bias[col + 1];
            #pragma unroll
            for (int t = 0; t < 2; t++) {
                const int row = row0 + t * 8;
                float v0 = acc[i][j][2 * t]     + bv0;
                float v1 = acc[i][j][2 * t + 1] + bv1;
                if (F32OUT) {
                    *(float2*)&Cout[(size_t)row * ldc + col] = make_float2(v0, v1);
                } else {
                    if (ROPE) {
                        const int idx = (col & (HD - 1)) >> 1;
                        const float cs = fc[row * 64 + idx];
                        const float sn = fs[row * 64 + idx];
                        const float re = v0 * cs - v1 * sn;
                        const float im = v0 * sn + v1 * cs;
                        v0 = re; v1 = im;
                    }
                    *(uint32_t*)&Ch[(size_t)row * ldc + col] = packh2(v0, v1);
                }
            }
        }
    }
}

// QKV: grid (48, 16), BN=128. bx<32: q (RoPE); [32,40): k (RoPE); [40,48): v.
__global__ __launch_bounds__(256, 2) void qkv_gemm_kernel(
    const __half* __restrict__ A,
    const __half* __restrict__ Wq, const float* __restrict__ bq, __half* __restrict__ Cq,
    const __half* __restrict__ Wk, const float* __restrict__ bk, __half* __restrict__ Ck,
    const __half* __restrict__ Wv, const float* __restrict__ bv, __half* __restrict__ Cv,
    const float* __restrict__ fc, const float* __restrict__ fs)
{
    extern __shared__ char dsm[];
    const uint32_t sb = smem_u32(dsm);
    const int bx = blockIdx.x;
    const int bm = blockIdx.y * 128;
    if (bx < 32) {
        gemm_core<true, false>(A, Wq, bq, nullptr, Cq, fc, fs, bm, bx * 128, DIM, sb);
    } else if (bx < 40) {
        gemm_core<true, false>(A, Wk, bk, nullptr, Ck, fc, fs, bm, (bx - 32) * 128, KVD, sb);
    } else {
        gemm_core<false, false>(A, Wv, bv, nullptr, Cv, fc, fs, bm, (bx - 40) * 128, KVD, sb);
    }
}

// Out-proj: grid (32, 16), BN=128, fp32 output.
__global__ __launch_bounds__(256, 2) void out_gemm_kernel(
    const __half* __restrict__ A,
    const __half* __restrict__ W, const float* __restrict__ bias,
    float* __restrict__ Cout)
{
    extern __shared__ char dsm[];
    const uint32_t sb = smem_u32(dsm);
    gemm_core<false, true>(A, W, bias, Cout, nullptr, nullptr, nullptr,
                           blockIdx.y * 128, blockIdx.x * 128, DIM, sb);
}

// ---------------------------------------------------------------------------
// fp16 tensor-core flash attention (fp32 softmax), causal, GQA.
// Next-tile KV cp.async interleaved into the QK MMA stream (2 per even kk).
// ---------------------------------------------------------------------------
#define FROWB  272u
#define SQ_    0u
#define SKV    34816u
#define VOFF   17408u
#define KVSTG  34816u
#define FA2SMEM (34816 + 2 * 34816)

__global__ __launch_bounds__(256) void fa_mma_kernel(
    const __half* __restrict__ qh, const __half* __restrict__ kh,
    const __half* __restrict__ vh, __half* __restrict__ oh)
{
    extern __shared__ char sm[];
    const uint32_t sb = smem_u32(sm);

    const int qtile = gridDim.x - 1 - blockIdx.x;
    const int h = blockIdx.y, kvh = h >> 2;
    const int tid = threadIdx.x, wid = tid >> 5, lane = tid & 31;
    const int qbase = qtile * 128;

    // per-part KV load geometry: part p covers rows (tid>>4)+16p, col (tid&15)*16
    const uint32_t kvr = (uint32_t)(tid >> 4);
    const uint32_t kvc = (uint32_t)(tid & 15) * 16u;
    const uint32_t kvd0 = kvr * FROWB + kvc;
    const size_t   kvg0 = (size_t)kvr * 2048 + kvc;

    {   // Q tile load (prologue burst)
        const char* gq = (const char*)qh + ((size_t)qbase * DIM + h * HD) * 2;
        for (int i = tid; i < 2048; i += 256) {
            uint32_t r = i >> 4, c = i & 15;
            CP16(sb + SQ_ + r * FROWB + c * 16, gq + (size_t)r * 8192 + c * 16);
        }
    }
    {   // KV tile 0 (prologue burst)
        size_t gb = ((size_t)0 * KVD + kvh * HD) * 2;
        #pragma unroll
        for (int p = 0; p < 4; p++) {
            uint32_t d = sb + SKV + kvd0 + (uint32_t)p * (16u * FROWB);
            size_t   s2 = gb + kvg0 + (size_t)p * (16 * 2048);
            CP16(d,        (const char*)kh + s2);
            CP16(d + VOFF, (const char*)vh + s2);
        }
        CP_COMMIT();
    }

    const int NT = (qtile + 1) * 2;

    float m0 = -1e30f, m1 = -1e30f, l0 = 0.f, l1 = 0.f;
    float acc_o[16][4];
    #pragma unroll
    for (int n = 0; n < 16; n++)
        #pragma unroll
        for (int t = 0; t < 4; t++) acc_o[n][t] = 0.f;

    const float kl = 0.12751689f;  // (1/sqrt(128)) * log2(e)
    const uint32_t aoff = (uint32_t)(wid * 16 + (lane & 15)) * FROWB + (uint32_t)((lane >> 4) & 1) * 16u;
    const uint32_t boffBase = (uint32_t)(((lane >> 4) << 3) + (lane & 7)) * FROWB
                            + (uint32_t)((lane >> 3) & 1) * 16u;
    const uint32_t voffBase = (uint32_t)(lane & 15) * FROWB + (uint32_t)(lane >> 4) * 16u;
    const int r0g = qbase + wid * 16 + (lane >> 2);

    for (int c = 0; c < NT; ++c) {
        CP_WAIT0();
        __syncthreads();

        const uint32_t stg = sb + SKV + (uint32_t)(c & 1) * KVSTG;
        const bool more = (c + 1 < NT);
        const uint32_t nst = sb + SKV + (uint32_t)((c + 1) & 1) * KVSTG;
        const size_t  ngb = ((size_t)(c + 1) * 64 * KVD + kvh * HD) * 2;

        float s[8][4];
        #pragma unroll
        for (int j = 0; j < 8; j++)
            #pragma unroll
            for (int t = 0; t < 4; t++) s[j][t] = 0.f;

        #pragma unroll
        for (int kk = 0; kk < 8; ++kk) {
            // interleave next-tile KV loads: 2 cp.async on each even kk
            if ((kk & 1) == 0 && more) {
                const int p = kk >> 1;
                uint32_t d = nst + kvd0 + (uint32_t)p * (16u * FROWB);
                size_t   s2 = ngb + kvg0 + (size_t)p * (16 * 2048);
                CP16(d,        (const char*)kh + s2);
                CP16(d + VOFF, (const char*)vh + s2);
            }
            uint32_t ah[4];
            LDSM4(ah, sb + SQ_ + aoff + kk * 32);
            #pragma unroll
            for (int g = 0; g < 4; ++g) {
                uint32_t bh[4];
                LDSM4(bh, stg + (uint32_t)(g * 16) * FROWB + boffBase + kk * 32);
                MMAH(s[2*g],   ah, bh[0], bh[1]);
                MMAH(s[2*g+1], ah, bh[2], bh[3]);
            }
        }
        if (more) CP_COMMIT();

        const int jbase = c * 64;
        if (jbase + 63 > qbase + wid * 16) {
            #pragma unroll
            for (int j = 0; j < 8; j++) {
                int col = jbase + j * 8 + (lane & 3) * 2;
                if (col     > r0g)     s[j][0] = -1e30f;
                if (col + 1 > r0g)     s[j][1] = -1e30f;
                if (col     > r0g + 8) s[j][2] = -1e30f;
                if (col + 1 > r0g + 8) s[j][3] = -1e30f;
            }
        }

        float mx0 = -1e30f, mx1 = -1e30f;
        #pragma unroll
        for (int j = 0; j < 8; j++) {
            mx0 = fmaxf(mx0, fmaxf(s[j][0], s[j][1]));
            mx1 = fmaxf(mx1, fmaxf(s[j][2], s[j][3]));
        }
        mx0 = fmaxf(mx0, __shfl_xor_sync(0xFFFFFFFFu, mx0, 1));
        mx0 = fmaxf(mx0, __shfl_xor_sync(0xFFFFFFFFu, mx0, 2));
        mx1 = fmaxf(mx1, __shfl_xor_sync(0xFFFFFFFFu, mx1, 1));
        mx1 = fmaxf(mx1, __shfl_xor_sync(0xFFFFFFFFu, mx1, 2));
        const float nm0 = fmaxf(m0, mx0), nm1 = fmaxf(m1, mx1);
        const float corr0 = exp2f((m0 - nm0) * kl), corr1 = exp2f((m1 - nm1) * kl);
        const float nb0 = -nm0 * kl, nb1 = -nm1 * kl;
        float sum0 = 0.f, sum1 = 0.f;
        #pragma unroll
        for (int j = 0; j < 8; j++) {
            s[j][0] = exp2f(fmaf(s[j][0], kl, nb0));
            s[j][1] = exp2f(fmaf(s[j][1], kl, nb0));
            s[j][2] = exp2f(fmaf(s[j][2], kl, nb1));
            s[j][3] = exp2f(fmaf(s[j][3], kl, nb1));
            sum0 += s[j][0] + s[j][1];
            sum1 += s[j][2] + s[j][3];
        }
        sum0 += __shfl_xor_sync(0xFFFFFFFFu, sum0, 1);
        sum0 += __shfl_xor_sync(0xFFFFFFFFu, sum0, 2);
        sum1 += __shfl_xor_sync(0xFFFFFFFFu, sum1, 1);
        sum1 += __shfl_xor_sync(0xFFFFFFFFu, sum1, 2);
        l0 = l0 * corr0 + sum0;
        l1 = l1 * corr1 + sum1;
        m0 = nm0; m1 = nm1;
        #pragma unroll
        for (int n = 0; n < 16; n++) {
            acc_o[n][0] *= corr0; acc_o[n][1] *= corr0;
            acc_o[n][2] *= corr1; acc_o[n][3] *= corr1;
        }

        uint32_t aP[4][4];
        #pragma unroll
        for (int g = 0; g < 4; ++g) {
            #pragma unroll
            for (int part = 0; part < 4; ++part) {
                const int j = 2 * g + (part >> 1);
                const int e = (part & 1) * 2;
                aP[g][part] = packh2(s[j][e], s[j][e + 1]);
            }
        }

        #pragma unroll
        for (int n16 = 0; n16 < 8; ++n16) {
            #pragma unroll
            for (int kk = 0; kk < 4; ++kk) {
                uint32_t vf[4];
                LDSM4T(vf, stg + VOFF + (uint32_t)(kk * 16) * FROWB + voffBase + n16 * 32);
                MMAH(acc_o[2*n16],   aP[kk], vf[0], vf[1]);
                MMAH(acc_o[2*n16+1], aP[kk], vf[2], vf[3]);
            }
        }
    }

    const float inv0 = 1.f / l0, inv1 = 1.f / l1;
    #pragma unroll
    for (int n8 = 0; n8 < 16; ++n8) {
        const int col = h * HD + n8 * 8 + (lane & 3) * 2;
        *(uint32_t*)&oh[(size_t)r0g * DIM + col] =
            packh2(acc_o[n8][0] * inv0, acc_o[n8][1] * inv0);
        *(uint32_t*)&oh[(size_t)(r0g + 8) * DIM + col] =
            packh2(acc_o[n8][2] * inv1, acc_o[n8][3] * inv1);
    }
}

// ---------------------------------------------------------------------------
extern "C" void kernel_launch(void* const* d_in, const int* in_sizes, int n_in,
                              void* d_out, int out_size)
{
    const float* x    = (const float*)d_in[0];
    const float* fc   = (const float*)d_in[1];
    const float* fs   = (const float*)d_in[2];
    const float* wk_w = (const float*)d_in[6];
    const float* wk_b = (const float*)d_in[7];
    const float* wv_w = (const float*)d_in[8];
    const float* wv_b = (const float*)d_in[9];
    const float* wo_w = (const float*)d_in[10];
    const float* wo_b = (const float*)d_in[11];
    float* out = (float*)d_out;

    __half *xh, *woh, *wkh, *wvh, *qh, *kh, *vh, *ah;
    cudaGetSymbolAddress((void**)&xh,  g_xh);
    cudaGetSymbolAddress((void**)&woh, g_woh);
    cudaGetSymbolAddress((void**)&wkh, g_wkh);
    cudaGetSymbolAddress((void**)&wvh, g_wvh);
    cudaGetSymbolAddress((void**)&qh,  g_qh);
    cudaGetSymbolAddress((void**)&kh,  g_kh);
    cudaGetSymbolAddress((void**)&vh,  g_vh);
    cudaGetSymbolAddress((void**)&ah,  g_ah);

    // 0) merged fp32 -> fp16 converts
    cvt_all_kernel<<<8192, 256>>>(x, wo_w, wk_w, wv_w, xh, woh, wkh, wvh);

    cudaFuncSetAttribute(qkv_gemm_kernel,
                         cudaFuncAttributeMaxDynamicSharedMemorySize, GSMEM);
    cudaFuncSetAttribute(out_gemm_kernel,
                         cudaFuncAttributeMaxDynamicSharedMemorySize, GSMEM);
    cudaFuncSetAttribute(fa_mma_kernel,
                         cudaFuncAttributeMaxDynamicSharedMemorySize, FA2SMEM);

    // 1) fused QKV projection + bias + RoPE -> fp16 q/k/v
    dim3 gqkv(48, 16);
    qkv_gemm_kernel<<<gqkv, 256, GSMEM>>>(xh,
                                          woh, wo_b, qh,
                                          wkh, wk_b, kh,
                                          wvh, wv_b, vh,
                                          fc, fs);

    // 2) fp16 tensor-core causal GQA flash attention -> fp16 att
    dim3 gfa(T_SEQ / 128, NH);
    fa_mma_kernel<<<gfa, 256, FA2SMEM>>>(qh, kh, vh, ah);

    // 3) output projection -> fp32 out
    dim3 go(32, 16);
    out_gemm_kernel<<<go, 256, GSMEM>>>(ah, woh, wo_b, out);
}

// round 15
// speedup vs baseline: 10.0046x; 1.0006x over previous
#include <cuda_runtime.h>
#include <cuda_fp16.h>
#include <math.h>
#include <stdint.h>

#define T_SEQ 2048
#define DIM   4096
#define NH    32
#define NKV   8
#define HD    128
#define KVD   1024
#define KDIM  4096

// ---------------- scratch (static __device__, no allocation) ----------------
__device__ __half g_xh [T_SEQ * DIM];
__device__ __half g_woh[DIM * DIM];
__device__ __half g_wkh[KVD * DIM];
__device__ __half g_wvh[KVD * DIM];
__device__ __half g_qh [T_SEQ * DIM];
__device__ __half g_kh [T_SEQ * KVD];
__device__ __half g_vh [T_SEQ * KVD];
__device__ __half g_ah [T_SEQ * DIM];

// ---------------- PTX helpers (baseline ISA only) ----------------
__device__ __forceinline__ uint32_t smem_u32(const void* p) {
    uint32_t a;
    asm("{ .reg .u64 t; cvta.to.shared.u64 t, %1; cvt.u32.u64 %0, t; }" : "=r"(a) : "l"(p));
    return a;
}
#define CP16(dst, src) asm volatile("cp.async.cg.shared.global [%0], [%1], 16;" :: "r"(dst), "l"(src))
#define CP_COMMIT()    asm volatile("cp.async.commit_group;" ::: "memory")
#define CP_WAIT1()     asm volatile("cp.async.wait_group 1;" ::: "memory")
#define CP_WAIT0()     asm volatile("cp.async.wait_group 0;" ::: "memory")

#define LDSM4(r, a) asm volatile( \
    "ldmatrix.sync.aligned.m8n8.x4.shared.b16 {%0,%1,%2,%3}, [%4];" \
    : "=r"((r)[0]), "=r"((r)[1]), "=r"((r)[2]), "=r"((r)[3]) : "r"(a))
#define LDSM4T(r, a) asm volatile( \
    "ldmatrix.sync.aligned.m8n8.x4.trans.shared.b16 {%0,%1,%2,%3}, [%4];" \
    : "=r"((r)[0]), "=r"((r)[1]), "=r"((r)[2]), "=r"((r)[3]) : "r"(a))

#define MMAH(c, a, b0, b1) asm volatile( \
    "mma.sync.aligned.m16n8k16.row.col.f32.f16.f16.f32 " \
    "{%0,%1,%2,%3},{%4,%5,%6,%7},{%8,%9},{%0,%1,%2,%3};" \
    : "+f"((c)[0]), "+f"((c)[1]), "+f"((c)[2]), "+f"((c)[3]) \
    : "r"((a)[0]), "r"((a)[1]), "r"((a)[2]), "r"((a)[3]), "r"(b0), "r"(b1))

__device__ __forceinline__ uint32_t packh2(float x, float y) {
    __half2 h = __floats2half2_rn(x, y);
    return *(uint32_t*)&h;
}

// ---------------------------------------------------------------------------
// merged fp32 -> fp16 convert, 4 independent float4 per thread (MLP=4)
// ---------------------------------------------------------------------------
__global__ __launch_bounds__(256) void cvt_all_kernel(
    const float* __restrict__ x,  const float* __restrict__ wo,
    const float* __restrict__ wk, const float* __restrict__ wv,
    __half* __restrict__ xh,  __half* __restrict__ woh,
    __half* __restrict__ wkh, __half* __restrict__ wvh)
{
    const long i = (long)blockIdx.x * blockDim.x + threadIdx.x;
    const long j = i * 4;
    const float4* s; __half2* d; long base;
    if (j < 2L*1024*1024)      { s = (const float4*)x;  d = (__half2*)xh;  base = j; }
    else if (j < 6L*1024*1024) { s = (const float4*)wo; d = (__half2*)woh; base = j - 2L*1024*1024; }
    else if (j < 7L*1024*1024) { s = (const float4*)wk; d = (__half2*)wkh; base = j - 6L*1024*1024; }
    else                       { s = (const float4*)wv; d = (__half2*)wvh; base = j - 7L*1024*1024; }
    float4 v0 = s[base], v1 = s[base+1], v2 = s[base+2], v3 = s[base+3];
    d[base*2+0] = __floats2half2_rn(v0.x, v0.y); d[base*2+1] = __floats2half2_rn(v0.z, v0.w);
    d[base*2+2] = __floats2half2_rn(v1.x, v1.y); d[base*2+3] = __floats2half2_rn(v1.z, v1.w);
    d[base*2+4] = __floats2half2_rn(v2.x, v2.y); d[base*2+5] = __floats2half2_rn(v2.z, v2.w);
    d[base*2+6] = __floats2half2_rn(v3.x, v3.y); d[base*2+7] = __floats2half2_rn(v3.z, v3.w);
}

// ---------------------------------------------------------------------------
// fp16 tensor-core GEMM core, BN=128, BK=64, 2-stage (72KB) -> 2 CTAs/SM.
// cp.async for chunk c+1 interleaved into the k16 MMA stream (2 per k16).
// ---------------------------------------------------------------------------
#define ROWB   144u                  // 128B data + 16B pad
#define B_OFF  (128u * 144u)
#define STAGEB (2u * 128u * 144u)
#define GSMEM  (2 * 36864)

template<bool ROPE, bool F32OUT>
__device__ __forceinline__ void gemm_core(
    const __half* __restrict__ A, const __half* __restrict__ W,
    const float* __restrict__ bias,
    float* __restrict__ Cout, __half* __restrict__ Ch,
    const float* __restrict__ fc, const float* __restrict__ fs,
    int bm, int n0, int ldc, uint32_t sb)
{
    const int tid  = threadIdx.x;
    const int lane = tid & 31;
    const int wid  = tid >> 5;
    const int wm   = wid & 1;
    const int wn   = wid >> 1;

    // cp.async geometry: thread covers rows {r0, r0+32, r0+64, r0+96}, 16B col cc
    const int r0 = tid >> 3, cc = tid & 7;
    const uint32_t so = (uint32_t)r0 * ROWB + cc * 16u;
    const size_t  go = (size_t)r0 * 8192 + cc * 16;

    const char* pA = (const char*)A + (size_t)bm * 8192;
    const char* pB = (const char*)W + (size_t)n0 * 8192;

    float acc[4][4][4];
    #pragma unroll
    for (int i = 0; i < 4; i++)
        #pragma unroll
        for (int j = 0; j < 4; j++)
            #pragma unroll
            for (int t = 0; t < 4; t++) acc[i][j][t] = 0.f;

    const int NC = KDIM / 64;   // 64 chunks

    // prologue: chunk 0 (burst; nothing to overlap with)
    {
        #pragma unroll
        for (int p = 0; p < 4; p++) {
            CP16(sb + so + p * (32u * ROWB),         pA + go + (size_t)p * (32 * 8192));
            CP16(sb + B_OFF + so + p * (32u * ROWB), pB + go + (size_t)p * (32 * 8192));
        }
        CP_COMMIT();
    }

    const uint32_t aRow = (uint32_t)(wm * 64 + (lane & 15)) * ROWB + ((lane >> 4) & 1) * 16u;
    const uint32_t bRow = (uint32_t)(wn * 32 + ((lane >> 4) << 3) + (lane & 7)) * ROWB
                        + ((lane >> 3) & 1) * 16u;

    for (int c = 0; c < NC; ++c) {
        CP_WAIT0();                       // chunk c resident
        __syncthreads();                  // stage (c-1)&1 free, chunk c visible

        const uint32_t stg = sb + (uint32_t)(c & 1) * STAGEB;
        const bool more = (c + 1 < NC);
        const uint32_t nst = sb + (uint32_t)((c + 1) & 1) * STAGEB;
        const size_t  nkb = (size_t)(c + 1) * 128;

        #pragma unroll
        for (int k16 = 0; k16 < 4; ++k16) {
            // interleave 2 of the 8 next-chunk cp.async into this k16 slot
            if (more) {
                CP16(nst + so + (uint32_t)k16 * (32u * ROWB),
                     pA + go + (size_t)k16 * (32 * 8192) + nkb);
                CP16(nst + B_OFF + so + (uint32_t)k16 * (32u * ROWB),
                     pB + go + (size_t)k16 * (32 * 8192) + nkb);
            }
            const uint32_t kb = (uint32_t)k16 * 32u;
            uint32_t ah[4][4], bh[2][4];
            #pragma unroll
            for (int i = 0; i < 4; i++)
                LDSM4(ah[i], stg + aRow + (uint32_t)(i * 16) * ROWB + kb);
            #pragma unroll
            for (int p = 0; p < 2; p++)
                LDSM4(bh[p], stg + B_OFF + bRow + (uint32_t)(p * 16) * ROWB + kb);
            #pragma unroll
            for (int i = 0; i < 4; i++) {
                #pragma unroll
                for (int j = 0; j < 4; j++) {
                    const int p = j >> 1, f = (j & 1) * 2;
                    MMAH(acc[i][j], ah[i], bh[p][f], bh[p][f + 1]);
                }
            }
        }
        if (more) CP_COMMIT();
    }

    // ---- epilogue ----
    #pragma unroll
    for (int i = 0; i < 4; i++) {
        const int row0 = bm + wm * 64 + i * 16 + (lane >> 2);
        #pragma unroll
        for (int j = 0; j < 4; j++) {
            const int col = n0 + wn * 32 + j * 8 + (lane & 3) * 2;
            const float bv0 = bias[col], bv1 = bias[col + 1];
            #pragma unroll
            for (int t = 0; t < 2; t++) {
                const int row = row0 + t * 8;
                float v0 = acc[i][j][2 * t]     + bv0;
                float v1 = acc[i][j][2 * t + 1] + bv1;
                if (F32OUT) {
                    *(float2*)&Cout[(size_t)row * ldc + col] = make_float2(v0, v1);
                } else {
                    if (ROPE) {
                        const int idx = (col & (HD - 1)) >> 1;
                        const float cs = fc[row * 64 + idx];
                        const float sn = fs[row * 64 + idx];
                        const float re = v0 * cs - v1 * sn;
                        const float im = v0 * sn + v1 * cs;
                        v0 = re; v1 = im;
                    }
                    *(uint32_t*)&Ch[(size_t)row * ldc + col] = packh2(v0, v1);
                }
            }
        }
    }
}

// QKV: grid (48, 16), BN=128. bx<32: q (RoPE); [32,40): k (RoPE); [40,48): v.
__global__ __launch_bounds__(256, 2) void qkv_gemm_kernel(
    const __half* __restrict__ A,
    const __half* __restrict__ Wq, const float* __restrict__ bq, __half* __restrict__ Cq,
    const __half* __restrict__ Wk, const float* __restrict__ bk, __half* __restrict__ Ck,
    const __half* __restrict__ Wv, const float* __restrict__ bv, __half* __restrict__ Cv,
    const float* __restrict__ fc, const float* __restrict__ fs)
{
    extern __shared__ char dsm[];
    const uint32_t sb = smem_u32(dsm);
    const int bx = blockIdx.x;
    const int bm = blockIdx.y * 128;
    if (bx < 32) {
        gemm_core<true, false>(A, Wq, bq, nullptr, Cq, fc, fs, bm, bx * 128, DIM, sb);
    } else if (bx < 40) {
        gemm_core<true, false>(A, Wk, bk, nullptr, Ck, fc, fs, bm, (bx - 32) * 128, KVD, sb);
    } else {
        gemm_core<false, false>(A, Wv, bv, nullptr, Cv, fc, fs, bm, (bx - 40) * 128, KVD, sb);
    }
}

// Out-proj: grid (32, 16), BN=128, fp32 output.
__global__ __launch_bounds__(256, 2) void out_gemm_kernel(
    const __half* __restrict__ A,
    const __half* __restrict__ W, const float* __restrict__ bias,
    float* __restrict__ Cout)
{
    extern __shared__ char dsm[];
    const uint32_t sb = smem_u32(dsm);
    gemm_core<false, true>(A, W, bias, Cout, nullptr, nullptr, nullptr,
                           blockIdx.y * 128, blockIdx.x * 128, DIM, sb);
}

// ---------------------------------------------------------------------------
// fp16 tensor-core flash attention (fp32 softmax), causal, GQA.
// Next-tile KV cp.async interleaved into the QK MMA stream (2 per even kk).
// ---------------------------------------------------------------------------
#define FROWB  272u
#define SQ_    0u
#define SKV    34816u
#define VOFF   17408u
#define KVSTG  34816u
#define FA2SMEM (34816 + 2 * 34816)

__global__ __launch_bounds__(256) void fa_mma_kernel(
    const __half* __restrict__ qh, const __half* __restrict__ kh,
    const __half* __restrict__ vh, __half* __restrict__ oh)
{
    extern __shared__ char sm[];
    const uint32_t sb = smem_u32(sm);

    const int qtile = gridDim.x - 1 - blockIdx.x;
    const int h = blockIdx.y, kvh = h >> 2;
    const int tid = threadIdx.x, wid = tid >> 5, lane = tid & 31;
    const int qbase = qtile * 128;

    // per-part KV load geometry: part p covers rows (tid>>4)+16p, col (tid&15)*16
    const uint32_t kvr = (uint32_t)(tid >> 4);
    const uint32_t kvc = (uint32_t)(tid & 15) * 16u;
    const uint32_t kvd0 = kvr * FROWB + kvc;
    const size_t   kvg0 = (size_t)kvr * 2048 + kvc;

    {   // Q tile load (prologue burst)
        const char* gq = (const char*)qh + ((size_t)qbase * DIM + h * HD) * 2;
        for (int i = tid; i < 2048; i += 256) {
            uint32_t r = i >> 4, c = i & 15;
            CP16(sb + SQ_ + r * FROWB + c * 16, gq + (size_t)r * 8192 + c * 16);
        }
    }
    {   // KV tile 0 (prologue burst)
        size_t gb = ((size_t)0 * KVD + kvh * HD) * 2;
        #pragma unroll
        for (int p = 0; p < 4; p++) {
            uint32_t d = sb + SKV + kvd0 + (uint32_t)p * (16u * FROWB);
            size_t   s2 = gb + kvg0 + (size_t)p * (16 * 2048);
            CP16(d,        (const char*)kh + s2);
            CP16(d + VOFF, (const char*)vh + s2);
        }
        CP_COMMIT();
    }

    const int NT = (qtile + 1) * 2;

    float m0 = -1e30f, m1 = -1e30f, l0 = 0.f, l1 = 0.f;
    float acc_o[16][4];
    #pragma unroll
    for (int n = 0; n < 16; n++)
        #pragma unroll
        for (int t = 0; t < 4; t++) acc_o[n][t] = 0.f;

    const float kl = 0.12751689f;  // (1/sqrt(128)) * log2(e)
    const uint32_t aoff = (uint32_t)(wid * 16 + (lane & 15)) * FROWB + (uint32_t)((lane >> 4) & 1) * 16u;
    const uint32_t boffBase = (uint32_t)(((lane >> 4) << 3) + (lane & 7)) * FROWB
                            + (uint32_t)((lane >> 3) & 1) * 16u;
    const uint32_t voffBase = (uint32_t)(lane & 15) * FROWB + (uint32_t)(lane >> 4) * 16u;
    const int r0g = qbase + wid * 16 + (lane >> 2);

    for (int c = 0; c < NT; ++c) {
        CP_WAIT0();
        __syncthreads();

        const uint32_t stg = sb + SKV + (uint32_t)(c & 1) * KVSTG;
        const bool more = (c + 1 < NT);
        const uint32_t nst = sb + SKV + (uint32_t)((c + 1) & 1) * KVSTG;
        const size_t  ngb = ((size_t)(c + 1) * 64 * KVD + kvh * HD) * 2;

        float s[8][4];
        #pragma unroll
        for (int j = 0; j < 8; j++)
            #pragma unroll
            for (int t = 0; t < 4; t++) s[j][t] = 0.f;

        #pragma unroll
        for (int kk = 0; kk < 8; ++kk) {
            // interleave next-tile KV loads: 2 cp.async on each even kk
            if ((kk & 1) == 0 && more) {
                const int p = kk >> 1;
                uint32_t d = nst + kvd0 + (uint32_t)p * (16u * FROWB);
                size_t   s2 = ngb + kvg0 + (size_t)p * (16 * 2048);
                CP16(d,        (const char*)kh + s2);
                CP16(d + VOFF, (const char*)vh + s2);
            }
            uint32_t ah[4];
            LDSM4(ah, sb + SQ_ + aoff + kk * 32);
            #pragma unroll
            for (int g = 0; g < 4; ++g) {
                uint32_t bh[4];
                LDSM4(bh, stg + (uint32_t)(g * 16) * FROWB + boffBase + kk * 32);
                MMAH(s[2*g],   ah, bh[0], bh[1]);
                MMAH(s[2*g+1], ah, bh[2], bh[3]);
            }
        }
        if (more) CP_COMMIT();

        const int jbase = c * 64;
        if (jbase + 63 > qbase + wid * 16) {
            #pragma unroll
            for (int j = 0; j < 8; j++) {
                int col = jbase + j * 8 + (lane & 3) * 2;
                if (col     > r0g)     s[j][0] = -1e30f;
                if (col + 1 > r0g)     s[j][1] = -1e30f;
                if (col     > r0g + 8) s[j][2] = -1e30f;
                if (col + 1 > r0g + 8) s[j][3] = -1e30f;
            }
        }

        float mx0 = -1e30f, mx1 = -1e30f;
        #pragma unroll
        for (int j = 0; j < 8; j++) {
            mx0 = fmaxf(mx0, fmaxf(s[j][0], s[j][1]));
            mx1 = fmaxf(mx1, fmaxf(s[j][2], s[j][3]));
        }
        mx0 = fmaxf(mx0, __shfl_xor_sync(0xFFFFFFFFu, mx0, 1));
        mx0 = fmaxf(mx0, __shfl_xor_sync(0xFFFFFFFFu, mx0, 2));
        mx1 = fmaxf(mx1, __shfl_xor_sync(0xFFFFFFFFu, mx1, 1));
        mx1 = fmaxf(mx1, __shfl_xor_sync(0xFFFFFFFFu, mx1, 2));
        const float nm0 = fmaxf(m0, mx0), nm1 = fmaxf(m1, mx1);
        const float corr0 = exp2f((m0 - nm0) * kl), corr1 = exp2f((m1 - nm1) * kl);
        const float nb0 = -nm0 * kl, nb1 = -nm1 * kl;
        float sum0 = 0.f, sum1 = 0.f;
        #pragma unroll
        for (int j = 0; j < 8; j++) {
            s[j][0] = exp2f(fmaf(s[j][0], kl, nb0));
            s[j][1] = exp2f(fmaf(s[j][1], kl, nb0));
            s[j][2] = exp2f(fmaf(s[j][2], kl, nb1));
            s[j][3] = exp2f(fmaf(s[j][3], kl, nb1));
            sum0 += s[j][0] + s[j][1];
            sum1 += s[j][2] + s[j][3];
        }
        sum0 += __shfl_xor_sync(0xFFFFFFFFu, sum0, 1);
        sum0 += __shfl_xor_sync(0xFFFFFFFFu, sum0, 2);
        sum1 += __shfl_xor_sync(0xFFFFFFFFu, sum1, 1);
        sum1 += __shfl_xor_sync(0xFFFFFFFFu, sum1, 2);
        l0 = l0 * corr0 + sum0;
        l1 = l1 * corr1 + sum1;
        m0 = nm0; m1 = nm1;
        #pragma unroll
        for (int n = 0; n < 16; n++) {
            acc_o[n][0] *= corr0; acc_o[n][1] *= corr0;
            acc_o[n][2] *= corr1; acc_o[n][3] *= corr1;
        }

        uint32_t aP[4][4];
        #pragma unroll
        for (int g = 0; g < 4; ++g) {
            #pragma unroll
            for (int part = 0; part < 4; ++part) {
                const int j = 2 * g + (part >> 1);
                const int e = (part & 1) * 2;
                aP[g][part] = packh2(s[j][e], s[j][e + 1]);
            }
        }

        #pragma unroll
        for (int n16 = 0; n16 < 8; ++n16) {
            #pragma unroll
            for (int kk = 0; kk < 4; ++kk) {
                uint32_t vf[4];
                LDSM4T(vf, stg + VOFF + (uint32_t)(kk * 16) * FROWB + voffBase + n16 * 32);
                MMAH(acc_o[2*n16],   aP[kk], vf[0], vf[1]);
                MMAH(acc_o[2*n16+1], aP[kk], vf[2], vf[3]);
            }
        }
    }

    const float inv0 = 1.f / l0, inv1 = 1.f / l1;
    #pragma unroll
    for (int n8 = 0; n8 < 16; ++n8) {
        const int col = h * HD + n8 * 8 + (lane & 3) * 2;
        *(uint32_t*)&oh[(size_t)r0g * DIM + col] =
            packh2(acc_o[n8][0] * inv0, acc_o[n8][1] * inv0);
        *(uint32_t*)&oh[(size_t)(r0g + 8) * DIM + col] =
            packh2(acc_o[n8][2] * inv1, acc_o[n8][3] * inv1);
    }
}

// ---------------------------------------------------------------------------
extern "C" void kernel_launch(void* const* d_in, const int* in_sizes, int n_in,
                              void* d_out, int out_size)
{
    const float* x    = (const float*)d_in[0];
    const float* fc   = (const float*)d_in[1];
    const float* fs   = (const float*)d_in[2];
    const float* wk_w = (const float*)d_in[6];
    const float* wk_b = (const float*)d_in[7];
    const float* wv_w = (const float*)d_in[8];
    const float* wv_b = (const float*)d_in[9];
    const float* wo_w = (const float*)d_in[10];
    const float* wo_b = (const float*)d_in[11];
    float* out = (float*)d_out;

    __half *xh, *woh, *wkh, *wvh, *qh, *kh, *vh, *ah;
    cudaGetSymbolAddress((void**)&xh,  g_xh);
    cudaGetSymbolAddress((void**)&woh, g_woh);
    cudaGetSymbolAddress((void**)&wkh, g_wkh);
    cudaGetSymbolAddress((void**)&wvh, g_wvh);
    cudaGetSymbolAddress((void**)&qh,  g_qh);
    cudaGetSymbolAddress((void**)&kh,  g_kh);
    cudaGetSymbolAddress((void**)&vh,  g_vh);
    cudaGetSymbolAddress((void**)&ah,  g_ah);

    // 0) merged fp32 -> fp16 converts
    cvt_all_kernel<<<8192, 256>>>(x, wo_w, wk_w, wv_w, xh, woh, wkh, wvh);

    cudaFuncSetAttribute(qkv_gemm_kernel,
                         cudaFuncAttributeMaxDynamicSharedMemorySize, GSMEM);
    cudaFuncSetAttribute(out_gemm_kernel,
                         cudaFuncAttributeMaxDynamicSharedMemorySize, GSMEM);
    cudaFuncSetAttribute(fa_mma_kernel,
                         cudaFuncAttributeMaxDynamicSharedMemorySize, FA2SMEM);

    // 1) fused QKV projection + bias + RoPE -> fp16 q/k/v
    dim3 gqkv(48, 16);
    qkv_gemm_kernel<<<gqkv, 256, GSMEM>>>(xh,
                                          woh, wo_b, qh,
                                          wkh, wk_b, kh,
                                          wvh, wv_b, vh,
                                          fc, fs);

    // 2) fp16 tensor-core causal GQA flash attention -> fp16 att
    dim3 gfa(T_SEQ / 128, NH);
    fa_mma_kernel<<<gfa, 256, FA2SMEM>>>(qh, kh, vh, ah);

    // 3) output projection -> fp32 out
    dim3 go(32, 16);
    out_gemm_kernel<<<go, 256, GSMEM>>>(ah, woh, wo_b, out);
}

// round 16
// speedup vs baseline: 10.0945x; 1.0090x over previous
#include <cuda_runtime.h>
#include <cuda_fp16.h>
#include <math.h>
#include <stdint.h>

#define T_SEQ 2048
#define DIM   4096
#define NH    32
#define NKV   8
#define HD    128
#define KVD   1024
#define KDIM  4096

// ---------------- scratch (static __device__, no allocation) ----------------
__device__ __half g_xh [T_SEQ * DIM];
__device__ __half g_woh[DIM * DIM];
__device__ __half g_wkh[KVD * DIM];
__device__ __half g_wvh[KVD * DIM];
__device__ __half g_qh [T_SEQ * DIM];
__device__ __half g_kh [T_SEQ * KVD];
__device__ __half g_vh [T_SEQ * KVD];
__device__ __half g_ah [T_SEQ * DIM];

// ---------------- PTX helpers (baseline ISA only) ----------------
__device__ __forceinline__ uint32_t smem_u32(const void* p) {
    uint32_t a;
    asm("{ .reg .u64 t; cvta.to.shared.u64 t, %1; cvt.u32.u64 %0, t; }" : "=r"(a) : "l"(p));
    return a;
}
#define CP16(dst, src) asm volatile("cp.async.cg.shared.global [%0], [%1], 16;" :: "r"(dst), "l"(src))
#define CP_COMMIT()    asm volatile("cp.async.commit_group;" ::: "memory")
#define CP_WAIT0()     asm volatile("cp.async.wait_group 0;" ::: "memory")

#define LDSM4(r, a) asm volatile( \
    "ldmatrix.sync.aligned.m8n8.x4.shared.b16 {%0,%1,%2,%3}, [%4];" \
    : "=r"((r)[0]), "=r"((r)[1]), "=r"((r)[2]), "=r"((r)[3]) : "r"(a))
#define LDSM4T(r, a) asm volatile( \
    "ldmatrix.sync.aligned.m8n8.x4.trans.shared.b16 {%0,%1,%2,%3}, [%4];" \
    : "=r"((r)[0]), "=r"((r)[1]), "=r"((r)[2]), "=r"((r)[3]) : "r"(a))

#define MMAH(c, a, b0, b1) asm volatile( \
    "mma.sync.aligned.m16n8k16.row.col.f32.f16.f16.f32 " \
    "{%0,%1,%2,%3},{%4,%5,%6,%7},{%8,%9},{%0,%1,%2,%3};" \
    : "+f"((c)[0]), "+f"((c)[1]), "+f"((c)[2]), "+f"((c)[3]) \
    : "r"((a)[0]), "r"((a)[1]), "r"((a)[2]), "r"((a)[3]), "r"(b0), "r"(b1))

__device__ __forceinline__ uint32_t packh2(float x, float y) {
    __half2 h = __floats2half2_rn(x, y);
    return *(uint32_t*)&h;
}

// ---------------------------------------------------------------------------
// merged fp32 -> fp16 convert, 4 independent float4 per thread (MLP=4)
// ---------------------------------------------------------------------------
__global__ __launch_bounds__(256) void cvt_all_kernel(
    const float* __restrict__ x,  const float* __restrict__ wo,
    const float* __restrict__ wk, const float* __restrict__ wv,
    __half* __restrict__ xh,  __half* __restrict__ woh,
    __half* __restrict__ wkh, __half* __restrict__ wvh)
{
    const long i = (long)blockIdx.x * blockDim.x + threadIdx.x;
    const long j = i * 4;
    const float4* s; __half2* d; long base;
    if (j < 2L*1024*1024)      { s = (const float4*)x;  d = (__half2*)xh;  base = j; }
    else if (j < 6L*1024*1024) { s = (const float4*)wo; d = (__half2*)woh; base = j - 2L*1024*1024; }
    else if (j < 7L*1024*1024) { s = (const float4*)wk; d = (__half2*)wkh; base = j - 6L*1024*1024; }
    else                       { s = (const float4*)wv; d = (__half2*)wvh; base = j - 7L*1024*1024; }
    float4 v0 = s[base], v1 = s[base+1], v2 = s[base+2], v3 = s[base+3];
    d[base*2+0] = __floats2half2_rn(v0.x, v0.y); d[base*2+1] = __floats2half2_rn(v0.z, v0.w);
    d[base*2+2] = __floats2half2_rn(v1.x, v1.y); d[base*2+3] = __floats2half2_rn(v1.z, v1.w);
    d[base*2+4] = __floats2half2_rn(v2.x, v2.y); d[base*2+5] = __floats2half2_rn(v2.z, v2.w);
    d[base*2+6] = __floats2half2_rn(v3.x, v3.y); d[base*2+7] = __floats2half2_rn(v3.z, v3.w);
}

// ---------------------------------------------------------------------------
// fp16 tensor-core GEMM core — BYTE-IDENTICAL to the passing R11/R15 version.
// ---------------------------------------------------------------------------
#define ROWB   144u                  // 128B data + 16B pad
#define B_OFF  (128u * 144u)
#define STAGEB (2u * 128u * 144u)
#define GSMEM  (2 * 36864)

template<bool ROPE, bool F32OUT>
__device__ __forceinline__ void gemm_core(
    const __half* __restrict__ A, const __half* __restrict__ W,
    const float* __restrict__ bias,
    float* __restrict__ Cout, __half* __restrict__ Ch,
    const float* __restrict__ fc, const float* __restrict__ fs,
    int bm, int n0, int ldc, uint32_t sb)
{
    const int tid  = threadIdx.x;
    const int lane = tid & 31;
    const int wid  = tid >> 5;
    const int wm   = wid & 1;
    const int wn   = wid >> 1;

    // cp.async geometry: thread covers rows {r0, r0+32, r0+64, r0+96}, 16B col cc
    const int r0 = tid >> 3, cc = tid & 7;
    const uint32_t so = (uint32_t)r0 * ROWB + cc * 16u;
    const size_t  go = (size_t)r0 * 8192 + cc * 16;

    const char* pA = (const char*)A + (size_t)bm * 8192;
    const char* pB = (const char*)W + (size_t)n0 * 8192;

    float acc[4][4][4];
    #pragma unroll
    for (int i = 0; i < 4; i++)
        #pragma unroll
        for (int j = 0; j < 4; j++)
            #pragma unroll
            for (int t = 0; t < 4; t++) acc[i][j][t] = 0.f;

    const int NC = KDIM / 64;   // 64 chunks

    // prologue: chunk 0 (burst; nothing to overlap with)
    {
        #pragma unroll
        for (int p = 0; p < 4; p++) {
            CP16(sb + so + p * (32u * ROWB),         pA + go + (size_t)p * (32 * 8192));
            CP16(sb + B_OFF + so + p * (32u * ROWB), pB + go + (size_t)p * (32 * 8192));
        }
        CP_COMMIT();
    }

    const uint32_t aRow = (uint32_t)(wm * 64 + (lane & 15)) * ROWB + ((lane >> 4) & 1) * 16u;
    const uint32_t bRow = (uint32_t)(wn * 32 + ((lane >> 4) << 3) + (lane & 7)) * ROWB
                        + ((lane >> 3) & 1) * 16u;

    for (int c = 0; c < NC; ++c) {
        CP_WAIT0();                       // chunk c resident
        __syncthreads();                  // stage (c-1)&1 free, chunk c visible

        const uint32_t stg = sb + (uint32_t)(c & 1) * STAGEB;
        const bool more = (c + 1 < NC);
        const uint32_t nst = sb + (uint32_t)((c + 1) & 1) * STAGEB;
        const size_t  nkb = (size_t)(c + 1) * 128;

        #pragma unroll
        for (int k16 = 0; k16 < 4; ++k16) {
            // interleave 2 of the 8 next-chunk cp.async into this k16 slot
            if (more) {
                CP16(nst + so + (uint32_t)k16 * (32u * ROWB),
                     pA + go + (size_t)k16 * (32 * 8192) + nkb);
                CP16(nst + B_OFF + so + (uint32_t)k16 * (32u * ROWB),
                     pB + go + (size_t)k16 * (32 * 8192) + nkb);
            }
            const uint32_t kb = (uint32_t)k16 * 32u;
            uint32_t ah[4][4], bh[2][4];
            #pragma unroll
            for (int i = 0; i < 4; i++)
                LDSM4(ah[i], stg + aRow + (uint32_t)(i * 16) * ROWB + kb);
            #pragma unroll
            for (int p = 0; p < 2; p++)
                LDSM4(bh[p], stg + B_OFF + bRow + (uint32_t)(p * 16) * ROWB + kb);
            #pragma unroll
            for (int i = 0; i < 4; i++) {
                #pragma unroll
                for (int j = 0; j < 4; j++) {
                    const int p = j >> 1, f = (j & 1) * 2;
                    MMAH(acc[i][j], ah[i], bh[p][f], bh[p][f + 1]);
                }
            }
        }
        if (more) CP_COMMIT();
    }

    // ---- epilogue ----
    #pragma unroll
    for (int i = 0; i < 4; i++) {
        const int row0 = bm + wm * 64 + i * 16 + (lane >> 2);
        #pragma unroll
        for (int j = 0; j < 4; j++) {
            const int col = n0 + wn * 32 + j * 8 + (lane & 3) * 2;
            const float bv0 = bias[col], bv1 = bias[col + 1];
            #pragma unroll
            for (int t = 0; t < 2; t++) {
                const int row = row0 + t * 8;
                float v0 = acc[i][j][2 * t]     + bv0;
                float v1 = acc[i][j][2 * t + 1] + bv1;
                if (F32OUT) {
                    *(float2*)&Cout[(size_t)row * ldc + col] = make_float2(v0, v1);
                } else {
                    if (ROPE) {
                        const int idx = (col & (HD - 1)) >> 1;
                        const float cs = fc[row * 64 + idx];
                        const float sn = fs[row * 64 + idx];
                        const float re = v0 * cs - v1 * sn;
                        const float im = v0 * sn + v1 * cs;
                        v0 = re; v1 = im;
                    }
                    *(uint32_t*)&Ch[(size_t)row * ldc + col] = packh2(v0, v1);
                }
            }
        }
    }
}

// QKV: grid (48, 16), BN=128. bx<32: q (RoPE); [32,40): k (RoPE); [40,48): v.
__global__ __launch_bounds__(256, 2) void qkv_gemm_kernel(
    const __half* __restrict__ A,
    const __half* __restrict__ Wq, const float* __restrict__ bq, __half* __restrict__ Cq,
    const __half* __restrict__ Wk, const float* __restrict__ bk, __half* __restrict__ Ck,
    const __half* __restrict__ Wv, const float* __restrict__ bv, __half* __restrict__ Cv,
    const float* __restrict__ fc, const float* __restrict__ fs)
{
    extern __shared__ char dsm[];
    const uint32_t sb = smem_u32(dsm);
    const int bx = blockIdx.x;
    const int bm = blockIdx.y * 128;
    if (bx < 32) {
        gemm_core<true, false>(A, Wq, bq, nullptr, Cq, fc, fs, bm, bx * 128, DIM, sb);
    } else if (bx < 40) {
        gemm_core<true, false>(A, Wk, bk, nullptr, Ck, fc, fs, bm, (bx - 32) * 128, KVD, sb);
    } else {
        gemm_core<false, false>(A, Wv, bv, nullptr, Cv, fc, fs, bm, (bx - 40) * 128, KVD, sb);
    }
}

// Out-proj: grid (32, 16), BN=128, fp32 output.
__global__ __launch_bounds__(256, 2) void out_gemm_kernel(
    const __half* __restrict__ A,
    const __half* __restrict__ W, const float* __restrict__ bias,
    float* __restrict__ Cout)
{
    extern __shared__ char dsm[];
    const uint32_t sb = smem_u32(dsm);
    gemm_core<false, true>(A, W, bias, Cout, nullptr, nullptr, nullptr,
                           blockIdx.y * 128, blockIdx.x * 128, DIM, sb);
}

// ---------------------------------------------------------------------------
// fp16 tensor-core flash attention (fp32 softmax), causal, GQA.
// R11 structure + (a) Q fragments hoisted to registers at tile 0,
// (b) fully-masked warps skip QK/softmax/PV on the final tile
// (their cp.async duties and barriers preserved; state provably unchanged).
// ---------------------------------------------------------------------------
#define FROWB  272u
#define SQ_    0u
#define SKV    34816u
#define VOFF   17408u
#define KVSTG  34816u
#define FA2SMEM (34816 + 2 * 34816)

__global__ __launch_bounds__(256) void fa_mma_kernel(
    const __half* __restrict__ qh, const __half* __restrict__ kh,
    const __half* __restrict__ vh, __half* __restrict__ oh)
{
    extern __shared__ char sm[];
    const uint32_t sb = smem_u32(sm);

    const int qtile = gridDim.x - 1 - blockIdx.x;
    const int h = blockIdx.y, kvh = h >> 2;
    const int tid = threadIdx.x, wid = tid >> 5, lane = tid & 31;
    const int qbase = qtile * 128;

    // per-part KV load geometry: part p covers rows (tid>>4)+16p, col (tid&15)*16
    const uint32_t kvr = (uint32_t)(tid >> 4);
    const uint32_t kvc = (uint32_t)(tid & 15) * 16u;
    const uint32_t kvd0 = kvr * FROWB + kvc;
    const size_t   kvg0 = (size_t)kvr * 2048 + kvc;

    {   // Q tile load (prologue burst)
        const char* gq = (const char*)qh + ((size_t)qbase * DIM + h * HD) * 2;
        for (int i = tid; i < 2048; i += 256) {
            uint32_t r = i >> 4, c = i & 15;
            CP16(sb + SQ_ + r * FROWB + c * 16, gq + (size_t)r * 8192 + c * 16);
        }
    }
    {   // KV tile 0 (prologue burst)
        size_t gb = ((size_t)0 * KVD + kvh * HD) * 2;
        #pragma unroll
        for (int p = 0; p < 4; p++) {
            uint32_t d = sb + SKV + kvd0 + (uint32_t)p * (16u * FROWB);
            size_t   s2 = gb + kvg0 + (size_t)p * (16 * 2048);
            CP16(d,        (const char*)kh + s2);
            CP16(d + VOFF, (const char*)vh + s2);
        }
        CP_COMMIT();
    }

    const int NT = (qtile + 1) * 2;

    float m0 = -1e30f, m1 = -1e30f, l0 = 0.f, l1 = 0.f;
    float acc_o[16][4];
    #pragma unroll
    for (int n = 0; n < 16; n++)
        #pragma unroll
        for (int t = 0; t < 4; t++) acc_o[n][t] = 0.f;

    const float kl = 0.12751689f;  // (1/sqrt(128)) * log2(e)
    const uint32_t aoff = (uint32_t)(wid * 16 + (lane & 15)) * FROWB + (uint32_t)((lane >> 4) & 1) * 16u;
    const uint32_t boffBase = (uint32_t)(((lane >> 4) << 3) + (lane & 7)) * FROWB
                            + (uint32_t)((lane >> 3) & 1) * 16u;
    const uint32_t voffBase = (uint32_t)(lane & 15) * FROWB + (uint32_t)(lane >> 4) * 16u;
    const int r0g = qbase + wid * 16 + (lane >> 2);
    const int rmax = qbase + wid * 16 + 15;          // last row this warp owns

    uint32_t aq[8][4];                                // hoisted Q fragments

    for (int c = 0; c < NT; ++c) {
        CP_WAIT0();
        __syncthreads();

        if (c == 0) {                                 // Q resident now; load once
            #pragma unroll
            for (int kk = 0; kk < 8; ++kk)
                LDSM4(aq[kk], sb + SQ_ + aoff + kk * 32);
        }

        const uint32_t stg = sb + SKV + (uint32_t)(c & 1) * KVSTG;
        const bool more = (c + 1 < NT);
        const uint32_t nst = sb + SKV + (uint32_t)((c + 1) & 1) * KVSTG;
        const size_t  ngb = ((size_t)(c + 1) * 64 * KVD + kvh * HD) * 2;

        const int jbase = c * 64;
        const bool skip = (jbase > rmax);             // tile fully masked for warp

        float s[8][4];

        if (skip) {
            // still perform this thread's share of next-tile loads
            if (more) {
                #pragma unroll
                for (int p = 0; p < 4; p++) {
                    uint32_t d = nst + kvd0 + (uint32_t)p * (16u * FROWB);
                    size_t   s2 = ngb + kvg0 + (size_t)p * (16 * 2048);
                    CP16(d,        (const char*)kh + s2);
                    CP16(d + VOFF, (const char*)vh + s2);
                }
            }
        } else {
            #pragma unroll
            for (int j = 0; j < 8; j++)
                #pragma unroll
                for (int t = 0; t < 4; t++) s[j][t] = 0.f;

            #pragma unroll
            for (int kk = 0; kk < 8; ++kk) {
                if ((kk & 1) == 0 && more) {
                    const int p = kk >> 1;
                    uint32_t d = nst + kvd0 + (uint32_t)p * (16u * FROWB);
                    size_t   s2 = ngb + kvg0 + (size_t)p * (16 * 2048);
                    CP16(d,        (const char*)kh + s2);
                    CP16(d + VOFF, (const char*)vh + s2);
                }
                #pragma unroll
                for (int g = 0; g < 4; ++g) {
                    uint32_t bh[4];
                    LDSM4(bh, stg + (uint32_t)(g * 16) * FROWB + boffBase + kk * 32);
                    MMAH(s[2*g],   aq[kk], bh[0], bh[1]);
                    MMAH(s[2*g+1], aq[kk], bh[2], bh[3]);
                }
            }
        }
        if (more) CP_COMMIT();

        if (!skip) {
            if (jbase + 63 > qbase + wid * 16) {
                #pragma unroll
                for (int j = 0; j < 8; j++) {
                    int col = jbase + j * 8 + (lane & 3) * 2;
                    if (col     > r0g)     s[j][0] = -1e30f;
                    if (col + 1 > r0g)     s[j][1] = -1e30f;
                    if (col     > r0g + 8) s[j][2] = -1e30f;
                    if (col + 1 > r0g + 8) s[j][3] = -1e30f;
                }
            }

            float mx0 = -1e30f, mx1 = -1e30f;
            #pragma unroll
            for (int j = 0; j < 8; j++) {
                mx0 = fmaxf(mx0, fmaxf(s[j][0], s[j][1]));
                mx1 = fmaxf(mx1, fmaxf(s[j][2], s[j][3]));
            }
            mx0 = fmaxf(mx0, __shfl_xor_sync(0xFFFFFFFFu, mx0, 1));
            mx0 = fmaxf(mx0, __shfl_xor_sync(0xFFFFFFFFu, mx0, 2));
            mx1 = fmaxf(mx1, __shfl_xor_sync(0xFFFFFFFFu, mx1, 1));
            mx1 = fmaxf(mx1, __shfl_xor_sync(0xFFFFFFFFu, mx1, 2));
            const float nm0 = fmaxf(m0, mx0), nm1 = fmaxf(m1, mx1);
            const float corr0 = exp2f((m0 - nm0) * kl), corr1 = exp2f((m1 - nm1) * kl);
            const float nb0 = -nm0 * kl, nb1 = -nm1 * kl;
            float sum0 = 0.f, sum1 = 0.f;
            #pragma unroll
            for (int j = 0; j < 8; j++) {
                s[j][0] = exp2f(fmaf(s[j][0], kl, nb0));
                s[j][1] = exp2f(fmaf(s[j][1], kl, nb0));
                s[j][2] = exp2f(fmaf(s[j][2], kl, nb1));
                s[j][3] = exp2f(fmaf(s[j][3], kl, nb1));
                sum0 += s[j][0] + s[j][1];
                sum1 += s[j][2] + s[j][3];
            }
            sum0 += __shfl_xor_sync(0xFFFFFFFFu, sum0, 1);
            sum0 += __shfl_xor_sync(0xFFFFFFFFu, sum0, 2);
            sum1 += __shfl_xor_sync(0xFFFFFFFFu, sum1, 1);
            sum1 += __shfl_xor_sync(0xFFFFFFFFu, sum1, 2);
            l0 = l0 * corr0 + sum0;
            l1 = l1 * corr1 + sum1;
            m0 = nm0; m1 = nm1;
            #pragma unroll
            for (int n = 0; n < 16; n++) {
                acc_o[n][0] *= corr0; acc_o[n][1] *= corr0;
                acc_o[n][2] *= corr1; acc_o[n][3] *= corr1;
            }

            uint32_t aP[4][4];
            #pragma unroll
            for (int g = 0; g < 4; ++g) {
                #pragma unroll
                for (int part = 0; part < 4; ++part) {
                    const int j = 2 * g + (part >> 1);
                    const int e = (part & 1) * 2;
                    aP[g][part] = packh2(s[j][e], s[j][e + 1]);
                }
            }

            #pragma unroll
            for (int n16 = 0; n16 < 8; ++n16) {
                #pragma unroll
                for (int kk = 0; kk < 4; ++kk) {
                    uint32_t vf[4];
                    LDSM4T(vf, stg + VOFF + (uint32_t)(kk * 16) * FROWB + voffBase + n16 * 32);
                    MMAH(acc_o[2*n16],   aP[kk], vf[0], vf[1]);
                    MMAH(acc_o[2*n16+1], aP[kk], vf[2], vf[3]);
                }
            }
        }
    }

    const float inv0 = 1.f / l0, inv1 = 1.f / l1;
    #pragma unroll
    for (int n8 = 0; n8 < 16; ++n8) {
        const int col = h * HD + n8 * 8 + (lane & 3) * 2;
        *(uint32_t*)&oh[(size_t)r0g * DIM + col] =
            packh2(acc_o[n8][0] * inv0, acc_o[n8][1] * inv0);
        *(uint32_t*)&oh[(size_t)(r0g + 8) * DIM + col] =
            packh2(acc_o[n8][2] * inv1, acc_o[n8][3] * inv1);
    }
}

// ---------------------------------------------------------------------------
extern "C" void kernel_launch(void* const* d_in, const int* in_sizes, int n_in,
                              void* d_out, int out_size)
{
    const float* x    = (const float*)d_in[0];
    const float* fc   = (const float*)d_in[1];
    const float* fs   = (const float*)d_in[2];
    const float* wk_w = (const float*)d_in[6];
    const float* wk_b = (const float*)d_in[7];
    const float* wv_w = (const float*)d_in[8];
    const float* wv_b = (const float*)d_in[9];
    const float* wo_w = (const float*)d_in[10];
    const float* wo_b = (const float*)d_in[11];
    float* out = (float*)d_out;

    __half *xh, *woh, *wkh, *wvh, *qh, *kh, *vh, *ah;
    cudaGetSymbolAddress((void**)&xh,  g_xh);
    cudaGetSymbolAddress((void**)&woh, g_woh);
    cudaGetSymbolAddress((void**)&wkh, g_wkh);
    cudaGetSymbolAddress((void**)&wvh, g_wvh);
    cudaGetSymbolAddress((void**)&qh,  g_qh);
    cudaGetSymbolAddress((void**)&kh,  g_kh);
    cudaGetSymbolAddress((void**)&vh,  g_vh);
    cudaGetSymbolAddress((void**)&ah,  g_ah);

    // 0) merged fp32 -> fp16 converts
    cvt_all_kernel<<<8192, 256>>>(x, wo_w, wk_w, wv_w, xh, woh, wkh, wvh);

    cudaFuncSetAttribute(qkv_gemm_kernel,
                         cudaFuncAttributeMaxDynamicSharedMemorySize, GSMEM);
    cudaFuncSetAttribute(out_gemm_kernel,
                         cudaFuncAttributeMaxDynamicSharedMemorySize, GSMEM);
    cudaFuncSetAttribute(fa_mma_kernel,
                         cudaFuncAttributeMaxDynamicSharedMemorySize, FA2SMEM);

    // 1) fused QKV projection + bias + RoPE -> fp16 q/k/v
    dim3 gqkv(48, 16);
    qkv_gemm_kernel<<<gqkv, 256, GSMEM>>>(xh,
                                          woh, wo_b, qh,
                                          wkh, wk_b, kh,
                                          wvh, wv_b, vh,
                                          fc, fs);

    // 2) fp16 tensor-core causal GQA flash attention -> fp16 att
    dim3 gfa(T_SEQ / 128, NH);
    fa_mma_kernel<<<gfa, 256, FA2SMEM>>>(qh, kh, vh, ah);

    // 3) output projection -> fp32 out
    dim3 go(32, 16);
    out_gemm_kernel<<<go, 256, GSMEM>>>(ah, woh, wo_b, out);
}